// round 1
// baseline (speedup 1.0000x reference)
#include <cuda_runtime.h>
#include <math.h>

// Problem constants
constexpr int Bn  = 4;
constexpr int Sn  = 2048;
constexpr int Dm  = 1024;
constexpr int Hn  = 16;
constexpr int Dh  = 64;      // Dm / Hn
constexpr int MTOT = Bn * Sn;   // 8192

// Scratch (static device globals -- no allocation)
__device__ float g_Q[(size_t)MTOT * Dm];
__device__ float g_K[(size_t)MTOT * Dm];
__device__ float g_V[(size_t)MTOT * Dm];
__device__ float g_C[(size_t)MTOT * Dm];

// ---------------------------------------------------------------------------
// Tiled GEMM core: C[m][n] = sum_k A[m][k] * W[n][k] + bias[n]
// BM=BN=128, BK=8, 256 threads, 8x8 register tile per thread.
// M assumed multiple of 128, N multiple of 128, K multiple of 8.
// ---------------------------------------------------------------------------
__device__ __forceinline__ void gemm_tile(const float* __restrict__ A,
                                          const float* __restrict__ W,
                                          const float* __restrict__ bias,
                                          float* __restrict__ C,
                                          int K, int N)
{
    __shared__ float As[8][132];
    __shared__ float Bs[8][132];

    const int tid = threadIdx.x;
    const int m0  = blockIdx.y * 128;
    const int n0  = blockIdx.x * 128;

    const int lr = tid >> 1;          // 0..127
    const int lc = (tid & 1) << 2;    // 0 or 4

    const float* Ap = A + (size_t)(m0 + lr) * K + lc;
    const float* Wp = W + (size_t)(n0 + lr) * K + lc;

    float acc[8][8];
#pragma unroll
    for (int i = 0; i < 8; ++i)
#pragma unroll
        for (int j = 0; j < 8; ++j) acc[i][j] = 0.f;

    const int ty = tid >> 4;   // 0..15 (row group)
    const int tx = tid & 15;   // 0..15 (col group)

    for (int k0 = 0; k0 < K; k0 += 8) {
        float4 av = *reinterpret_cast<const float4*>(Ap + k0);
        float4 wv = *reinterpret_cast<const float4*>(Wp + k0);
        As[lc + 0][lr] = av.x; As[lc + 1][lr] = av.y;
        As[lc + 2][lr] = av.z; As[lc + 3][lr] = av.w;
        Bs[lc + 0][lr] = wv.x; Bs[lc + 1][lr] = wv.y;
        Bs[lc + 2][lr] = wv.z; Bs[lc + 3][lr] = wv.w;
        __syncthreads();

#pragma unroll
        for (int kk = 0; kk < 8; ++kk) {
            float ra[8], rb[8];
            *reinterpret_cast<float4*>(&ra[0]) = *reinterpret_cast<const float4*>(&As[kk][ty * 8]);
            *reinterpret_cast<float4*>(&ra[4]) = *reinterpret_cast<const float4*>(&As[kk][ty * 8 + 4]);
            *reinterpret_cast<float4*>(&rb[0]) = *reinterpret_cast<const float4*>(&Bs[kk][tx * 8]);
            *reinterpret_cast<float4*>(&rb[4]) = *reinterpret_cast<const float4*>(&Bs[kk][tx * 8 + 4]);
#pragma unroll
            for (int i = 0; i < 8; ++i)
#pragma unroll
                for (int j = 0; j < 8; ++j)
                    acc[i][j] += ra[i] * rb[j];
        }
        __syncthreads();
    }

#pragma unroll
    for (int i = 0; i < 8; ++i) {
        float* Crow = C + (size_t)(m0 + ty * 8 + i) * N + n0;
#pragma unroll
        for (int j = 0; j < 8; ++j)
            Crow[tx * 8 + j] = acc[i][j] + bias[n0 + tx * 8 + j];
    }
}

// ---------------------------------------------------------------------------
// Fused QKV projection: gridDim.z selects Q/K/V
// ---------------------------------------------------------------------------
__global__ __launch_bounds__(256)
void k_qkv(const float* __restrict__ X,
           const float* __restrict__ Wq, const float* __restrict__ bq,
           const float* __restrict__ Wk, const float* __restrict__ bk,
           const float* __restrict__ Wv, const float* __restrict__ bv)
{
    const float* W;
    const float* bb;
    float* out;
    if (blockIdx.z == 0)      { W = Wq; bb = bq; out = g_Q; }
    else if (blockIdx.z == 1) { W = Wk; bb = bk; out = g_K; }
    else                      { W = Wv; bb = bv; out = g_V; }
    gemm_tile(X, W, bb, out, Dm, Dm);
}

// ---------------------------------------------------------------------------
// Output projection
// ---------------------------------------------------------------------------
__global__ __launch_bounds__(256)
void k_oproj(const float* __restrict__ Wo, const float* __restrict__ bo,
             float* __restrict__ out)
{
    gemm_tile(g_C, Wo, bo, out, Dm, Dm);
}

// ---------------------------------------------------------------------------
// Flash attention. One thread = one query row. BR = BC = 64.
// grid: (S/64, B*H), block: 64 threads.
// ---------------------------------------------------------------------------
__global__ __launch_bounds__(64)
void k_attn(const int* __restrict__ mask)
{
    __shared__ float Ks[64][64];
    __shared__ float Vs[64][64];
    __shared__ float Ssc[64][65];
    __shared__ int   msk[64];

    const int bh = blockIdx.y;
    const int b  = bh >> 4;
    const int h  = bh & 15;
    const int r  = threadIdx.x;           // 0..63 -> query row within tile
    const int sq = blockIdx.x * 64 + r;   // global query position

    const float* qp = g_Q + ((size_t)(b * Sn + sq) * Dm + h * Dh);
    float q[Dh];
#pragma unroll
    for (int d = 0; d < Dh; ++d) q[d] = qp[d];

    float o[Dh];
#pragma unroll
    for (int d = 0; d < Dh; ++d) o[d] = 0.f;

    float mi = -INFINITY;
    float li = 0.f;

    const float inv_scale = 0.125f;   // 1/sqrt(64)

    for (int kt = 0; kt < Sn / 64; ++kt) {
        __syncthreads();   // previous tile fully consumed before overwrite
        const int kbase = b * Sn + kt * 64;
        {
            const float* kp = g_K + ((size_t)kbase * Dm + h * Dh + r);
            const float* vp = g_V + ((size_t)kbase * Dm + h * Dh + r);
#pragma unroll 4
            for (int i = 0; i < 64; ++i) {
                Ks[i][r] = kp[(size_t)i * Dm];
                Vs[i][r] = vp[(size_t)i * Dm];
            }
            msk[r] = mask[kbase + r];
        }
        __syncthreads();

        // scores for this row against 64 keys
        float tmax = -INFINITY;
        for (int t = 0; t < 64; ++t) {
            const float4* krow = reinterpret_cast<const float4*>(&Ks[t][0]);
            float s = 0.f;
#pragma unroll
            for (int d4 = 0; d4 < 16; ++d4) {
                float4 kv = krow[d4];
                s += q[d4 * 4 + 0] * kv.x + q[d4 * 4 + 1] * kv.y
                   + q[d4 * 4 + 2] * kv.z + q[d4 * 4 + 3] * kv.w;
            }
            s = msk[t] ? s * inv_scale : -1e30f;
            Ssc[r][t] = s;
            tmax = fmaxf(tmax, s);
        }

        const float mnew  = fmaxf(mi, tmax);
        const float alpha = __expf(mi - mnew);
        li *= alpha;
#pragma unroll
        for (int d = 0; d < Dh; ++d) o[d] *= alpha;

        for (int t = 0; t < 64; ++t) {
            const float p = __expf(Ssc[r][t] - mnew);
            li += p;
            const float4* vrow = reinterpret_cast<const float4*>(&Vs[t][0]);
#pragma unroll
            for (int d4 = 0; d4 < 16; ++d4) {
                float4 vv = vrow[d4];
                o[d4 * 4 + 0] += p * vv.x;
                o[d4 * 4 + 1] += p * vv.y;
                o[d4 * 4 + 2] += p * vv.z;
                o[d4 * 4 + 3] += p * vv.w;
            }
        }
        mi = mnew;
    }

    const float inv = 1.f / li;
    float* cp = g_C + ((size_t)(b * Sn + sq) * Dm + h * Dh);
#pragma unroll
    for (int d = 0; d < Dh; ++d) cp[d] = o[d] * inv;
}

// ---------------------------------------------------------------------------
// Launch
// ---------------------------------------------------------------------------
extern "C" void kernel_launch(void* const* d_in, const int* in_sizes, int n_in,
                              void* d_out, int out_size)
{
    const float* query = (const float*)d_in[0];
    const int*   mask  = (const int*)  d_in[1];
    const float* Wq    = (const float*)d_in[2];
    const float* bq    = (const float*)d_in[3];
    const float* Wk    = (const float*)d_in[4];
    const float* bk    = (const float*)d_in[5];
    const float* Wv    = (const float*)d_in[6];
    const float* bv    = (const float*)d_in[7];
    const float* Wo    = (const float*)d_in[8];
    const float* bo    = (const float*)d_in[9];
    float* out = (float*)d_out;

    // QKV projections: grid (N/128, M/128, 3)
    dim3 gq(Dm / 128, MTOT / 128, 3);
    k_qkv<<<gq, 256>>>(query, Wq, bq, Wk, bk, Wv, bv);

    // Flash attention: grid (S/64, B*H)
    dim3 ga(Sn / 64, Bn * Hn);
    k_attn<<<ga, 64>>>(mask);

    // Output projection
    dim3 go(Dm / 128, MTOT / 128);
    k_oproj<<<go, 256>>>(Wo, bo, out);
}

// round 2
// speedup vs baseline: 1.9301x; 1.9301x over previous
#include <cuda_runtime.h>
#include <math.h>

constexpr int Bn  = 4;
constexpr int Sn  = 2048;
constexpr int Dm  = 1024;
constexpr int Hn  = 16;
constexpr int Dh  = 64;
constexpr int MTOT = Bn * Sn;   // 8192

// Scratch (static device globals -- no allocation)
__device__ float g_Q[(size_t)MTOT * Dm];
__device__ float g_K[(size_t)MTOT * Dm];
__device__ float g_V[(size_t)MTOT * Dm];
__device__ float g_C[(size_t)MTOT * Dm];

// ---------------------------------------------------------------------------
// tf32 helpers
// ---------------------------------------------------------------------------
__device__ __forceinline__ unsigned f2tf(float x) {
    unsigned r;
    asm("cvt.rna.tf32.f32 %0, %1;" : "=r"(r) : "f"(x));
    return r;
}

__device__ __forceinline__ void mma8(float* d, const unsigned* a, const unsigned* b) {
    asm volatile(
        "mma.sync.aligned.m16n8k8.row.col.f32.tf32.tf32.f32 "
        "{%0,%1,%2,%3},{%4,%5,%6,%7},{%8,%9},{%0,%1,%2,%3};"
        : "+f"(d[0]), "+f"(d[1]), "+f"(d[2]), "+f"(d[3])
        : "r"(a[0]), "r"(a[1]), "r"(a[2]), "r"(a[3]), "r"(b[0]), "r"(b[1]));
}

// ---------------------------------------------------------------------------
// 3xTF32 GEMM core: C[m][n] = A[m][:] . W[n][:] + bias[n]
// Block tile 128(M) x 128(N), K-step 16, double-buffered smem (transposed).
// 256 threads = 8 warps in 2(M) x 4(N); warp tile 64x32; mma m16n8k8.
// K = N = Dm = 1024 fixed.
// ---------------------------------------------------------------------------
__device__ __forceinline__ void gemm_core(const float* __restrict__ A,
                                          const float* __restrict__ W,
                                          const float* __restrict__ bias,
                                          float* __restrict__ C)
{
    __shared__ float As[2][16][136];   // [k][m], stride 136 => conflict-free frags
    __shared__ float Bs[2][16][136];   // [k][n]

    const int tid  = threadIdx.x;
    const int lane = tid & 31;
    const int warp = tid >> 5;
    const int wm   = warp >> 2;        // 0..1
    const int wn   = warp & 3;         // 0..3
    const int m0   = blockIdx.y * 128;
    const int n0   = blockIdx.x * 128;

    const int lr  = tid >> 1;          // 0..127: row within tile
    const int lcb = (tid & 1) * 8;     // k offset base: 0 or 8

    const float* Ap = A + (size_t)(m0 + lr) * Dm + lcb;
    const float* Wp = W + (size_t)(n0 + lr) * Dm + lcb;

    float acc[4][4][4];
#pragma unroll
    for (int mf = 0; mf < 4; ++mf)
#pragma unroll
        for (int nf = 0; nf < 4; ++nf)
#pragma unroll
            for (int j = 0; j < 4; ++j) acc[mf][nf][j] = 0.f;

    float4 pa0, pa1, pb0, pb1;

    // prologue: tile 0
    pa0 = *reinterpret_cast<const float4*>(Ap);
    pa1 = *reinterpret_cast<const float4*>(Ap + 4);
    pb0 = *reinterpret_cast<const float4*>(Wp);
    pb1 = *reinterpret_cast<const float4*>(Wp + 4);
    {
        As[0][lcb + 0][lr] = pa0.x; As[0][lcb + 1][lr] = pa0.y;
        As[0][lcb + 2][lr] = pa0.z; As[0][lcb + 3][lr] = pa0.w;
        As[0][lcb + 4][lr] = pa1.x; As[0][lcb + 5][lr] = pa1.y;
        As[0][lcb + 6][lr] = pa1.z; As[0][lcb + 7][lr] = pa1.w;
        Bs[0][lcb + 0][lr] = pb0.x; Bs[0][lcb + 1][lr] = pb0.y;
        Bs[0][lcb + 2][lr] = pb0.z; Bs[0][lcb + 3][lr] = pb0.w;
        Bs[0][lcb + 4][lr] = pb1.x; Bs[0][lcb + 5][lr] = pb1.y;
        Bs[0][lcb + 6][lr] = pb1.z; Bs[0][lcb + 7][lr] = pb1.w;
    }
    __syncthreads();

    int buf = 0;
    const int mrow = wm * 64 + (lane >> 2);
    const int ncol = wn * 32 + (lane >> 2);

    for (int kt = 0; kt < Dm / 16; ++kt) {
        if (kt < Dm / 16 - 1) {
            const float* a2 = Ap + (kt + 1) * 16;
            const float* w2 = Wp + (kt + 1) * 16;
            pa0 = *reinterpret_cast<const float4*>(a2);
            pa1 = *reinterpret_cast<const float4*>(a2 + 4);
            pb0 = *reinterpret_cast<const float4*>(w2);
            pb1 = *reinterpret_cast<const float4*>(w2 + 4);
        }

#pragma unroll
        for (int k8 = 0; k8 < 2; ++k8) {
            const int kb = k8 * 8;
            unsigned ahi[4][4], alo[4][4], bhi[4][2], blo[4][2];
#pragma unroll
            for (int mf = 0; mf < 4; ++mf)
#pragma unroll
                for (int j = 0; j < 4; ++j) {
                    float v = As[buf][kb + (lane & 3) + ((j >> 1) << 2)]
                                     [mrow + mf * 16 + ((j & 1) << 3)];
                    ahi[mf][j] = f2tf(v);
                    alo[mf][j] = f2tf(v - __uint_as_float(ahi[mf][j]));
                }
#pragma unroll
            for (int nf = 0; nf < 4; ++nf)
#pragma unroll
                for (int j = 0; j < 2; ++j) {
                    float v = Bs[buf][kb + (lane & 3) + j * 4][ncol + nf * 8];
                    bhi[nf][j] = f2tf(v);
                    blo[nf][j] = f2tf(v - __uint_as_float(bhi[nf][j]));
                }
#pragma unroll
            for (int mf = 0; mf < 4; ++mf)
#pragma unroll
                for (int nf = 0; nf < 4; ++nf) {
                    mma8(acc[mf][nf], alo[mf], bhi[nf]);
                    mma8(acc[mf][nf], ahi[mf], blo[nf]);
                    mma8(acc[mf][nf], ahi[mf], bhi[nf]);
                }
        }

        if (kt < Dm / 16 - 1) {
            const int nb = buf ^ 1;
            As[nb][lcb + 0][lr] = pa0.x; As[nb][lcb + 1][lr] = pa0.y;
            As[nb][lcb + 2][lr] = pa0.z; As[nb][lcb + 3][lr] = pa0.w;
            As[nb][lcb + 4][lr] = pa1.x; As[nb][lcb + 5][lr] = pa1.y;
            As[nb][lcb + 6][lr] = pa1.z; As[nb][lcb + 7][lr] = pa1.w;
            Bs[nb][lcb + 0][lr] = pb0.x; Bs[nb][lcb + 1][lr] = pb0.y;
            Bs[nb][lcb + 2][lr] = pb0.z; Bs[nb][lcb + 3][lr] = pb0.w;
            Bs[nb][lcb + 4][lr] = pb1.x; Bs[nb][lcb + 5][lr] = pb1.y;
            Bs[nb][lcb + 6][lr] = pb1.z; Bs[nb][lcb + 7][lr] = pb1.w;
        }
        __syncthreads();
        buf ^= 1;
    }

    // epilogue
#pragma unroll
    for (int mf = 0; mf < 4; ++mf) {
        const int r0 = m0 + wm * 64 + mf * 16 + (lane >> 2);
#pragma unroll
        for (int nf = 0; nf < 4; ++nf) {
            const int c = n0 + wn * 32 + nf * 8 + (lane & 3) * 2;
            float2 bv = *reinterpret_cast<const float2*>(bias + c);
            float2 o0 = { acc[mf][nf][0] + bv.x, acc[mf][nf][1] + bv.y };
            float2 o1 = { acc[mf][nf][2] + bv.x, acc[mf][nf][3] + bv.y };
            *reinterpret_cast<float2*>(C + (size_t)r0 * Dm + c) = o0;
            *reinterpret_cast<float2*>(C + (size_t)(r0 + 8) * Dm + c) = o1;
        }
    }
}

__global__ __launch_bounds__(256)
void k_qkv(const float* __restrict__ X,
           const float* __restrict__ Wq, const float* __restrict__ bq,
           const float* __restrict__ Wk, const float* __restrict__ bk,
           const float* __restrict__ Wv, const float* __restrict__ bv)
{
    const float* W; const float* bb; float* out;
    if (blockIdx.z == 0)      { W = Wq; bb = bq; out = g_Q; }
    else if (blockIdx.z == 1) { W = Wk; bb = bk; out = g_K; }
    else                      { W = Wv; bb = bv; out = g_V; }
    gemm_core(X, W, bb, out);
}

__global__ __launch_bounds__(256)
void k_oproj(const float* __restrict__ Wo, const float* __restrict__ bo,
             float* __restrict__ out)
{
    gemm_core(g_C, Wo, bo, out);
}

// ---------------------------------------------------------------------------
// Flash attention with tf32 mma.
// Block: 128 threads (4 warps), 64 query rows, one (b,h). Key tiles of 64.
// Each warp owns 16 query rows. QK^T and PV via m16n8k8 tf32.
// ---------------------------------------------------------------------------
__global__ __launch_bounds__(128)
void k_attn(const int* __restrict__ mask)
{
    __shared__ float Ks[64][68];   // [key][d]; reused as P [qrow][key]
    __shared__ float Vs[64][72];   // [key][d]
    __shared__ int   msk[64];

    const int tid  = threadIdx.x;
    const int lane = tid & 31;
    const int wq   = tid >> 5;             // warp 0..3 -> query rows wq*16..
    const int bh   = blockIdx.y;
    const int b    = bh >> 4;
    const int h    = bh & 15;
    const int q0   = blockIdx.x * 64;

    // Load Q fragments (tf32), pre-scaled by 1/sqrt(Dh) = 1/8
    unsigned qf[8][4];
    {
        const float* qbase = g_Q + ((size_t)(b * Sn + q0 + wq * 16) * Dm + h * Dh);
#pragma unroll
        for (int k8 = 0; k8 < 8; ++k8)
#pragma unroll
            for (int j = 0; j < 4; ++j) {
                int row = (lane >> 2) + ((j & 1) << 3);
                int col = k8 * 8 + (lane & 3) + ((j >> 1) << 2);
                qf[k8][j] = f2tf(qbase[(size_t)row * Dm + col] * 0.125f);
            }
    }

    float of[8][4];
#pragma unroll
    for (int nf = 0; nf < 8; ++nf)
#pragma unroll
        for (int j = 0; j < 4; ++j) of[nf][j] = 0.f;

    float m0r = -INFINITY, m1r = -INFINITY;
    float l0 = 0.f, l1 = 0.f;

    for (int kt = 0; kt < Sn / 64; ++kt) {
        __syncthreads();   // prev iter fully consumed (Ks-as-P + Vs)

        // load K, V tiles (64 x 64 f32 each) + mask
        {
            const int row  = tid >> 1;
            const int half = (tid & 1) * 8;
            const float* kp = g_K + ((size_t)(b * Sn + kt * 64 + row) * Dm + h * Dh);
            const float* vp = g_V + ((size_t)(b * Sn + kt * 64 + row) * Dm + h * Dh);
#pragma unroll
            for (int i = 0; i < 8; ++i) {
                float4 kv = *reinterpret_cast<const float4*>(kp + (half + i) * 4);
                float4 vv = *reinterpret_cast<const float4*>(vp + (half + i) * 4);
                *reinterpret_cast<float4*>(&Ks[row][(half + i) * 4]) = kv;
                *reinterpret_cast<float4*>(&Vs[row][(half + i) * 4]) = vv;
            }
            if (tid < 64) msk[tid] = mask[b * Sn + kt * 64 + tid];
        }
        __syncthreads();

        // S = Q . K^T  (scaled); warp computes its 16 rows x 64 keys
        float sf[8][4];
#pragma unroll
        for (int nf = 0; nf < 8; ++nf)
#pragma unroll
            for (int j = 0; j < 4; ++j) sf[nf][j] = 0.f;

#pragma unroll
        for (int k8 = 0; k8 < 8; ++k8) {
            const int kb = k8 * 8;
#pragma unroll
            for (int nf = 0; nf < 8; ++nf) {
                unsigned bfr[2];
                bfr[0] = f2tf(Ks[nf * 8 + (lane >> 2)][kb + (lane & 3)]);
                bfr[1] = f2tf(Ks[nf * 8 + (lane >> 2)][kb + (lane & 3) + 4]);
                mma8(sf[nf], qf[k8], bfr);
            }
        }

        // mask + online softmax
        float tmax0 = -INFINITY, tmax1 = -INFINITY;
#pragma unroll
        for (int nf = 0; nf < 8; ++nf) {
            const int c = nf * 8 + (lane & 3) * 2;
            if (!msk[c])     { sf[nf][0] = -1e20f; sf[nf][2] = -1e20f; }
            if (!msk[c + 1]) { sf[nf][1] = -1e20f; sf[nf][3] = -1e20f; }
            tmax0 = fmaxf(tmax0, fmaxf(sf[nf][0], sf[nf][1]));
            tmax1 = fmaxf(tmax1, fmaxf(sf[nf][2], sf[nf][3]));
        }
        tmax0 = fmaxf(tmax0, __shfl_xor_sync(0xffffffff, tmax0, 1));
        tmax0 = fmaxf(tmax0, __shfl_xor_sync(0xffffffff, tmax0, 2));
        tmax1 = fmaxf(tmax1, __shfl_xor_sync(0xffffffff, tmax1, 1));
        tmax1 = fmaxf(tmax1, __shfl_xor_sync(0xffffffff, tmax1, 2));

        const float mn0 = fmaxf(m0r, tmax0);
        const float mn1 = fmaxf(m1r, tmax1);
        const float a0  = __expf(m0r - mn0);
        const float a1  = __expf(m1r - mn1);
        l0 *= a0; l1 *= a1;
#pragma unroll
        for (int nf = 0; nf < 8; ++nf) {
            of[nf][0] *= a0; of[nf][1] *= a0;
            of[nf][2] *= a1; of[nf][3] *= a1;
        }

        float s0 = 0.f, s1 = 0.f;
#pragma unroll
        for (int nf = 0; nf < 8; ++nf) {
            sf[nf][0] = __expf(sf[nf][0] - mn0);
            sf[nf][1] = __expf(sf[nf][1] - mn0);
            sf[nf][2] = __expf(sf[nf][2] - mn1);
            sf[nf][3] = __expf(sf[nf][3] - mn1);
            s0 += sf[nf][0] + sf[nf][1];
            s1 += sf[nf][2] + sf[nf][3];
        }
        s0 += __shfl_xor_sync(0xffffffff, s0, 1);
        s0 += __shfl_xor_sync(0xffffffff, s0, 2);
        s1 += __shfl_xor_sync(0xffffffff, s1, 1);
        s1 += __shfl_xor_sync(0xffffffff, s1, 2);
        l0 += s0; l1 += s1;
        m0r = mn0; m1r = mn1;

        __syncthreads();   // all warps done reading Ks before P overwrites it

        // write P into Ks region (own 16 rows only)
#pragma unroll
        for (int nf = 0; nf < 8; ++nf) {
            const int c = nf * 8 + (lane & 3) * 2;
            const int r = wq * 16 + (lane >> 2);
            *reinterpret_cast<float2*>(&Ks[r][c])     = make_float2(sf[nf][0], sf[nf][1]);
            *reinterpret_cast<float2*>(&Ks[r + 8][c]) = make_float2(sf[nf][2], sf[nf][3]);
        }
        __syncwarp();

        // O += P . V
#pragma unroll
        for (int k8 = 0; k8 < 8; ++k8) {
            const int kb = k8 * 8;
            unsigned af[4];
#pragma unroll
            for (int j = 0; j < 4; ++j)
                af[j] = f2tf(Ks[wq * 16 + (lane >> 2) + ((j & 1) << 3)]
                               [kb + (lane & 3) + ((j >> 1) << 2)]);
#pragma unroll
            for (int nf = 0; nf < 8; ++nf) {
                unsigned bfr[2];
                bfr[0] = f2tf(Vs[kb + (lane & 3)]    [nf * 8 + (lane >> 2)]);
                bfr[1] = f2tf(Vs[kb + (lane & 3) + 4][nf * 8 + (lane >> 2)]);
                mma8(of[nf], af, bfr);
            }
        }
    }

    // epilogue: normalize + write ctx
    const float inv0 = 1.f / l0;
    const float inv1 = 1.f / l1;
    float* cbase = g_C + ((size_t)(b * Sn + q0 + wq * 16) * Dm + h * Dh);
#pragma unroll
    for (int nf = 0; nf < 8; ++nf) {
        const int c  = nf * 8 + (lane & 3) * 2;
        const int r  = lane >> 2;
        *reinterpret_cast<float2*>(cbase + (size_t)r * Dm + c) =
            make_float2(of[nf][0] * inv0, of[nf][1] * inv0);
        *reinterpret_cast<float2*>(cbase + (size_t)(r + 8) * Dm + c) =
            make_float2(of[nf][2] * inv1, of[nf][3] * inv1);
    }
}

// ---------------------------------------------------------------------------
// Launch
// ---------------------------------------------------------------------------
extern "C" void kernel_launch(void* const* d_in, const int* in_sizes, int n_in,
                              void* d_out, int out_size)
{
    const float* query = (const float*)d_in[0];
    const int*   mask  = (const int*)  d_in[1];
    const float* Wq    = (const float*)d_in[2];
    const float* bq    = (const float*)d_in[3];
    const float* Wk    = (const float*)d_in[4];
    const float* bk    = (const float*)d_in[5];
    const float* Wv    = (const float*)d_in[6];
    const float* bv    = (const float*)d_in[7];
    const float* Wo    = (const float*)d_in[8];
    const float* bo    = (const float*)d_in[9];
    float* out = (float*)d_out;

    dim3 gq(Dm / 128, MTOT / 128, 3);
    k_qkv<<<gq, 256>>>(query, Wq, bq, Wk, bk, Wv, bv);

    dim3 ga(Sn / 64, Bn * Hn);
    k_attn<<<ga, 128>>>(mask);

    dim3 go(Dm / 128, MTOT / 128);
    k_oproj<<<go, 256>>>(Wo, bo, out);
}

// round 4
// speedup vs baseline: 2.3986x; 1.2427x over previous
#include <cuda_runtime.h>
#include <cuda_bf16.h>
#include <math.h>
#include <stdint.h>

constexpr int Bn  = 4;
constexpr int Sn  = 2048;
constexpr int Dm  = 1024;
constexpr int Hn  = 16;
constexpr int Dh  = 64;
constexpr int MTOT = Bn * Sn;   // 8192

// f32 scratch
__device__ float g_Q[(size_t)MTOT * Dm];
__device__ float g_K[(size_t)MTOT * Dm];
__device__ float g_V[(size_t)MTOT * Dm];
__device__ float g_C[(size_t)MTOT * Dm];

// bf16 hi/lo scratch
__device__ __nv_bfloat16 g_Xhi[(size_t)MTOT * Dm];
__device__ __nv_bfloat16 g_Xlo[(size_t)MTOT * Dm];
__device__ __nv_bfloat16 g_Chi[(size_t)MTOT * Dm];
__device__ __nv_bfloat16 g_Clo[(size_t)MTOT * Dm];
__device__ __nv_bfloat16 g_Whi[4][(size_t)Dm * Dm];
__device__ __nv_bfloat16 g_Wlo[4][(size_t)Dm * Dm];

// ---------------------------------------------------------------------------
// helpers
// ---------------------------------------------------------------------------
__device__ __forceinline__ unsigned f2tf(float x) {
    unsigned r;
    asm("cvt.rna.tf32.f32 %0, %1;" : "=r"(r) : "f"(x));
    return r;
}

// tf32 m16n8k8 (attention)
__device__ __forceinline__ void mma8(float* d, const unsigned* a, const unsigned* b) {
    asm volatile(
        "mma.sync.aligned.m16n8k8.row.col.f32.tf32.tf32.f32 "
        "{%0,%1,%2,%3},{%4,%5,%6,%7},{%8,%9},{%0,%1,%2,%3};"
        : "+f"(d[0]), "+f"(d[1]), "+f"(d[2]), "+f"(d[3])
        : "r"(a[0]), "r"(a[1]), "r"(a[2]), "r"(a[3]), "r"(b[0]), "r"(b[1]));
}

// bf16 m16n8k16 (projections)
__device__ __forceinline__ void mma16(float* d, const unsigned* a, const unsigned* b) {
    asm volatile(
        "mma.sync.aligned.m16n8k16.row.col.f32.bf16.bf16.f32 "
        "{%0,%1,%2,%3},{%4,%5,%6,%7},{%8,%9},{%0,%1,%2,%3};"
        : "+f"(d[0]), "+f"(d[1]), "+f"(d[2]), "+f"(d[3])
        : "r"(a[0]), "r"(a[1]), "r"(a[2]), "r"(a[3]), "r"(b[0]), "r"(b[1]));
}

// ---------------------------------------------------------------------------
// fp32 -> (bf16 hi, bf16 lo) split conversion
// ---------------------------------------------------------------------------
__global__ __launch_bounds__(256)
void k_cvt(const float* __restrict__ src, __nv_bfloat16* __restrict__ hi,
           __nv_bfloat16* __restrict__ lo, int n4)
{
    int i = blockIdx.x * blockDim.x + threadIdx.x;
    if (i >= n4) return;
    float4 v = reinterpret_cast<const float4*>(src)[i];
    __nv_bfloat16 h0 = __float2bfloat16_rn(v.x);
    __nv_bfloat16 h1 = __float2bfloat16_rn(v.y);
    __nv_bfloat16 h2 = __float2bfloat16_rn(v.z);
    __nv_bfloat16 h3 = __float2bfloat16_rn(v.w);
    __nv_bfloat16 l0 = __float2bfloat16_rn(v.x - __bfloat162float(h0));
    __nv_bfloat16 l1 = __float2bfloat16_rn(v.y - __bfloat162float(h1));
    __nv_bfloat16 l2 = __float2bfloat16_rn(v.z - __bfloat162float(h2));
    __nv_bfloat16 l3 = __float2bfloat16_rn(v.w - __bfloat162float(h3));
    reinterpret_cast<__nv_bfloat162*>(hi)[i * 2 + 0] = __nv_bfloat162(h0, h1);
    reinterpret_cast<__nv_bfloat162*>(hi)[i * 2 + 1] = __nv_bfloat162(h2, h3);
    reinterpret_cast<__nv_bfloat162*>(lo)[i * 2 + 0] = __nv_bfloat162(l0, l1);
    reinterpret_cast<__nv_bfloat162*>(lo)[i * 2 + 1] = __nv_bfloat162(l2, l3);
}

// ---------------------------------------------------------------------------
// Split-bf16 GEMM: C[m][n] = A[m][:] . W[n][:] + bias[n]
// Block tile 128x128, K-stage 32 bf16 (2 x k16), double-buffered smem.
// 8 warps in 2(M) x 4(N); warp tile 64x32. 3 passes: hi*hi + hi*lo + lo*hi.
// round_out: store values rna-rounded to tf32 bit patterns (for attention).
// ---------------------------------------------------------------------------
constexpr int ROWU  = 20;               // uints per 128-row (16 data + 4 pad)
constexpr int TILEU = 128 * ROWU;       // 2560 uints per tile
constexpr int GEMM_SMEM = 2 * 4 * TILEU * 4;   // 81920 bytes

__global__ __launch_bounds__(256)
void k_gemm(const __nv_bfloat16* __restrict__ Ahi,
            const __nv_bfloat16* __restrict__ Alo,
            const __nv_bfloat16* __restrict__ Bhi,
            const __nv_bfloat16* __restrict__ Blo,
            const float* __restrict__ bias,
            float* __restrict__ C, int round_out)
{
    extern __shared__ unsigned sm[];   // [buf][mat][TILEU]

    const int tid  = threadIdx.x;
    const int lane = tid & 31;
    const int warp = tid >> 5;
    const int wm   = warp >> 2;
    const int wn   = warp & 3;
    const int m0   = blockIdx.y * 128;
    const int n0   = blockIdx.x * 128;

    const int r  = tid >> 1;          // 0..127
    const int c0 = (tid & 1) * 8;     // uint col 0 or 8

    const unsigned* gp[4];
    gp[0] = reinterpret_cast<const unsigned*>(Ahi) + (size_t)(m0 + r) * (Dm / 2) + c0;
    gp[1] = reinterpret_cast<const unsigned*>(Alo) + (size_t)(m0 + r) * (Dm / 2) + c0;
    gp[2] = reinterpret_cast<const unsigned*>(Bhi) + (size_t)(n0 + r) * (Dm / 2) + c0;
    gp[3] = reinterpret_cast<const unsigned*>(Blo) + (size_t)(n0 + r) * (Dm / 2) + c0;
    const int stoff = r * ROWU + c0;

    float acc[4][4][4];
#pragma unroll
    for (int mf = 0; mf < 4; ++mf)
#pragma unroll
        for (int nf = 0; nf < 4; ++nf)
#pragma unroll
            for (int j = 0; j < 4; ++j) acc[mf][nf][j] = 0.f;

    uint4 ld[4][2];

    // prologue: stage 0
#pragma unroll
    for (int mat = 0; mat < 4; ++mat) {
        ld[mat][0] = *reinterpret_cast<const uint4*>(gp[mat]);
        ld[mat][1] = *reinterpret_cast<const uint4*>(gp[mat] + 4);
    }
#pragma unroll
    for (int mat = 0; mat < 4; ++mat) {
        *reinterpret_cast<uint4*>(sm + mat * TILEU + stoff)     = ld[mat][0];
        *reinterpret_cast<uint4*>(sm + mat * TILEU + stoff + 4) = ld[mat][1];
    }
    __syncthreads();

    int buf = 0;
    const int NSTAGE = Dm / 32;   // 32

    for (int st = 0; st < NSTAGE; ++st) {
        if (st + 1 < NSTAGE) {
#pragma unroll
            for (int mat = 0; mat < 4; ++mat) {
                ld[mat][0] = *reinterpret_cast<const uint4*>(gp[mat] + (st + 1) * 16);
                ld[mat][1] = *reinterpret_cast<const uint4*>(gp[mat] + (st + 1) * 16 + 4);
            }
        }

        const unsigned* As_hi = sm + (buf * 4 + 0) * TILEU;
        const unsigned* As_lo = sm + (buf * 4 + 1) * TILEU;
        const unsigned* Bs_hi = sm + (buf * 4 + 2) * TILEU;
        const unsigned* Bs_lo = sm + (buf * 4 + 3) * TILEU;

#pragma unroll
        for (int ks = 0; ks < 2; ++ks) {
            const int tcol = ks * 8 + (lane & 3);
            unsigned ahi[4][4], alo[4][4], bhi[4][2], blo[4][2];
#pragma unroll
            for (int mf = 0; mf < 4; ++mf) {
                const int ar = (wm * 64 + mf * 16 + (lane >> 2)) * ROWU + tcol;
                ahi[mf][0] = As_hi[ar];
                ahi[mf][1] = As_hi[ar + 8 * ROWU];
                ahi[mf][2] = As_hi[ar + 4];
                ahi[mf][3] = As_hi[ar + 8 * ROWU + 4];
                alo[mf][0] = As_lo[ar];
                alo[mf][1] = As_lo[ar + 8 * ROWU];
                alo[mf][2] = As_lo[ar + 4];
                alo[mf][3] = As_lo[ar + 8 * ROWU + 4];
            }
#pragma unroll
            for (int nf = 0; nf < 4; ++nf) {
                const int br = (wn * 32 + nf * 8 + (lane >> 2)) * ROWU + tcol;
                bhi[nf][0] = Bs_hi[br];
                bhi[nf][1] = Bs_hi[br + 4];
                blo[nf][0] = Bs_lo[br];
                blo[nf][1] = Bs_lo[br + 4];
            }
#pragma unroll
            for (int mf = 0; mf < 4; ++mf)
#pragma unroll
                for (int nf = 0; nf < 4; ++nf) {
                    mma16(acc[mf][nf], ahi[mf], bhi[nf]);
                    mma16(acc[mf][nf], ahi[mf], blo[nf]);
                    mma16(acc[mf][nf], alo[mf], bhi[nf]);
                }
        }

        if (st + 1 < NSTAGE) {
            const int nb = buf ^ 1;
#pragma unroll
            for (int mat = 0; mat < 4; ++mat) {
                *reinterpret_cast<uint4*>(sm + (nb * 4 + mat) * TILEU + stoff)     = ld[mat][0];
                *reinterpret_cast<uint4*>(sm + (nb * 4 + mat) * TILEU + stoff + 4) = ld[mat][1];
            }
        }
        __syncthreads();
        buf ^= 1;
    }

    // epilogue
#pragma unroll
    for (int mf = 0; mf < 4; ++mf) {
        const int r0 = m0 + wm * 64 + mf * 16 + (lane >> 2);
#pragma unroll
        for (int nf = 0; nf < 4; ++nf) {
            const int c = n0 + wn * 32 + nf * 8 + (lane & 3) * 2;
            float2 bv = *reinterpret_cast<const float2*>(bias + c);
            float o0x = acc[mf][nf][0] + bv.x;
            float o0y = acc[mf][nf][1] + bv.y;
            float o1x = acc[mf][nf][2] + bv.x;
            float o1y = acc[mf][nf][3] + bv.y;
            if (round_out) {
                o0x = __uint_as_float(f2tf(o0x));
                o0y = __uint_as_float(f2tf(o0y));
                o1x = __uint_as_float(f2tf(o1x));
                o1y = __uint_as_float(f2tf(o1y));
            }
            *reinterpret_cast<float2*>(C + (size_t)r0 * Dm + c)       = make_float2(o0x, o0y);
            *reinterpret_cast<float2*>(C + (size_t)(r0 + 8) * Dm + c) = make_float2(o1x, o1y);
        }
    }
}

// ---------------------------------------------------------------------------
// Flash attention, tf32 mma, zero in-loop cvt (g_Q/K/V pre-rounded to tf32).
// Block: 128 threads (4 warps), 64 query rows, one (b,h). Key tiles of 64.
// ---------------------------------------------------------------------------
__global__ __launch_bounds__(128)
void k_attn(const int* __restrict__ mask)
{
    __shared__ float Ks[64][68];   // [key][d]; reused as P [qrow][key]
    __shared__ float Vs[64][72];   // [key][d]
    __shared__ int   msk[64];

    const int tid  = threadIdx.x;
    const int lane = tid & 31;
    const int wq   = tid >> 5;
    const int bh   = blockIdx.y;
    const int b    = bh >> 4;
    const int h    = bh & 15;
    const int q0   = blockIdx.x * 64;

    // Q fragments: pre-rounded tf32 values; *0.125f (power of 2) stays exact
    unsigned qf[8][4];
    {
        const float* qbase = g_Q + ((size_t)(b * Sn + q0 + wq * 16) * Dm + h * Dh);
#pragma unroll
        for (int k8 = 0; k8 < 8; ++k8)
#pragma unroll
            for (int j = 0; j < 4; ++j) {
                int row = (lane >> 2) + ((j & 1) << 3);
                int col = k8 * 8 + (lane & 3) + ((j >> 1) << 2);
                qf[k8][j] = __float_as_uint(qbase[(size_t)row * Dm + col] * 0.125f);
            }
    }

    float of[8][4];
#pragma unroll
    for (int nf = 0; nf < 8; ++nf)
#pragma unroll
        for (int j = 0; j < 4; ++j) of[nf][j] = 0.f;

    float m0r = -INFINITY, m1r = -INFINITY;
    float l0 = 0.f, l1 = 0.f;

    for (int kt = 0; kt < Sn / 64; ++kt) {
        __syncthreads();
        {
            const int row  = tid >> 1;
            const int half = (tid & 1) * 8;
            const float* kp = g_K + ((size_t)(b * Sn + kt * 64 + row) * Dm + h * Dh);
            const float* vp = g_V + ((size_t)(b * Sn + kt * 64 + row) * Dm + h * Dh);
#pragma unroll
            for (int i = 0; i < 8; ++i) {
                float4 kv = *reinterpret_cast<const float4*>(kp + (half + i) * 4);
                float4 vv = *reinterpret_cast<const float4*>(vp + (half + i) * 4);
                *reinterpret_cast<float4*>(&Ks[row][(half + i) * 4]) = kv;
                *reinterpret_cast<float4*>(&Vs[row][(half + i) * 4]) = vv;
            }
            if (tid < 64) msk[tid] = mask[b * Sn + kt * 64 + tid];
        }
        __syncthreads();

        float sf[8][4];
#pragma unroll
        for (int nf = 0; nf < 8; ++nf)
#pragma unroll
            for (int j = 0; j < 4; ++j) sf[nf][j] = 0.f;

#pragma unroll
        for (int k8 = 0; k8 < 8; ++k8) {
            const int kb = k8 * 8;
#pragma unroll
            for (int nf = 0; nf < 8; ++nf) {
                unsigned bfr[2];
                bfr[0] = __float_as_uint(Ks[nf * 8 + (lane >> 2)][kb + (lane & 3)]);
                bfr[1] = __float_as_uint(Ks[nf * 8 + (lane >> 2)][kb + (lane & 3) + 4]);
                mma8(sf[nf], qf[k8], bfr);
            }
        }

        float tmax0 = -INFINITY, tmax1 = -INFINITY;
#pragma unroll
        for (int nf = 0; nf < 8; ++nf) {
            const int c = nf * 8 + (lane & 3) * 2;
            if (!msk[c])     { sf[nf][0] = -1e20f; sf[nf][2] = -1e20f; }
            if (!msk[c + 1]) { sf[nf][1] = -1e20f; sf[nf][3] = -1e20f; }
            tmax0 = fmaxf(tmax0, fmaxf(sf[nf][0], sf[nf][1]));
            tmax1 = fmaxf(tmax1, fmaxf(sf[nf][2], sf[nf][3]));
        }
        tmax0 = fmaxf(tmax0, __shfl_xor_sync(0xffffffff, tmax0, 1));
        tmax0 = fmaxf(tmax0, __shfl_xor_sync(0xffffffff, tmax0, 2));
        tmax1 = fmaxf(tmax1, __shfl_xor_sync(0xffffffff, tmax1, 1));
        tmax1 = fmaxf(tmax1, __shfl_xor_sync(0xffffffff, tmax1, 2));

        const float mn0 = fmaxf(m0r, tmax0);
        const float mn1 = fmaxf(m1r, tmax1);
        const float a0  = __expf(m0r - mn0);
        const float a1  = __expf(m1r - mn1);
        l0 *= a0; l1 *= a1;
#pragma unroll
        for (int nf = 0; nf < 8; ++nf) {
            of[nf][0] *= a0; of[nf][1] *= a0;
            of[nf][2] *= a1; of[nf][3] *= a1;
        }

        float s0 = 0.f, s1 = 0.f;
#pragma unroll
        for (int nf = 0; nf < 8; ++nf) {
            sf[nf][0] = __expf(sf[nf][0] - mn0);
            sf[nf][1] = __expf(sf[nf][1] - mn0);
            sf[nf][2] = __expf(sf[nf][2] - mn1);
            sf[nf][3] = __expf(sf[nf][3] - mn1);
            s0 += sf[nf][0] + sf[nf][1];
            s1 += sf[nf][2] + sf[nf][3];
        }
        s0 += __shfl_xor_sync(0xffffffff, s0, 1);
        s0 += __shfl_xor_sync(0xffffffff, s0, 2);
        s1 += __shfl_xor_sync(0xffffffff, s1, 1);
        s1 += __shfl_xor_sync(0xffffffff, s1, 2);
        l0 += s0; l1 += s1;
        m0r = mn0; m1r = mn1;

        __syncthreads();

#pragma unroll
        for (int nf = 0; nf < 8; ++nf) {
            const int c = nf * 8 + (lane & 3) * 2;
            const int r = wq * 16 + (lane >> 2);
            *reinterpret_cast<float2*>(&Ks[r][c])     = make_float2(sf[nf][0], sf[nf][1]);
            *reinterpret_cast<float2*>(&Ks[r + 8][c]) = make_float2(sf[nf][2], sf[nf][3]);
        }
        __syncwarp();

#pragma unroll
        for (int k8 = 0; k8 < 8; ++k8) {
            const int kb = k8 * 8;
            unsigned af[4];
#pragma unroll
            for (int j = 0; j < 4; ++j)
                af[j] = __float_as_uint(Ks[wq * 16 + (lane >> 2) + ((j & 1) << 3)]
                                          [kb + (lane & 3) + ((j >> 1) << 2)]);
#pragma unroll
            for (int nf = 0; nf < 8; ++nf) {
                unsigned bfr[2];
                bfr[0] = __float_as_uint(Vs[kb + (lane & 3)]    [nf * 8 + (lane >> 2)]);
                bfr[1] = __float_as_uint(Vs[kb + (lane & 3) + 4][nf * 8 + (lane >> 2)]);
                mma8(of[nf], af, bfr);
            }
        }
    }

    const float inv0 = 1.f / l0;
    const float inv1 = 1.f / l1;
    float* cbase = g_C + ((size_t)(b * Sn + q0 + wq * 16) * Dm + h * Dh);
#pragma unroll
    for (int nf = 0; nf < 8; ++nf) {
        const int c  = nf * 8 + (lane & 3) * 2;
        const int r  = lane >> 2;
        *reinterpret_cast<float2*>(cbase + (size_t)r * Dm + c) =
            make_float2(of[nf][0] * inv0, of[nf][1] * inv0);
        *reinterpret_cast<float2*>(cbase + (size_t)(r + 8) * Dm + c) =
            make_float2(of[nf][2] * inv1, of[nf][3] * inv1);
    }
}

// ---------------------------------------------------------------------------
// Launch
// ---------------------------------------------------------------------------
extern "C" void kernel_launch(void* const* d_in, const int* in_sizes, int n_in,
                              void* d_out, int out_size)
{
    const float* query = (const float*)d_in[0];
    const int*   mask  = (const int*)  d_in[1];
    const float* Wq    = (const float*)d_in[2];
    const float* bq    = (const float*)d_in[3];
    const float* Wk    = (const float*)d_in[4];
    const float* bk    = (const float*)d_in[5];
    const float* Wv    = (const float*)d_in[6];
    const float* bv    = (const float*)d_in[7];
    const float* Wo    = (const float*)d_in[8];
    const float* bo    = (const float*)d_in[9];
    float* out = (float*)d_out;

    static int smem_set = 0;
    if (!smem_set) {
        cudaFuncSetAttribute(k_gemm, cudaFuncAttributeMaxDynamicSharedMemorySize,
                             GEMM_SMEM);
        smem_set = 1;
    }

    __nv_bfloat16 *xhi, *xlo, *chi, *clo, *whi, *wlo;
    float *q32, *k32, *v32, *c32;
    cudaGetSymbolAddress((void**)&xhi, g_Xhi);
    cudaGetSymbolAddress((void**)&xlo, g_Xlo);
    cudaGetSymbolAddress((void**)&chi, g_Chi);
    cudaGetSymbolAddress((void**)&clo, g_Clo);
    cudaGetSymbolAddress((void**)&whi, g_Whi);
    cudaGetSymbolAddress((void**)&wlo, g_Wlo);
    cudaGetSymbolAddress((void**)&q32, g_Q);
    cudaGetSymbolAddress((void**)&k32, g_K);
    cudaGetSymbolAddress((void**)&v32, g_V);
    cudaGetSymbolAddress((void**)&c32, g_C);

    const size_t WSZ = (size_t)Dm * Dm;
    const int nX4 = MTOT * Dm / 4;
    const int nW4 = Dm * Dm / 4;

    // split conversions
    k_cvt<<<(nX4 + 255) / 256, 256>>>(query, xhi, xlo, nX4);
    k_cvt<<<(nW4 + 255) / 256, 256>>>(Wq, whi + 0 * WSZ, wlo + 0 * WSZ, nW4);
    k_cvt<<<(nW4 + 255) / 256, 256>>>(Wk, whi + 1 * WSZ, wlo + 1 * WSZ, nW4);
    k_cvt<<<(nW4 + 255) / 256, 256>>>(Wv, whi + 2 * WSZ, wlo + 2 * WSZ, nW4);
    k_cvt<<<(nW4 + 255) / 256, 256>>>(Wo, whi + 3 * WSZ, wlo + 3 * WSZ, nW4);

    // QKV projections (split-bf16 mma, outputs tf32-rounded)
    dim3 gg(Dm / 128, MTOT / 128);
    k_gemm<<<gg, 256, GEMM_SMEM>>>(xhi, xlo, whi + 0 * WSZ, wlo + 0 * WSZ, bq, q32, 1);
    k_gemm<<<gg, 256, GEMM_SMEM>>>(xhi, xlo, whi + 1 * WSZ, wlo + 1 * WSZ, bk, k32, 1);
    k_gemm<<<gg, 256, GEMM_SMEM>>>(xhi, xlo, whi + 2 * WSZ, wlo + 2 * WSZ, bv, v32, 1);

    // attention
    dim3 ga(Sn / 64, Bn * Hn);
    k_attn<<<ga, 128>>>(mask);

    // output projection
    k_cvt<<<(nX4 + 255) / 256, 256>>>(c32, chi, clo, nX4);
    k_gemm<<<gg, 256, GEMM_SMEM>>>(chi, clo, whi + 3 * WSZ, wlo + 3 * WSZ, bo, out, 0);
}

// round 5
// speedup vs baseline: 3.4644x; 1.4443x over previous
#include <cuda_runtime.h>
#include <cuda_bf16.h>
#include <math.h>
#include <stdint.h>

constexpr int Bn  = 4;
constexpr int Sn  = 2048;
constexpr int Dm  = 1024;
constexpr int Hn  = 16;
constexpr int Dh  = 64;
constexpr int MTOT = Bn * Sn;   // 8192

// f32 scratch (Q/K/V post-projection, tf32-rounded)
__device__ float g_Q[(size_t)MTOT * Dm];
__device__ float g_K[(size_t)MTOT * Dm];
__device__ float g_V[(size_t)MTOT * Dm];

// bf16 hi/lo scratch
__device__ __nv_bfloat16 g_Xhi[(size_t)MTOT * Dm];
__device__ __nv_bfloat16 g_Xlo[(size_t)MTOT * Dm];
__device__ __nv_bfloat16 g_Chi[(size_t)MTOT * Dm];
__device__ __nv_bfloat16 g_Clo[(size_t)MTOT * Dm];
__device__ __nv_bfloat16 g_Whi[4][(size_t)Dm * Dm];
__device__ __nv_bfloat16 g_Wlo[4][(size_t)Dm * Dm];

// ---------------------------------------------------------------------------
// helpers
// ---------------------------------------------------------------------------
__device__ __forceinline__ unsigned f2tf(float x) {
    unsigned r;
    asm("cvt.rna.tf32.f32 %0, %1;" : "=r"(r) : "f"(x));
    return r;
}

__device__ __forceinline__ void mma8(float* d, const unsigned* a, const unsigned* b) {
    asm volatile(
        "mma.sync.aligned.m16n8k8.row.col.f32.tf32.tf32.f32 "
        "{%0,%1,%2,%3},{%4,%5,%6,%7},{%8,%9},{%0,%1,%2,%3};"
        : "+f"(d[0]), "+f"(d[1]), "+f"(d[2]), "+f"(d[3])
        : "r"(a[0]), "r"(a[1]), "r"(a[2]), "r"(a[3]), "r"(b[0]), "r"(b[1]));
}

__device__ __forceinline__ void mma16(float* d, const unsigned* a, const unsigned* b) {
    asm volatile(
        "mma.sync.aligned.m16n8k16.row.col.f32.bf16.bf16.f32 "
        "{%0,%1,%2,%3},{%4,%5,%6,%7},{%8,%9},{%0,%1,%2,%3};"
        : "+f"(d[0]), "+f"(d[1]), "+f"(d[2]), "+f"(d[3])
        : "r"(a[0]), "r"(a[1]), "r"(a[2]), "r"(a[3]), "r"(b[0]), "r"(b[1]));
}

__device__ __forceinline__ void ldm_x4(unsigned* r, uint32_t addr) {
    asm volatile(
        "ldmatrix.sync.aligned.m8n8.x4.shared.b16 {%0,%1,%2,%3}, [%4];"
        : "=r"(r[0]), "=r"(r[1]), "=r"(r[2]), "=r"(r[3]) : "r"(addr));
}

// ---------------------------------------------------------------------------
// fp32 -> (bf16 hi, bf16 lo) split conversion
// ---------------------------------------------------------------------------
__global__ __launch_bounds__(256)
void k_cvt(const float* __restrict__ src, __nv_bfloat16* __restrict__ hi,
           __nv_bfloat16* __restrict__ lo, int n4)
{
    int i = blockIdx.x * blockDim.x + threadIdx.x;
    if (i >= n4) return;
    float4 v = reinterpret_cast<const float4*>(src)[i];
    __nv_bfloat16 h0 = __float2bfloat16_rn(v.x);
    __nv_bfloat16 h1 = __float2bfloat16_rn(v.y);
    __nv_bfloat16 h2 = __float2bfloat16_rn(v.z);
    __nv_bfloat16 h3 = __float2bfloat16_rn(v.w);
    __nv_bfloat16 l0 = __float2bfloat16_rn(v.x - __bfloat162float(h0));
    __nv_bfloat16 l1 = __float2bfloat16_rn(v.y - __bfloat162float(h1));
    __nv_bfloat16 l2 = __float2bfloat16_rn(v.z - __bfloat162float(h2));
    __nv_bfloat16 l3 = __float2bfloat16_rn(v.w - __bfloat162float(h3));
    reinterpret_cast<__nv_bfloat162*>(hi)[i * 2 + 0] = __nv_bfloat162(h0, h1);
    reinterpret_cast<__nv_bfloat162*>(hi)[i * 2 + 1] = __nv_bfloat162(h2, h3);
    reinterpret_cast<__nv_bfloat162*>(lo)[i * 2 + 0] = __nv_bfloat162(l0, l1);
    reinterpret_cast<__nv_bfloat162*>(lo)[i * 2 + 1] = __nv_bfloat162(l2, l3);
}

// ---------------------------------------------------------------------------
// Split-bf16 GEMM core with ldmatrix fragment loads.
// Block tile 128x128, K-stage 32 bf16 (2 x k16), double-buffered smem.
// 8 warps 2(M) x 4(N); warp tile 64x32. 3 passes: hi*hi + hi*lo + lo*hi.
// ---------------------------------------------------------------------------
constexpr int ROWU  = 20;               // uints per 128-row (16 data + 4 pad)
constexpr int TILEU = 128 * ROWU;       // 2560 uints per tile
constexpr int TILEB = TILEU * 4;        // 10240 bytes
constexpr int GEMM_SMEM = 2 * 4 * TILEB;   // 81920 bytes

__device__ __forceinline__ void gemm_core(
    const __nv_bfloat16* __restrict__ Ahi,
    const __nv_bfloat16* __restrict__ Alo,
    const __nv_bfloat16* __restrict__ Bhi,
    const __nv_bfloat16* __restrict__ Blo,
    const float* __restrict__ bias,
    float* __restrict__ C, int round_out)
{
    extern __shared__ unsigned sm[];   // [buf][mat][TILEU]

    const int tid  = threadIdx.x;
    const int lane = tid & 31;
    const int warp = tid >> 5;
    const int wm   = warp >> 2;
    const int wn   = warp & 3;
    const int m0   = blockIdx.y * 128;
    const int n0   = blockIdx.x * 128;

    const int r  = tid >> 1;
    const int c0 = (tid & 1) * 8;

    const unsigned* gp[4];
    gp[0] = reinterpret_cast<const unsigned*>(Ahi) + (size_t)(m0 + r) * (Dm / 2) + c0;
    gp[1] = reinterpret_cast<const unsigned*>(Alo) + (size_t)(m0 + r) * (Dm / 2) + c0;
    gp[2] = reinterpret_cast<const unsigned*>(Bhi) + (size_t)(n0 + r) * (Dm / 2) + c0;
    gp[3] = reinterpret_cast<const unsigned*>(Blo) + (size_t)(n0 + r) * (Dm / 2) + c0;
    const int stoff = r * ROWU + c0;

    // ldmatrix per-lane address offsets (bytes)
    const uint32_t smemBase = (uint32_t)__cvta_generic_to_shared(sm);
    const uint32_t aOff = ((lane & 15) * ROWU + ((lane >> 4) & 1) * 4) * 4
                          + wm * 64 * ROWU * 4;
    const uint32_t bOff = (((lane & 7) + ((lane >> 1) & 8)) * ROWU
                           + ((lane >> 3) & 1) * 4) * 4
                          + wn * 32 * ROWU * 4;

    float acc[4][4][4];
#pragma unroll
    for (int mf = 0; mf < 4; ++mf)
#pragma unroll
        for (int nf = 0; nf < 4; ++nf)
#pragma unroll
            for (int j = 0; j < 4; ++j) acc[mf][nf][j] = 0.f;

    uint4 ld[4][2];

    // prologue
#pragma unroll
    for (int mat = 0; mat < 4; ++mat) {
        ld[mat][0] = *reinterpret_cast<const uint4*>(gp[mat]);
        ld[mat][1] = *reinterpret_cast<const uint4*>(gp[mat] + 4);
    }
#pragma unroll
    for (int mat = 0; mat < 4; ++mat) {
        *reinterpret_cast<uint4*>(sm + mat * TILEU + stoff)     = ld[mat][0];
        *reinterpret_cast<uint4*>(sm + mat * TILEU + stoff + 4) = ld[mat][1];
    }
    __syncthreads();

    int buf = 0;
    const int NSTAGE = Dm / 32;

    for (int st = 0; st < NSTAGE; ++st) {
        if (st + 1 < NSTAGE) {
#pragma unroll
            for (int mat = 0; mat < 4; ++mat) {
                ld[mat][0] = *reinterpret_cast<const uint4*>(gp[mat] + (st + 1) * 16);
                ld[mat][1] = *reinterpret_cast<const uint4*>(gp[mat] + (st + 1) * 16 + 4);
            }
        }

        const uint32_t aHiB = smemBase + (buf * 4 + 0) * TILEB + aOff;
        const uint32_t aLoB = smemBase + (buf * 4 + 1) * TILEB + aOff;
        const uint32_t bHiB = smemBase + (buf * 4 + 2) * TILEB + bOff;
        const uint32_t bLoB = smemBase + (buf * 4 + 3) * TILEB + bOff;

#pragma unroll
        for (int ks = 0; ks < 2; ++ks) {
            const uint32_t kadd = ks * 32;
            unsigned ahi[4][4], alo[4][4], bhi[4][2], blo[4][2];
#pragma unroll
            for (int mf = 0; mf < 4; ++mf) {
                ldm_x4(ahi[mf], aHiB + mf * (16 * ROWU * 4) + kadd);
                ldm_x4(alo[mf], aLoB + mf * (16 * ROWU * 4) + kadd);
            }
#pragma unroll
            for (int np = 0; np < 2; ++np) {
                unsigned t[4];
                ldm_x4(t, bHiB + np * (16 * ROWU * 4) + kadd);
                bhi[np * 2][0] = t[0]; bhi[np * 2][1] = t[1];
                bhi[np * 2 + 1][0] = t[2]; bhi[np * 2 + 1][1] = t[3];
                ldm_x4(t, bLoB + np * (16 * ROWU * 4) + kadd);
                blo[np * 2][0] = t[0]; blo[np * 2][1] = t[1];
                blo[np * 2 + 1][0] = t[2]; blo[np * 2 + 1][1] = t[3];
            }
#pragma unroll
            for (int mf = 0; mf < 4; ++mf)
#pragma unroll
                for (int nf = 0; nf < 4; ++nf) {
                    mma16(acc[mf][nf], ahi[mf], bhi[nf]);
                    mma16(acc[mf][nf], ahi[mf], blo[nf]);
                    mma16(acc[mf][nf], alo[mf], bhi[nf]);
                }
        }

        if (st + 1 < NSTAGE) {
            const int nb = buf ^ 1;
#pragma unroll
            for (int mat = 0; mat < 4; ++mat) {
                *reinterpret_cast<uint4*>(sm + (nb * 4 + mat) * TILEU + stoff)     = ld[mat][0];
                *reinterpret_cast<uint4*>(sm + (nb * 4 + mat) * TILEU + stoff + 4) = ld[mat][1];
            }
        }
        __syncthreads();
        buf ^= 1;
    }

    // epilogue
#pragma unroll
    for (int mf = 0; mf < 4; ++mf) {
        const int r0 = m0 + wm * 64 + mf * 16 + (lane >> 2);
#pragma unroll
        for (int nf = 0; nf < 4; ++nf) {
            const int c = n0 + wn * 32 + nf * 8 + (lane & 3) * 2;
            float2 bv = *reinterpret_cast<const float2*>(bias + c);
            float o0x = acc[mf][nf][0] + bv.x;
            float o0y = acc[mf][nf][1] + bv.y;
            float o1x = acc[mf][nf][2] + bv.x;
            float o1y = acc[mf][nf][3] + bv.y;
            if (round_out) {
                o0x = __uint_as_float(f2tf(o0x));
                o0y = __uint_as_float(f2tf(o0y));
                o1x = __uint_as_float(f2tf(o1x));
                o1y = __uint_as_float(f2tf(o1y));
            }
            *reinterpret_cast<float2*>(C + (size_t)r0 * Dm + c)       = make_float2(o0x, o0y);
            *reinterpret_cast<float2*>(C + (size_t)(r0 + 8) * Dm + c) = make_float2(o1x, o1y);
        }
    }
}

// QKV fused launch: blockIdx.z selects the projection
__global__ __launch_bounds__(256)
void k_qkv3(const __nv_bfloat16* __restrict__ xhi, const __nv_bfloat16* __restrict__ xlo,
            const __nv_bfloat16* __restrict__ whi, const __nv_bfloat16* __restrict__ wlo,
            const float* __restrict__ bq, const float* __restrict__ bk,
            const float* __restrict__ bv,
            float* __restrict__ q, float* __restrict__ k, float* __restrict__ v)
{
    const size_t WSZ = (size_t)Dm * Dm;
    const float* bias;
    float* out;
    if (blockIdx.z == 0)      { bias = bq; out = q; }
    else if (blockIdx.z == 1) { bias = bk; out = k; }
    else                      { bias = bv; out = v; }
    gemm_core(xhi, xlo, whi + blockIdx.z * WSZ, wlo + blockIdx.z * WSZ, bias, out, 1);
}

__global__ __launch_bounds__(256)
void k_oproj(const __nv_bfloat16* __restrict__ chi, const __nv_bfloat16* __restrict__ clo,
             const __nv_bfloat16* __restrict__ whi, const __nv_bfloat16* __restrict__ wlo,
             const float* __restrict__ bo, float* __restrict__ out)
{
    gemm_core(chi, clo, whi, wlo, bo, out, 0);
}

// ---------------------------------------------------------------------------
// Flash attention, tf32 mma, zero in-loop cvt.
// Block: 256 threads (8 warps), 128 query rows, one (b,h). Key tiles of 64.
// Separate P buffer (no Ks aliasing) -> 2 syncthreads per tile.
// Epilogue writes bf16 hi/lo ctx directly.
// ---------------------------------------------------------------------------
constexpr int KS_STRIDE = 68;
constexpr int VS_STRIDE = 72;
constexpr int PS_STRIDE = 68;
constexpr int ATTN_SMEM = (64 * KS_STRIDE + 64 * VS_STRIDE + 128 * PS_STRIDE) * 4 + 256;

__global__ __launch_bounds__(256)
void k_attn(const int* __restrict__ mask,
            __nv_bfloat16* __restrict__ Chi, __nv_bfloat16* __restrict__ Clo)
{
    extern __shared__ float dynf[];
    float* Ks = dynf;                       // [64][68]
    float* Vs = Ks + 64 * KS_STRIDE;        // [64][72]
    float* Ps = Vs + 64 * VS_STRIDE;        // [128][68]
    int*   msk = (int*)(Ps + 128 * PS_STRIDE);   // [64]

    const int tid  = threadIdx.x;
    const int lane = tid & 31;
    const int wq   = tid >> 5;             // 0..7, warp owns rows wq*16..+15
    const int bh   = blockIdx.y;
    const int b    = bh >> 4;
    const int h    = bh & 15;
    const int q0   = blockIdx.x * 128;

    // Q fragments (pre-rounded tf32; *0.125f exact)
    unsigned qf[8][4];
    {
        const float* qbase = g_Q + ((size_t)(b * Sn + q0 + wq * 16) * Dm + h * Dh);
#pragma unroll
        for (int k8 = 0; k8 < 8; ++k8)
#pragma unroll
            for (int j = 0; j < 4; ++j) {
                int row = (lane >> 2) + ((j & 1) << 3);
                int col = k8 * 8 + (lane & 3) + ((j >> 1) << 2);
                qf[k8][j] = __float_as_uint(qbase[(size_t)row * Dm + col] * 0.125f);
            }
    }

    float of[8][4];
#pragma unroll
    for (int nf = 0; nf < 8; ++nf)
#pragma unroll
        for (int j = 0; j < 4; ++j) of[nf][j] = 0.f;

    float m0r = -INFINITY, m1r = -INFINITY;
    float l0 = 0.f, l1 = 0.f;

    for (int kt = 0; kt < Sn / 64; ++kt) {
        __syncthreads();   // prev tile fully consumed
        {
            const int row = tid >> 2;             // 0..63
            const int seg = (tid & 3) * 16;       // 0,16,32,48
            const float* kp = g_K + ((size_t)(b * Sn + kt * 64 + row) * Dm + h * Dh + seg);
            const float* vp = g_V + ((size_t)(b * Sn + kt * 64 + row) * Dm + h * Dh + seg);
#pragma unroll
            for (int i = 0; i < 4; ++i) {
                *reinterpret_cast<float4*>(&Ks[row * KS_STRIDE + seg + i * 4]) =
                    *reinterpret_cast<const float4*>(kp + i * 4);
                *reinterpret_cast<float4*>(&Vs[row * VS_STRIDE + seg + i * 4]) =
                    *reinterpret_cast<const float4*>(vp + i * 4);
            }
            if (tid < 64) msk[tid] = mask[b * Sn + kt * 64 + tid];
        }
        __syncthreads();

        // S = Q . K^T
        float sf[8][4];
#pragma unroll
        for (int nf = 0; nf < 8; ++nf)
#pragma unroll
            for (int j = 0; j < 4; ++j) sf[nf][j] = 0.f;

#pragma unroll
        for (int k8 = 0; k8 < 8; ++k8) {
            const int kb = k8 * 8;
#pragma unroll
            for (int nf = 0; nf < 8; ++nf) {
                unsigned bfr[2];
                bfr[0] = __float_as_uint(Ks[(nf * 8 + (lane >> 2)) * KS_STRIDE + kb + (lane & 3)]);
                bfr[1] = __float_as_uint(Ks[(nf * 8 + (lane >> 2)) * KS_STRIDE + kb + (lane & 3) + 4]);
                mma8(sf[nf], qf[k8], bfr);
            }
        }

        // mask + online softmax
        float tmax0 = -INFINITY, tmax1 = -INFINITY;
#pragma unroll
        for (int nf = 0; nf < 8; ++nf) {
            const int c = nf * 8 + (lane & 3) * 2;
            if (!msk[c])     { sf[nf][0] = -1e20f; sf[nf][2] = -1e20f; }
            if (!msk[c + 1]) { sf[nf][1] = -1e20f; sf[nf][3] = -1e20f; }
            tmax0 = fmaxf(tmax0, fmaxf(sf[nf][0], sf[nf][1]));
            tmax1 = fmaxf(tmax1, fmaxf(sf[nf][2], sf[nf][3]));
        }
        tmax0 = fmaxf(tmax0, __shfl_xor_sync(0xffffffff, tmax0, 1));
        tmax0 = fmaxf(tmax0, __shfl_xor_sync(0xffffffff, tmax0, 2));
        tmax1 = fmaxf(tmax1, __shfl_xor_sync(0xffffffff, tmax1, 1));
        tmax1 = fmaxf(tmax1, __shfl_xor_sync(0xffffffff, tmax1, 2));

        const float mn0 = fmaxf(m0r, tmax0);
        const float mn1 = fmaxf(m1r, tmax1);
        const float a0  = __expf(m0r - mn0);
        const float a1  = __expf(m1r - mn1);
        l0 *= a0; l1 *= a1;
#pragma unroll
        for (int nf = 0; nf < 8; ++nf) {
            of[nf][0] *= a0; of[nf][1] *= a0;
            of[nf][2] *= a1; of[nf][3] *= a1;
        }

        float s0 = 0.f, s1 = 0.f;
#pragma unroll
        for (int nf = 0; nf < 8; ++nf) {
            sf[nf][0] = __expf(sf[nf][0] - mn0);
            sf[nf][1] = __expf(sf[nf][1] - mn0);
            sf[nf][2] = __expf(sf[nf][2] - mn1);
            sf[nf][3] = __expf(sf[nf][3] - mn1);
            s0 += sf[nf][0] + sf[nf][1];
            s1 += sf[nf][2] + sf[nf][3];
        }
        s0 += __shfl_xor_sync(0xffffffff, s0, 1);
        s0 += __shfl_xor_sync(0xffffffff, s0, 2);
        s1 += __shfl_xor_sync(0xffffffff, s1, 1);
        s1 += __shfl_xor_sync(0xffffffff, s1, 2);
        l0 += s0; l1 += s1;
        m0r = mn0; m1r = mn1;

        // write P to own rows (warp-private region), no block sync needed
#pragma unroll
        for (int nf = 0; nf < 8; ++nf) {
            const int c = nf * 8 + (lane & 3) * 2;
            const int r = wq * 16 + (lane >> 2);
            *reinterpret_cast<float2*>(&Ps[r * PS_STRIDE + c]) =
                make_float2(sf[nf][0], sf[nf][1]);
            *reinterpret_cast<float2*>(&Ps[(r + 8) * PS_STRIDE + c]) =
                make_float2(sf[nf][2], sf[nf][3]);
        }
        __syncwarp();

        // O += P . V
#pragma unroll
        for (int k8 = 0; k8 < 8; ++k8) {
            const int kb = k8 * 8;
            unsigned af[4];
#pragma unroll
            for (int j = 0; j < 4; ++j)
                af[j] = __float_as_uint(
                    Ps[(wq * 16 + (lane >> 2) + ((j & 1) << 3)) * PS_STRIDE
                       + kb + (lane & 3) + ((j >> 1) << 2)]);
#pragma unroll
            for (int nf = 0; nf < 8; ++nf) {
                unsigned bfr[2];
                bfr[0] = __float_as_uint(Vs[(kb + (lane & 3)) * VS_STRIDE + nf * 8 + (lane >> 2)]);
                bfr[1] = __float_as_uint(Vs[(kb + (lane & 3) + 4) * VS_STRIDE + nf * 8 + (lane >> 2)]);
                mma8(of[nf], af, bfr);
            }
        }
    }

    // epilogue: normalize, split to bf16 hi/lo, write
    const float inv0 = 1.f / l0;
    const float inv1 = 1.f / l1;
    const size_t rbase = (size_t)(b * Sn + q0 + wq * 16);
#pragma unroll
    for (int nf = 0; nf < 8; ++nf) {
        const int c = h * Dh + nf * 8 + (lane & 3) * 2;
        const int r = lane >> 2;
        float v00 = of[nf][0] * inv0, v01 = of[nf][1] * inv0;
        float v10 = of[nf][2] * inv1, v11 = of[nf][3] * inv1;
        __nv_bfloat16 h00 = __float2bfloat16_rn(v00), h01 = __float2bfloat16_rn(v01);
        __nv_bfloat16 h10 = __float2bfloat16_rn(v10), h11 = __float2bfloat16_rn(v11);
        __nv_bfloat16 l00 = __float2bfloat16_rn(v00 - __bfloat162float(h00));
        __nv_bfloat16 l01 = __float2bfloat16_rn(v01 - __bfloat162float(h01));
        __nv_bfloat16 l10 = __float2bfloat16_rn(v10 - __bfloat162float(h10));
        __nv_bfloat16 l11 = __float2bfloat16_rn(v11 - __bfloat162float(h11));
        *reinterpret_cast<__nv_bfloat162*>(Chi + (rbase + r) * Dm + c)     = __nv_bfloat162(h00, h01);
        *reinterpret_cast<__nv_bfloat162*>(Chi + (rbase + r + 8) * Dm + c) = __nv_bfloat162(h10, h11);
        *reinterpret_cast<__nv_bfloat162*>(Clo + (rbase + r) * Dm + c)     = __nv_bfloat162(l00, l01);
        *reinterpret_cast<__nv_bfloat162*>(Clo + (rbase + r + 8) * Dm + c) = __nv_bfloat162(l10, l11);
    }
}

// ---------------------------------------------------------------------------
// Launch
// ---------------------------------------------------------------------------
extern "C" void kernel_launch(void* const* d_in, const int* in_sizes, int n_in,
                              void* d_out, int out_size)
{
    const float* query = (const float*)d_in[0];
    const int*   mask  = (const int*)  d_in[1];
    const float* Wq    = (const float*)d_in[2];
    const float* bq    = (const float*)d_in[3];
    const float* Wk    = (const float*)d_in[4];
    const float* bk    = (const float*)d_in[5];
    const float* Wv    = (const float*)d_in[6];
    const float* bv    = (const float*)d_in[7];
    const float* Wo    = (const float*)d_in[8];
    const float* bo    = (const float*)d_in[9];
    float* out = (float*)d_out;

    static int init_done = 0;
    if (!init_done) {
        cudaFuncSetAttribute(k_qkv3, cudaFuncAttributeMaxDynamicSharedMemorySize, GEMM_SMEM);
        cudaFuncSetAttribute(k_oproj, cudaFuncAttributeMaxDynamicSharedMemorySize, GEMM_SMEM);
        cudaFuncSetAttribute(k_attn, cudaFuncAttributeMaxDynamicSharedMemorySize, ATTN_SMEM);
        init_done = 1;
    }

    __nv_bfloat16 *xhi, *xlo, *chi, *clo, *whi, *wlo;
    float *q32, *k32, *v32;
    cudaGetSymbolAddress((void**)&xhi, g_Xhi);
    cudaGetSymbolAddress((void**)&xlo, g_Xlo);
    cudaGetSymbolAddress((void**)&chi, g_Chi);
    cudaGetSymbolAddress((void**)&clo, g_Clo);
    cudaGetSymbolAddress((void**)&whi, g_Whi);
    cudaGetSymbolAddress((void**)&wlo, g_Wlo);
    cudaGetSymbolAddress((void**)&q32, g_Q);
    cudaGetSymbolAddress((void**)&k32, g_K);
    cudaGetSymbolAddress((void**)&v32, g_V);

    const size_t WSZ = (size_t)Dm * Dm;
    const int nX4 = MTOT * Dm / 4;
    const int nW4 = Dm * Dm / 4;

    // split conversions
    k_cvt<<<(nX4 + 255) / 256, 256>>>(query, xhi, xlo, nX4);
    k_cvt<<<(nW4 + 255) / 256, 256>>>(Wq, whi + 0 * WSZ, wlo + 0 * WSZ, nW4);
    k_cvt<<<(nW4 + 255) / 256, 256>>>(Wk, whi + 1 * WSZ, wlo + 1 * WSZ, nW4);
    k_cvt<<<(nW4 + 255) / 256, 256>>>(Wv, whi + 2 * WSZ, wlo + 2 * WSZ, nW4);
    k_cvt<<<(nW4 + 255) / 256, 256>>>(Wo, whi + 3 * WSZ, wlo + 3 * WSZ, nW4);

    // fused QKV projections
    dim3 gq(Dm / 128, MTOT / 128, 3);
    k_qkv3<<<gq, 256, GEMM_SMEM>>>(xhi, xlo, whi, wlo, bq, bk, bv, q32, k32, v32);

    // attention (writes bf16 hi/lo ctx)
    dim3 ga(Sn / 128, Bn * Hn);
    k_attn<<<ga, 256, ATTN_SMEM>>>(mask, chi, clo);

    // output projection
    dim3 go(Dm / 128, MTOT / 128);
    k_oproj<<<go, 256, GEMM_SMEM>>>(chi, clo, whi + 3 * WSZ, wlo + 3 * WSZ, bo, out);
}

// round 7
// speedup vs baseline: 3.9606x; 1.1432x over previous
#include <cuda_runtime.h>
#include <cuda_bf16.h>
#include <cuda_fp16.h>
#include <math.h>
#include <stdint.h>

constexpr int Bn  = 4;
constexpr int Sn  = 2048;
constexpr int Dm  = 1024;
constexpr int Hn  = 16;
constexpr int Dh  = 64;
constexpr int MTOT = Bn * Sn;   // 8192

// f32 scratch (Q/K/V post-projection, tf32-rounded)
__device__ float g_Q[(size_t)MTOT * Dm];
__device__ float g_K[(size_t)MTOT * Dm];
__device__ float g_V[(size_t)MTOT * Dm];

// bf16 hi/lo scratch
__device__ __nv_bfloat16 g_Xhi[(size_t)MTOT * Dm];
__device__ __nv_bfloat16 g_Xlo[(size_t)MTOT * Dm];
__device__ __nv_bfloat16 g_Chi[(size_t)MTOT * Dm];
__device__ __nv_bfloat16 g_Clo[(size_t)MTOT * Dm];
__device__ __nv_bfloat16 g_Whi[4][(size_t)Dm * Dm];
__device__ __nv_bfloat16 g_Wlo[4][(size_t)Dm * Dm];

// ---------------------------------------------------------------------------
// helpers
// ---------------------------------------------------------------------------
__device__ __forceinline__ unsigned f2tf(float x) {
    unsigned r;
    asm("cvt.rna.tf32.f32 %0, %1;" : "=r"(r) : "f"(x));
    return r;
}

__device__ __forceinline__ float ex2(float x) {
    float y;
    asm("ex2.approx.ftz.f32 %0, %1;" : "=f"(y) : "f"(x));
    return y;
}

__device__ __forceinline__ void mma8(float* d, const unsigned* a, const unsigned* b) {
    asm volatile(
        "mma.sync.aligned.m16n8k8.row.col.f32.tf32.tf32.f32 "
        "{%0,%1,%2,%3},{%4,%5,%6,%7},{%8,%9},{%0,%1,%2,%3};"
        : "+f"(d[0]), "+f"(d[1]), "+f"(d[2]), "+f"(d[3])
        : "r"(a[0]), "r"(a[1]), "r"(a[2]), "r"(a[3]), "r"(b[0]), "r"(b[1]));
}

__device__ __forceinline__ void mma16(float* d, const unsigned* a, const unsigned* b) {
    asm volatile(
        "mma.sync.aligned.m16n8k16.row.col.f32.bf16.bf16.f32 "
        "{%0,%1,%2,%3},{%4,%5,%6,%7},{%8,%9},{%0,%1,%2,%3};"
        : "+f"(d[0]), "+f"(d[1]), "+f"(d[2]), "+f"(d[3])
        : "r"(a[0]), "r"(a[1]), "r"(a[2]), "r"(a[3]), "r"(b[0]), "r"(b[1]));
}

__device__ __forceinline__ void mma16h(float* d, const unsigned* a, const unsigned* b) {
    asm volatile(
        "mma.sync.aligned.m16n8k16.row.col.f32.f16.f16.f32 "
        "{%0,%1,%2,%3},{%4,%5,%6,%7},{%8,%9},{%0,%1,%2,%3};"
        : "+f"(d[0]), "+f"(d[1]), "+f"(d[2]), "+f"(d[3])
        : "r"(a[0]), "r"(a[1]), "r"(a[2]), "r"(a[3]), "r"(b[0]), "r"(b[1]));
}

__device__ __forceinline__ void ldm_x4(unsigned* r, uint32_t addr) {
    asm volatile(
        "ldmatrix.sync.aligned.m8n8.x4.shared.b16 {%0,%1,%2,%3}, [%4];"
        : "=r"(r[0]), "=r"(r[1]), "=r"(r[2]), "=r"(r[3]) : "r"(addr));
}

__device__ __forceinline__ unsigned packh2(float a, float b) {
    __half2 h = __floats2half2_rn(a, b);    // low = a
    return *reinterpret_cast<unsigned*>(&h);
}

// ---------------------------------------------------------------------------
// fp32 -> (bf16 hi, bf16 lo) split conversion
// ---------------------------------------------------------------------------
__global__ __launch_bounds__(256)
void k_cvt(const float* __restrict__ src, __nv_bfloat16* __restrict__ hi,
           __nv_bfloat16* __restrict__ lo, int n4)
{
    int i = blockIdx.x * blockDim.x + threadIdx.x;
    if (i >= n4) return;
    float4 v = reinterpret_cast<const float4*>(src)[i];
    __nv_bfloat16 h0 = __float2bfloat16_rn(v.x);
    __nv_bfloat16 h1 = __float2bfloat16_rn(v.y);
    __nv_bfloat16 h2 = __float2bfloat16_rn(v.z);
    __nv_bfloat16 h3 = __float2bfloat16_rn(v.w);
    __nv_bfloat16 l0 = __float2bfloat16_rn(v.x - __bfloat162float(h0));
    __nv_bfloat16 l1 = __float2bfloat16_rn(v.y - __bfloat162float(h1));
    __nv_bfloat16 l2 = __float2bfloat16_rn(v.z - __bfloat162float(h2));
    __nv_bfloat16 l3 = __float2bfloat16_rn(v.w - __bfloat162float(h3));
    reinterpret_cast<__nv_bfloat162*>(hi)[i * 2 + 0] = __nv_bfloat162(h0, h1);
    reinterpret_cast<__nv_bfloat162*>(hi)[i * 2 + 1] = __nv_bfloat162(h2, h3);
    reinterpret_cast<__nv_bfloat162*>(lo)[i * 2 + 0] = __nv_bfloat162(l0, l1);
    reinterpret_cast<__nv_bfloat162*>(lo)[i * 2 + 1] = __nv_bfloat162(l2, l3);
}

// ---------------------------------------------------------------------------
// Split-bf16 GEMM core with ldmatrix fragment loads (validated round 5).
// ---------------------------------------------------------------------------
constexpr int ROWU  = 20;
constexpr int TILEU = 128 * ROWU;
constexpr int TILEB = TILEU * 4;
constexpr int GEMM_SMEM = 2 * 4 * TILEB;   // 81920 bytes

__device__ __forceinline__ void gemm_core(
    const __nv_bfloat16* __restrict__ Ahi,
    const __nv_bfloat16* __restrict__ Alo,
    const __nv_bfloat16* __restrict__ Bhi,
    const __nv_bfloat16* __restrict__ Blo,
    const float* __restrict__ bias,
    float* __restrict__ C, int round_out)
{
    extern __shared__ unsigned sm[];

    const int tid  = threadIdx.x;
    const int lane = tid & 31;
    const int warp = tid >> 5;
    const int wm   = warp >> 2;
    const int wn   = warp & 3;
    const int m0   = blockIdx.y * 128;
    const int n0   = blockIdx.x * 128;

    const int r  = tid >> 1;
    const int c0 = (tid & 1) * 8;

    const unsigned* gp[4];
    gp[0] = reinterpret_cast<const unsigned*>(Ahi) + (size_t)(m0 + r) * (Dm / 2) + c0;
    gp[1] = reinterpret_cast<const unsigned*>(Alo) + (size_t)(m0 + r) * (Dm / 2) + c0;
    gp[2] = reinterpret_cast<const unsigned*>(Bhi) + (size_t)(n0 + r) * (Dm / 2) + c0;
    gp[3] = reinterpret_cast<const unsigned*>(Blo) + (size_t)(n0 + r) * (Dm / 2) + c0;
    const int stoff = r * ROWU + c0;

    const uint32_t smemBase = (uint32_t)__cvta_generic_to_shared(sm);
    const uint32_t aOff = ((lane & 15) * ROWU + ((lane >> 4) & 1) * 4) * 4
                          + wm * 64 * ROWU * 4;
    const uint32_t bOff = (((lane & 7) + ((lane >> 1) & 8)) * ROWU
                           + ((lane >> 3) & 1) * 4) * 4
                          + wn * 32 * ROWU * 4;

    float acc[4][4][4];
#pragma unroll
    for (int mf = 0; mf < 4; ++mf)
#pragma unroll
        for (int nf = 0; nf < 4; ++nf)
#pragma unroll
            for (int j = 0; j < 4; ++j) acc[mf][nf][j] = 0.f;

    uint4 ld[4][2];

#pragma unroll
    for (int mat = 0; mat < 4; ++mat) {
        ld[mat][0] = *reinterpret_cast<const uint4*>(gp[mat]);
        ld[mat][1] = *reinterpret_cast<const uint4*>(gp[mat] + 4);
    }
#pragma unroll
    for (int mat = 0; mat < 4; ++mat) {
        *reinterpret_cast<uint4*>(sm + mat * TILEU + stoff)     = ld[mat][0];
        *reinterpret_cast<uint4*>(sm + mat * TILEU + stoff + 4) = ld[mat][1];
    }
    __syncthreads();

    int buf = 0;
    const int NSTAGE = Dm / 32;

    for (int st = 0; st < NSTAGE; ++st) {
        if (st + 1 < NSTAGE) {
#pragma unroll
            for (int mat = 0; mat < 4; ++mat) {
                ld[mat][0] = *reinterpret_cast<const uint4*>(gp[mat] + (st + 1) * 16);
                ld[mat][1] = *reinterpret_cast<const uint4*>(gp[mat] + (st + 1) * 16 + 4);
            }
        }

        const uint32_t aHiB = smemBase + (buf * 4 + 0) * TILEB + aOff;
        const uint32_t aLoB = smemBase + (buf * 4 + 1) * TILEB + aOff;
        const uint32_t bHiB = smemBase + (buf * 4 + 2) * TILEB + bOff;
        const uint32_t bLoB = smemBase + (buf * 4 + 3) * TILEB + bOff;

#pragma unroll
        for (int ks = 0; ks < 2; ++ks) {
            const uint32_t kadd = ks * 32;
            unsigned ahi[4][4], alo[4][4], bhi[4][2], blo[4][2];
#pragma unroll
            for (int mf = 0; mf < 4; ++mf) {
                ldm_x4(ahi[mf], aHiB + mf * (16 * ROWU * 4) + kadd);
                ldm_x4(alo[mf], aLoB + mf * (16 * ROWU * 4) + kadd);
            }
#pragma unroll
            for (int np = 0; np < 2; ++np) {
                unsigned t[4];
                ldm_x4(t, bHiB + np * (16 * ROWU * 4) + kadd);
                bhi[np * 2][0] = t[0]; bhi[np * 2][1] = t[1];
                bhi[np * 2 + 1][0] = t[2]; bhi[np * 2 + 1][1] = t[3];
                ldm_x4(t, bLoB + np * (16 * ROWU * 4) + kadd);
                blo[np * 2][0] = t[0]; blo[np * 2][1] = t[1];
                blo[np * 2 + 1][0] = t[2]; blo[np * 2 + 1][1] = t[3];
            }
#pragma unroll
            for (int mf = 0; mf < 4; ++mf)
#pragma unroll
                for (int nf = 0; nf < 4; ++nf) {
                    mma16(acc[mf][nf], ahi[mf], bhi[nf]);
                    mma16(acc[mf][nf], ahi[mf], blo[nf]);
                    mma16(acc[mf][nf], alo[mf], bhi[nf]);
                }
        }

        if (st + 1 < NSTAGE) {
            const int nb = buf ^ 1;
#pragma unroll
            for (int mat = 0; mat < 4; ++mat) {
                *reinterpret_cast<uint4*>(sm + (nb * 4 + mat) * TILEU + stoff)     = ld[mat][0];
                *reinterpret_cast<uint4*>(sm + (nb * 4 + mat) * TILEU + stoff + 4) = ld[mat][1];
            }
        }
        __syncthreads();
        buf ^= 1;
    }

#pragma unroll
    for (int mf = 0; mf < 4; ++mf) {
        const int r0 = m0 + wm * 64 + mf * 16 + (lane >> 2);
#pragma unroll
        for (int nf = 0; nf < 4; ++nf) {
            const int c = n0 + wn * 32 + nf * 8 + (lane & 3) * 2;
            float2 bv = *reinterpret_cast<const float2*>(bias + c);
            float o0x = acc[mf][nf][0] + bv.x;
            float o0y = acc[mf][nf][1] + bv.y;
            float o1x = acc[mf][nf][2] + bv.x;
            float o1y = acc[mf][nf][3] + bv.y;
            if (round_out) {
                o0x = __uint_as_float(f2tf(o0x));
                o0y = __uint_as_float(f2tf(o0y));
                o1x = __uint_as_float(f2tf(o1x));
                o1y = __uint_as_float(f2tf(o1y));
            }
            *reinterpret_cast<float2*>(C + (size_t)r0 * Dm + c)       = make_float2(o0x, o0y);
            *reinterpret_cast<float2*>(C + (size_t)(r0 + 8) * Dm + c) = make_float2(o1x, o1y);
        }
    }
}

__global__ __launch_bounds__(256)
void k_qkv3(const __nv_bfloat16* __restrict__ xhi, const __nv_bfloat16* __restrict__ xlo,
            const __nv_bfloat16* __restrict__ whi, const __nv_bfloat16* __restrict__ wlo,
            const float* __restrict__ bq, const float* __restrict__ bk,
            const float* __restrict__ bv,
            float* __restrict__ q, float* __restrict__ k, float* __restrict__ v)
{
    const size_t WSZ = (size_t)Dm * Dm;
    const float* bias;
    float* out;
    if (blockIdx.z == 0)      { bias = bq; out = q; }
    else if (blockIdx.z == 1) { bias = bk; out = k; }
    else                      { bias = bv; out = v; }
    gemm_core(xhi, xlo, whi + blockIdx.z * WSZ, wlo + blockIdx.z * WSZ, bias, out, 1);
}

__global__ __launch_bounds__(256)
void k_oproj(const __nv_bfloat16* __restrict__ chi, const __nv_bfloat16* __restrict__ clo,
             const __nv_bfloat16* __restrict__ whi, const __nv_bfloat16* __restrict__ wlo,
             const float* __restrict__ bo, float* __restrict__ out)
{
    gemm_core(chi, clo, whi, wlo, bo, out, 0);
}

// ---------------------------------------------------------------------------
// Flash attention: QK^T tf32 (ldmatrix B-frags), PV fp16 (packed layouts).
// 256 threads / 8 warps, 128 q rows per block, 64-key tiles, base-2 softmax.
// All ldmatrix row strides are multiples of 16 bytes:
//   Ks: 68 f32 = 272 B; Vp: 36 u32 = 144 B; Pp: 36 u32 = 144 B.
// ---------------------------------------------------------------------------
__global__ __launch_bounds__(256)
void k_attn(const int* __restrict__ mask,
            __nv_bfloat16* __restrict__ Chi, __nv_bfloat16* __restrict__ Clo)
{
    __shared__ __align__(16) float    Ks[64][68];    // [key][d] f32
    __shared__ __align__(16) unsigned Vp[64][36];    // [d][keypair] half2 (32 used + pad)
    __shared__ __align__(16) unsigned Pp[128][36];   // [qrow][keypair] half2 (32 used + pad)
    __shared__ int      msk[64];

    const int tid  = threadIdx.x;
    const int lane = tid & 31;
    const int wq   = tid >> 5;
    const int bh   = blockIdx.y;
    const int b    = bh >> 4;
    const int h    = bh & 15;
    const int q0   = blockIdx.x * 128;

    const uint32_t KsA = (uint32_t)__cvta_generic_to_shared(&Ks[0][0]);
    const uint32_t VpA = (uint32_t)__cvta_generic_to_shared(&Vp[0][0]);
    const uint32_t PpA = (uint32_t)__cvta_generic_to_shared(&Pp[0][0]);

    // per-lane ldmatrix offsets
    const int rowB = (lane & 7) + ((lane & 16) ? 8 : 0);
    const int colB = ((lane >> 3) & 1) * 4;
    const uint32_t offQK  = (uint32_t)(rowB * 68 + colB) * 4;   // into Ks
    const uint32_t offPVb = (uint32_t)(rowB * 36 + colB) * 4;   // into Vp
    const int rowA = wq * 16 + (lane & 7) + ((lane >> 3) & 1) * 8;
    const int colA = ((lane >> 4) & 1) * 4;
    const uint32_t offPVa = (uint32_t)(rowA * 36 + colA) * 4;   // into Pp

    // Q fragments: pre-rounded tf32 * (1/8 * log2e)  (base-2 logits)
    const float QSCALE = 0.125f * 1.44269504088896f;
    unsigned qf[8][4];
    {
        const float* qbase = g_Q + ((size_t)(b * Sn + q0 + wq * 16) * Dm + h * Dh);
#pragma unroll
        for (int k8 = 0; k8 < 8; ++k8)
#pragma unroll
            for (int j = 0; j < 4; ++j) {
                int row = (lane >> 2) + ((j & 1) << 3);
                int col = k8 * 8 + (lane & 3) + ((j >> 1) << 2);
                qf[k8][j] = __float_as_uint(qbase[(size_t)row * Dm + col] * QSCALE);
            }
    }

    float of[8][4];
#pragma unroll
    for (int nf = 0; nf < 8; ++nf)
#pragma unroll
        for (int j = 0; j < 4; ++j) of[nf][j] = 0.f;

    float m0r = -INFINITY, m1r = -INFINITY;
    float l0 = 0.f, l1 = 0.f;

    for (int kt = 0; kt < Sn / 64; ++kt) {
        __syncthreads();   // prev tile fully consumed

        // K tile: [key][d] f32
        {
            const int row = tid >> 2;
            const int seg = (tid & 3) * 16;
            const float* kp = g_K + ((size_t)(b * Sn + kt * 64 + row) * Dm + h * Dh + seg);
#pragma unroll
            for (int i = 0; i < 4; ++i)
                *reinterpret_cast<float4*>(&Ks[row][seg + i * 4]) =
                    *reinterpret_cast<const float4*>(kp + i * 4);
        }
        // V tile: [d][keypair] half2 (transposed + key-paired)
        {
            const int kpi  = tid >> 3;            // 0..31
            const int dseg = (tid & 7) * 8;
            const float* v0 = g_V + ((size_t)(b * Sn + kt * 64 + 2 * kpi) * Dm + h * Dh + dseg);
            const float* v1 = v0 + Dm;
            float4 a0 = *reinterpret_cast<const float4*>(v0);
            float4 a1 = *reinterpret_cast<const float4*>(v0 + 4);
            float4 b0 = *reinterpret_cast<const float4*>(v1);
            float4 b1 = *reinterpret_cast<const float4*>(v1 + 4);
            Vp[dseg + 0][kpi] = packh2(a0.x, b0.x);
            Vp[dseg + 1][kpi] = packh2(a0.y, b0.y);
            Vp[dseg + 2][kpi] = packh2(a0.z, b0.z);
            Vp[dseg + 3][kpi] = packh2(a0.w, b0.w);
            Vp[dseg + 4][kpi] = packh2(a1.x, b1.x);
            Vp[dseg + 5][kpi] = packh2(a1.y, b1.y);
            Vp[dseg + 6][kpi] = packh2(a1.z, b1.z);
            Vp[dseg + 7][kpi] = packh2(a1.w, b1.w);
        }
        if (tid < 64) msk[tid] = mask[b * Sn + kt * 64 + tid];
        __syncthreads();

        // S = Q . K^T via ldmatrix B-frags
        float sf[8][4];
#pragma unroll
        for (int nf = 0; nf < 8; ++nf)
#pragma unroll
            for (int j = 0; j < 4; ++j) sf[nf][j] = 0.f;

#pragma unroll
        for (int k8 = 0; k8 < 8; ++k8) {
#pragma unroll
            for (int np = 0; np < 4; ++np) {
                unsigned t[4];
                ldm_x4(t, KsA + (uint32_t)(np * 16 * 68 * 4 + k8 * 32) + offQK);
                mma8(sf[np * 2],     qf[k8], t);
                mma8(sf[np * 2 + 1], qf[k8], t + 2);
            }
        }

        // mask + online softmax (base 2)
        float tmax0 = -INFINITY, tmax1 = -INFINITY;
#pragma unroll
        for (int nf = 0; nf < 8; ++nf) {
            const int c = nf * 8 + (lane & 3) * 2;
            if (!msk[c])     { sf[nf][0] = -1e20f; sf[nf][2] = -1e20f; }
            if (!msk[c + 1]) { sf[nf][1] = -1e20f; sf[nf][3] = -1e20f; }
            tmax0 = fmaxf(tmax0, fmaxf(sf[nf][0], sf[nf][1]));
            tmax1 = fmaxf(tmax1, fmaxf(sf[nf][2], sf[nf][3]));
        }
        tmax0 = fmaxf(tmax0, __shfl_xor_sync(0xffffffff, tmax0, 1));
        tmax0 = fmaxf(tmax0, __shfl_xor_sync(0xffffffff, tmax0, 2));
        tmax1 = fmaxf(tmax1, __shfl_xor_sync(0xffffffff, tmax1, 1));
        tmax1 = fmaxf(tmax1, __shfl_xor_sync(0xffffffff, tmax1, 2));

        const float mn0 = fmaxf(m0r, tmax0);
        const float mn1 = fmaxf(m1r, tmax1);
        const float a0  = ex2(m0r - mn0);
        const float a1  = ex2(m1r - mn1);
        l0 *= a0; l1 *= a1;
        if (!__all_sync(0xffffffff, (a0 == 1.f) & (a1 == 1.f))) {
#pragma unroll
            for (int nf = 0; nf < 8; ++nf) {
                of[nf][0] *= a0; of[nf][1] *= a0;
                of[nf][2] *= a1; of[nf][3] *= a1;
            }
        }

        float s0 = 0.f, s1 = 0.f;
#pragma unroll
        for (int nf = 0; nf < 8; ++nf) {
            sf[nf][0] = ex2(sf[nf][0] - mn0);
            sf[nf][1] = ex2(sf[nf][1] - mn0);
            sf[nf][2] = ex2(sf[nf][2] - mn1);
            sf[nf][3] = ex2(sf[nf][3] - mn1);
            s0 += sf[nf][0] + sf[nf][1];
            s1 += sf[nf][2] + sf[nf][3];
        }
        s0 += __shfl_xor_sync(0xffffffff, s0, 1);
        s0 += __shfl_xor_sync(0xffffffff, s0, 2);
        s1 += __shfl_xor_sync(0xffffffff, s1, 1);
        s1 += __shfl_xor_sync(0xffffffff, s1, 2);
        l0 += s0; l1 += s1;
        m0r = mn0; m1r = mn1;

        // pack P -> half2 into warp-private Pp rows
        {
            const int r  = wq * 16 + (lane >> 2);
            const int kp = (lane & 3);
#pragma unroll
            for (int nf = 0; nf < 8; ++nf) {
                Pp[r][nf * 4 + kp]     = packh2(sf[nf][0], sf[nf][1]);
                Pp[r + 8][nf * 4 + kp] = packh2(sf[nf][2], sf[nf][3]);
            }
        }
        __syncwarp();

        // O += P . V  (fp16 m16n8k16, ldmatrix A and B frags)
#pragma unroll
        for (int c = 0; c < 4; ++c) {
            unsigned af[4];
            ldm_x4(af, PpA + (uint32_t)(c * 32) + offPVa);
#pragma unroll
            for (int np = 0; np < 4; ++np) {
                unsigned t[4];
                ldm_x4(t, VpA + (uint32_t)(np * 16 * 36 * 4 + c * 32) + offPVb);
                mma16h(of[np * 2],     af, t);
                mma16h(of[np * 2 + 1], af, t + 2);
            }
        }
    }

    // epilogue: normalize, split to bf16 hi/lo, write
    const float inv0 = 1.f / l0;
    const float inv1 = 1.f / l1;
    const size_t rbase = (size_t)(b * Sn + q0 + wq * 16);
#pragma unroll
    for (int nf = 0; nf < 8; ++nf) {
        const int c = h * Dh + nf * 8 + (lane & 3) * 2;
        const int r = lane >> 2;
        float v00 = of[nf][0] * inv0, v01 = of[nf][1] * inv0;
        float v10 = of[nf][2] * inv1, v11 = of[nf][3] * inv1;
        __nv_bfloat16 h00 = __float2bfloat16_rn(v00), h01 = __float2bfloat16_rn(v01);
        __nv_bfloat16 h10 = __float2bfloat16_rn(v10), h11 = __float2bfloat16_rn(v11);
        __nv_bfloat16 l00 = __float2bfloat16_rn(v00 - __bfloat162float(h00));
        __nv_bfloat16 l01 = __float2bfloat16_rn(v01 - __bfloat162float(h01));
        __nv_bfloat16 l10 = __float2bfloat16_rn(v10 - __bfloat162float(h10));
        __nv_bfloat16 l11 = __float2bfloat16_rn(v11 - __bfloat162float(h11));
        *reinterpret_cast<__nv_bfloat162*>(Chi + (rbase + r) * Dm + c)     = __nv_bfloat162(h00, h01);
        *reinterpret_cast<__nv_bfloat162*>(Chi + (rbase + r + 8) * Dm + c) = __nv_bfloat162(h10, h11);
        *reinterpret_cast<__nv_bfloat162*>(Clo + (rbase + r) * Dm + c)     = __nv_bfloat162(l00, l01);
        *reinterpret_cast<__nv_bfloat162*>(Clo + (rbase + r + 8) * Dm + c) = __nv_bfloat162(l10, l11);
    }
}

// ---------------------------------------------------------------------------
// Launch
// ---------------------------------------------------------------------------
extern "C" void kernel_launch(void* const* d_in, const int* in_sizes, int n_in,
                              void* d_out, int out_size)
{
    const float* query = (const float*)d_in[0];
    const int*   mask  = (const int*)  d_in[1];
    const float* Wq    = (const float*)d_in[2];
    const float* bq    = (const float*)d_in[3];
    const float* Wk    = (const float*)d_in[4];
    const float* bk    = (const float*)d_in[5];
    const float* Wv    = (const float*)d_in[6];
    const float* bv    = (const float*)d_in[7];
    const float* Wo    = (const float*)d_in[8];
    const float* bo    = (const float*)d_in[9];
    float* out = (float*)d_out;

    static int init_done = 0;
    if (!init_done) {
        cudaFuncSetAttribute(k_qkv3, cudaFuncAttributeMaxDynamicSharedMemorySize, GEMM_SMEM);
        cudaFuncSetAttribute(k_oproj, cudaFuncAttributeMaxDynamicSharedMemorySize, GEMM_SMEM);
        init_done = 1;
    }

    __nv_bfloat16 *xhi, *xlo, *chi, *clo, *whi, *wlo;
    float *q32, *k32, *v32;
    cudaGetSymbolAddress((void**)&xhi, g_Xhi);
    cudaGetSymbolAddress((void**)&xlo, g_Xlo);
    cudaGetSymbolAddress((void**)&chi, g_Chi);
    cudaGetSymbolAddress((void**)&clo, g_Clo);
    cudaGetSymbolAddress((void**)&whi, g_Whi);
    cudaGetSymbolAddress((void**)&wlo, g_Wlo);
    cudaGetSymbolAddress((void**)&q32, g_Q);
    cudaGetSymbolAddress((void**)&k32, g_K);
    cudaGetSymbolAddress((void**)&v32, g_V);

    const size_t WSZ = (size_t)Dm * Dm;
    const int nX4 = MTOT * Dm / 4;
    const int nW4 = Dm * Dm / 4;

    k_cvt<<<(nX4 + 255) / 256, 256>>>(query, xhi, xlo, nX4);
    k_cvt<<<(nW4 + 255) / 256, 256>>>(Wq, whi + 0 * WSZ, wlo + 0 * WSZ, nW4);
    k_cvt<<<(nW4 + 255) / 256, 256>>>(Wk, whi + 1 * WSZ, wlo + 1 * WSZ, nW4);
    k_cvt<<<(nW4 + 255) / 256, 256>>>(Wv, whi + 2 * WSZ, wlo + 2 * WSZ, nW4);
    k_cvt<<<(nW4 + 255) / 256, 256>>>(Wo, whi + 3 * WSZ, wlo + 3 * WSZ, nW4);

    dim3 gq(Dm / 128, MTOT / 128, 3);
    k_qkv3<<<gq, 256, GEMM_SMEM>>>(xhi, xlo, whi, wlo, bq, bk, bv, q32, k32, v32);

    dim3 ga(Sn / 128, Bn * Hn);
    k_attn<<<ga, 256>>>(mask, chi, clo);

    dim3 go(Dm / 128, MTOT / 128);
    k_oproj<<<go, 256, GEMM_SMEM>>>(chi, clo, whi + 3 * WSZ, wlo + 3 * WSZ, bo, out);
}

// round 8
// speedup vs baseline: 4.1720x; 1.0534x over previous
#include <cuda_runtime.h>
#include <cuda_bf16.h>
#include <cuda_fp16.h>
#include <math.h>
#include <stdint.h>

constexpr int Bn  = 4;
constexpr int Sn  = 2048;
constexpr int Dm  = 1024;
constexpr int Hn  = 16;
constexpr int Dh  = 64;
constexpr int MTOT = Bn * Sn;   // 8192

// f32 scratch (Q/K/V post-projection; Q,K tf32-rounded)
__device__ float g_Q[(size_t)MTOT * Dm];
__device__ float g_K[(size_t)MTOT * Dm];
__device__ float g_V[(size_t)MTOT * Dm];

// bf16 hi/lo scratch (Q,K projections)
__device__ __nv_bfloat16 g_Xhi[(size_t)MTOT * Dm];
__device__ __nv_bfloat16 g_Xlo[(size_t)MTOT * Dm];
__device__ __nv_bfloat16 g_Whi[2][(size_t)Dm * Dm];
__device__ __nv_bfloat16 g_Wlo[2][(size_t)Dm * Dm];

// fp16 hi/lo scratch (V, O projections)
__device__ __half g_X16hi[(size_t)MTOT * Dm];
__device__ __half g_X16lo[(size_t)MTOT * Dm];
__device__ __half g_C16hi[(size_t)MTOT * Dm];
__device__ __half g_C16lo[(size_t)MTOT * Dm];
__device__ __half g_Wv16[(size_t)Dm * Dm];
__device__ __half g_Wo16[(size_t)Dm * Dm];

// ---------------------------------------------------------------------------
// helpers
// ---------------------------------------------------------------------------
__device__ __forceinline__ unsigned f2tf(float x) {
    unsigned r;
    asm("cvt.rna.tf32.f32 %0, %1;" : "=r"(r) : "f"(x));
    return r;
}

__device__ __forceinline__ float ex2(float x) {
    float y;
    asm("ex2.approx.ftz.f32 %0, %1;" : "=f"(y) : "f"(x));
    return y;
}

__device__ __forceinline__ void mma8(float* d, const unsigned* a, const unsigned* b) {
    asm volatile(
        "mma.sync.aligned.m16n8k8.row.col.f32.tf32.tf32.f32 "
        "{%0,%1,%2,%3},{%4,%5,%6,%7},{%8,%9},{%0,%1,%2,%3};"
        : "+f"(d[0]), "+f"(d[1]), "+f"(d[2]), "+f"(d[3])
        : "r"(a[0]), "r"(a[1]), "r"(a[2]), "r"(a[3]), "r"(b[0]), "r"(b[1]));
}

__device__ __forceinline__ void mma16(float* d, const unsigned* a, const unsigned* b) {
    asm volatile(
        "mma.sync.aligned.m16n8k16.row.col.f32.bf16.bf16.f32 "
        "{%0,%1,%2,%3},{%4,%5,%6,%7},{%8,%9},{%0,%1,%2,%3};"
        : "+f"(d[0]), "+f"(d[1]), "+f"(d[2]), "+f"(d[3])
        : "r"(a[0]), "r"(a[1]), "r"(a[2]), "r"(a[3]), "r"(b[0]), "r"(b[1]));
}

__device__ __forceinline__ void mma16h(float* d, const unsigned* a, const unsigned* b) {
    asm volatile(
        "mma.sync.aligned.m16n8k16.row.col.f32.f16.f16.f32 "
        "{%0,%1,%2,%3},{%4,%5,%6,%7},{%8,%9},{%0,%1,%2,%3};"
        : "+f"(d[0]), "+f"(d[1]), "+f"(d[2]), "+f"(d[3])
        : "r"(a[0]), "r"(a[1]), "r"(a[2]), "r"(a[3]), "r"(b[0]), "r"(b[1]));
}

__device__ __forceinline__ void ldm_x4(unsigned* r, uint32_t addr) {
    asm volatile(
        "ldmatrix.sync.aligned.m8n8.x4.shared.b16 {%0,%1,%2,%3}, [%4];"
        : "=r"(r[0]), "=r"(r[1]), "=r"(r[2]), "=r"(r[3]) : "r"(addr));
}

__device__ __forceinline__ unsigned packh2(float a, float b) {
    __half2 h = __floats2half2_rn(a, b);    // low = a
    return *reinterpret_cast<unsigned*>(&h);
}

__device__ __forceinline__ void cpasync16(uint32_t dst, const void* src) {
    asm volatile("cp.async.cg.shared.global [%0], [%1], 16;" :: "r"(dst), "l"(src));
}

// ---------------------------------------------------------------------------
// conversions
// ---------------------------------------------------------------------------
__global__ __launch_bounds__(256)
void k_cvt(const float* __restrict__ src, __nv_bfloat16* __restrict__ hi,
           __nv_bfloat16* __restrict__ lo, int n4)
{
    int i = blockIdx.x * blockDim.x + threadIdx.x;
    if (i >= n4) return;
    float4 v = reinterpret_cast<const float4*>(src)[i];
    __nv_bfloat16 h0 = __float2bfloat16_rn(v.x);
    __nv_bfloat16 h1 = __float2bfloat16_rn(v.y);
    __nv_bfloat16 h2 = __float2bfloat16_rn(v.z);
    __nv_bfloat16 h3 = __float2bfloat16_rn(v.w);
    __nv_bfloat16 l0 = __float2bfloat16_rn(v.x - __bfloat162float(h0));
    __nv_bfloat16 l1 = __float2bfloat16_rn(v.y - __bfloat162float(h1));
    __nv_bfloat16 l2 = __float2bfloat16_rn(v.z - __bfloat162float(h2));
    __nv_bfloat16 l3 = __float2bfloat16_rn(v.w - __bfloat162float(h3));
    reinterpret_cast<__nv_bfloat162*>(hi)[i * 2 + 0] = __nv_bfloat162(h0, h1);
    reinterpret_cast<__nv_bfloat162*>(hi)[i * 2 + 1] = __nv_bfloat162(h2, h3);
    reinterpret_cast<__nv_bfloat162*>(lo)[i * 2 + 0] = __nv_bfloat162(l0, l1);
    reinterpret_cast<__nv_bfloat162*>(lo)[i * 2 + 1] = __nv_bfloat162(l2, l3);
}

__global__ __launch_bounds__(256)
void k_cvt16(const float* __restrict__ src, __half* __restrict__ hi,
             __half* __restrict__ lo, int n4)
{
    int i = blockIdx.x * blockDim.x + threadIdx.x;
    if (i >= n4) return;
    float4 v = reinterpret_cast<const float4*>(src)[i];
    __half h0 = __float2half_rn(v.x);
    __half h1 = __float2half_rn(v.y);
    __half h2 = __float2half_rn(v.z);
    __half h3 = __float2half_rn(v.w);
    __half l0 = __float2half_rn(v.x - __half2float(h0));
    __half l1 = __float2half_rn(v.y - __half2float(h1));
    __half l2 = __float2half_rn(v.z - __half2float(h2));
    __half l3 = __float2half_rn(v.w - __half2float(h3));
    reinterpret_cast<__half2*>(hi)[i * 2 + 0] = __halves2half2(h0, h1);
    reinterpret_cast<__half2*>(hi)[i * 2 + 1] = __halves2half2(h2, h3);
    reinterpret_cast<__half2*>(lo)[i * 2 + 0] = __halves2half2(l0, l1);
    reinterpret_cast<__half2*>(lo)[i * 2 + 1] = __halves2half2(l2, l3);
}

__global__ __launch_bounds__(256)
void k_cvt16h(const float* __restrict__ src, __half* __restrict__ hi, int n4)
{
    int i = blockIdx.x * blockDim.x + threadIdx.x;
    if (i >= n4) return;
    float4 v = reinterpret_cast<const float4*>(src)[i];
    reinterpret_cast<__half2*>(hi)[i * 2 + 0] =
        __halves2half2(__float2half_rn(v.x), __float2half_rn(v.y));
    reinterpret_cast<__half2*>(hi)[i * 2 + 1] =
        __halves2half2(__float2half_rn(v.z), __float2half_rn(v.w));
}

// ---------------------------------------------------------------------------
// Split-bf16 3-pass GEMM core with ldmatrix (validated round 5/7). Q,K proj.
// ---------------------------------------------------------------------------
constexpr int ROWU  = 20;
constexpr int TILEU = 128 * ROWU;
constexpr int TILEB = TILEU * 4;
constexpr int GEMM_SMEM  = 2 * 4 * TILEB;   // 81920 bytes
constexpr int GEMM2_SMEM = 2 * 3 * TILEB;   // 61440 bytes

__device__ __forceinline__ void gemm_core(
    const __nv_bfloat16* __restrict__ Ahi,
    const __nv_bfloat16* __restrict__ Alo,
    const __nv_bfloat16* __restrict__ Bhi,
    const __nv_bfloat16* __restrict__ Blo,
    const float* __restrict__ bias,
    float* __restrict__ C, int round_out)
{
    extern __shared__ unsigned sm[];

    const int tid  = threadIdx.x;
    const int lane = tid & 31;
    const int warp = tid >> 5;
    const int wm   = warp >> 2;
    const int wn   = warp & 3;
    const int m0   = blockIdx.y * 128;
    const int n0   = blockIdx.x * 128;

    const int r  = tid >> 1;
    const int c0 = (tid & 1) * 8;

    const unsigned* gp[4];
    gp[0] = reinterpret_cast<const unsigned*>(Ahi) + (size_t)(m0 + r) * (Dm / 2) + c0;
    gp[1] = reinterpret_cast<const unsigned*>(Alo) + (size_t)(m0 + r) * (Dm / 2) + c0;
    gp[2] = reinterpret_cast<const unsigned*>(Bhi) + (size_t)(n0 + r) * (Dm / 2) + c0;
    gp[3] = reinterpret_cast<const unsigned*>(Blo) + (size_t)(n0 + r) * (Dm / 2) + c0;
    const int stoff = r * ROWU + c0;

    const uint32_t smemBase = (uint32_t)__cvta_generic_to_shared(sm);
    const uint32_t aOff = ((lane & 15) * ROWU + ((lane >> 4) & 1) * 4) * 4
                          + wm * 64 * ROWU * 4;
    const uint32_t bOff = (((lane & 7) + ((lane >> 1) & 8)) * ROWU
                           + ((lane >> 3) & 1) * 4) * 4
                          + wn * 32 * ROWU * 4;

    float acc[4][4][4];
#pragma unroll
    for (int mf = 0; mf < 4; ++mf)
#pragma unroll
        for (int nf = 0; nf < 4; ++nf)
#pragma unroll
            for (int j = 0; j < 4; ++j) acc[mf][nf][j] = 0.f;

    uint4 ld[4][2];

#pragma unroll
    for (int mat = 0; mat < 4; ++mat) {
        ld[mat][0] = *reinterpret_cast<const uint4*>(gp[mat]);
        ld[mat][1] = *reinterpret_cast<const uint4*>(gp[mat] + 4);
    }
#pragma unroll
    for (int mat = 0; mat < 4; ++mat) {
        *reinterpret_cast<uint4*>(sm + mat * TILEU + stoff)     = ld[mat][0];
        *reinterpret_cast<uint4*>(sm + mat * TILEU + stoff + 4) = ld[mat][1];
    }
    __syncthreads();

    int buf = 0;
    const int NSTAGE = Dm / 32;

    for (int st = 0; st < NSTAGE; ++st) {
        if (st + 1 < NSTAGE) {
#pragma unroll
            for (int mat = 0; mat < 4; ++mat) {
                ld[mat][0] = *reinterpret_cast<const uint4*>(gp[mat] + (st + 1) * 16);
                ld[mat][1] = *reinterpret_cast<const uint4*>(gp[mat] + (st + 1) * 16 + 4);
            }
        }

        const uint32_t aHiB = smemBase + (buf * 4 + 0) * TILEB + aOff;
        const uint32_t aLoB = smemBase + (buf * 4 + 1) * TILEB + aOff;
        const uint32_t bHiB = smemBase + (buf * 4 + 2) * TILEB + bOff;
        const uint32_t bLoB = smemBase + (buf * 4 + 3) * TILEB + bOff;

#pragma unroll
        for (int ks = 0; ks < 2; ++ks) {
            const uint32_t kadd = ks * 32;
            unsigned ahi[4][4], alo[4][4], bhi[4][2], blo[4][2];
#pragma unroll
            for (int mf = 0; mf < 4; ++mf) {
                ldm_x4(ahi[mf], aHiB + mf * (16 * ROWU * 4) + kadd);
                ldm_x4(alo[mf], aLoB + mf * (16 * ROWU * 4) + kadd);
            }
#pragma unroll
            for (int np = 0; np < 2; ++np) {
                unsigned t[4];
                ldm_x4(t, bHiB + np * (16 * ROWU * 4) + kadd);
                bhi[np * 2][0] = t[0]; bhi[np * 2][1] = t[1];
                bhi[np * 2 + 1][0] = t[2]; bhi[np * 2 + 1][1] = t[3];
                ldm_x4(t, bLoB + np * (16 * ROWU * 4) + kadd);
                blo[np * 2][0] = t[0]; blo[np * 2][1] = t[1];
                blo[np * 2 + 1][0] = t[2]; blo[np * 2 + 1][1] = t[3];
            }
#pragma unroll
            for (int mf = 0; mf < 4; ++mf)
#pragma unroll
                for (int nf = 0; nf < 4; ++nf) {
                    mma16(acc[mf][nf], ahi[mf], bhi[nf]);
                    mma16(acc[mf][nf], ahi[mf], blo[nf]);
                    mma16(acc[mf][nf], alo[mf], bhi[nf]);
                }
        }

        if (st + 1 < NSTAGE) {
            const int nb = buf ^ 1;
#pragma unroll
            for (int mat = 0; mat < 4; ++mat) {
                *reinterpret_cast<uint4*>(sm + (nb * 4 + mat) * TILEU + stoff)     = ld[mat][0];
                *reinterpret_cast<uint4*>(sm + (nb * 4 + mat) * TILEU + stoff + 4) = ld[mat][1];
            }
        }
        __syncthreads();
        buf ^= 1;
    }

#pragma unroll
    for (int mf = 0; mf < 4; ++mf) {
        const int r0 = m0 + wm * 64 + mf * 16 + (lane >> 2);
#pragma unroll
        for (int nf = 0; nf < 4; ++nf) {
            const int c = n0 + wn * 32 + nf * 8 + (lane & 3) * 2;
            float2 bv = *reinterpret_cast<const float2*>(bias + c);
            float o0x = acc[mf][nf][0] + bv.x;
            float o0y = acc[mf][nf][1] + bv.y;
            float o1x = acc[mf][nf][2] + bv.x;
            float o1y = acc[mf][nf][3] + bv.y;
            if (round_out) {
                o0x = __uint_as_float(f2tf(o0x));
                o0y = __uint_as_float(f2tf(o0y));
                o1x = __uint_as_float(f2tf(o1x));
                o1y = __uint_as_float(f2tf(o1y));
            }
            *reinterpret_cast<float2*>(C + (size_t)r0 * Dm + c)       = make_float2(o0x, o0y);
            *reinterpret_cast<float2*>(C + (size_t)(r0 + 8) * Dm + c) = make_float2(o1x, o1y);
        }
    }
}

// ---------------------------------------------------------------------------
// fp16 2-pass GEMM core: C = (Ahi + Alo) . Bhi^T + bias  (A = activations)
// ---------------------------------------------------------------------------
__device__ __forceinline__ void gemm2_core(
    const __half* __restrict__ Ahi,
    const __half* __restrict__ Alo,
    const __half* __restrict__ Bh,
    const float* __restrict__ bias,
    float* __restrict__ C)
{
    extern __shared__ unsigned sm[];

    const int tid  = threadIdx.x;
    const int lane = tid & 31;
    const int warp = tid >> 5;
    const int wm   = warp >> 2;
    const int wn   = warp & 3;
    const int m0   = blockIdx.y * 128;
    const int n0   = blockIdx.x * 128;

    const int r  = tid >> 1;
    const int c0 = (tid & 1) * 8;

    const unsigned* gp[3];
    gp[0] = reinterpret_cast<const unsigned*>(Ahi) + (size_t)(m0 + r) * (Dm / 2) + c0;
    gp[1] = reinterpret_cast<const unsigned*>(Alo) + (size_t)(m0 + r) * (Dm / 2) + c0;
    gp[2] = reinterpret_cast<const unsigned*>(Bh)  + (size_t)(n0 + r) * (Dm / 2) + c0;
    const int stoff = r * ROWU + c0;

    const uint32_t smemBase = (uint32_t)__cvta_generic_to_shared(sm);
    const uint32_t aOff = ((lane & 15) * ROWU + ((lane >> 4) & 1) * 4) * 4
                          + wm * 64 * ROWU * 4;
    const uint32_t bOff = (((lane & 7) + ((lane >> 1) & 8)) * ROWU
                           + ((lane >> 3) & 1) * 4) * 4
                          + wn * 32 * ROWU * 4;

    float acc[4][4][4];
#pragma unroll
    for (int mf = 0; mf < 4; ++mf)
#pragma unroll
        for (int nf = 0; nf < 4; ++nf)
#pragma unroll
            for (int j = 0; j < 4; ++j) acc[mf][nf][j] = 0.f;

    uint4 ld[3][2];

#pragma unroll
    for (int mat = 0; mat < 3; ++mat) {
        ld[mat][0] = *reinterpret_cast<const uint4*>(gp[mat]);
        ld[mat][1] = *reinterpret_cast<const uint4*>(gp[mat] + 4);
    }
#pragma unroll
    for (int mat = 0; mat < 3; ++mat) {
        *reinterpret_cast<uint4*>(sm + mat * TILEU + stoff)     = ld[mat][0];
        *reinterpret_cast<uint4*>(sm + mat * TILEU + stoff + 4) = ld[mat][1];
    }
    __syncthreads();

    int buf = 0;
    const int NSTAGE = Dm / 32;

    for (int st = 0; st < NSTAGE; ++st) {
        if (st + 1 < NSTAGE) {
#pragma unroll
            for (int mat = 0; mat < 3; ++mat) {
                ld[mat][0] = *reinterpret_cast<const uint4*>(gp[mat] + (st + 1) * 16);
                ld[mat][1] = *reinterpret_cast<const uint4*>(gp[mat] + (st + 1) * 16 + 4);
            }
        }

        const uint32_t aHiB = smemBase + (buf * 3 + 0) * TILEB + aOff;
        const uint32_t aLoB = smemBase + (buf * 3 + 1) * TILEB + aOff;
        const uint32_t bB   = smemBase + (buf * 3 + 2) * TILEB + bOff;

#pragma unroll
        for (int ks = 0; ks < 2; ++ks) {
            const uint32_t kadd = ks * 32;
            unsigned ahi[4][4], alo[4][4], bf[4][2];
#pragma unroll
            for (int mf = 0; mf < 4; ++mf) {
                ldm_x4(ahi[mf], aHiB + mf * (16 * ROWU * 4) + kadd);
                ldm_x4(alo[mf], aLoB + mf * (16 * ROWU * 4) + kadd);
            }
#pragma unroll
            for (int np = 0; np < 2; ++np) {
                unsigned t[4];
                ldm_x4(t, bB + np * (16 * ROWU * 4) + kadd);
                bf[np * 2][0] = t[0]; bf[np * 2][1] = t[1];
                bf[np * 2 + 1][0] = t[2]; bf[np * 2 + 1][1] = t[3];
            }
#pragma unroll
            for (int mf = 0; mf < 4; ++mf)
#pragma unroll
                for (int nf = 0; nf < 4; ++nf) {
                    mma16h(acc[mf][nf], ahi[mf], bf[nf]);
                    mma16h(acc[mf][nf], alo[mf], bf[nf]);
                }
        }

        if (st + 1 < NSTAGE) {
            const int nb = buf ^ 1;
#pragma unroll
            for (int mat = 0; mat < 3; ++mat) {
                *reinterpret_cast<uint4*>(sm + (nb * 3 + mat) * TILEU + stoff)     = ld[mat][0];
                *reinterpret_cast<uint4*>(sm + (nb * 3 + mat) * TILEU + stoff + 4) = ld[mat][1];
            }
        }
        __syncthreads();
        buf ^= 1;
    }

#pragma unroll
    for (int mf = 0; mf < 4; ++mf) {
        const int r0 = m0 + wm * 64 + mf * 16 + (lane >> 2);
#pragma unroll
        for (int nf = 0; nf < 4; ++nf) {
            const int c = n0 + wn * 32 + nf * 8 + (lane & 3) * 2;
            float2 bv = *reinterpret_cast<const float2*>(bias + c);
            *reinterpret_cast<float2*>(C + (size_t)r0 * Dm + c) =
                make_float2(acc[mf][nf][0] + bv.x, acc[mf][nf][1] + bv.y);
            *reinterpret_cast<float2*>(C + (size_t)(r0 + 8) * Dm + c) =
                make_float2(acc[mf][nf][2] + bv.x, acc[mf][nf][3] + bv.y);
        }
    }
}

__global__ __launch_bounds__(256)
void k_qkv2(const __nv_bfloat16* __restrict__ xhi, const __nv_bfloat16* __restrict__ xlo,
            const __nv_bfloat16* __restrict__ whi, const __nv_bfloat16* __restrict__ wlo,
            const float* __restrict__ bq, const float* __restrict__ bk,
            float* __restrict__ q, float* __restrict__ k)
{
    const size_t WSZ = (size_t)Dm * Dm;
    const int z = blockIdx.z;
    gemm_core(xhi, xlo, whi + z * WSZ, wlo + z * WSZ, z ? bk : bq, z ? k : q, 1);
}

__global__ __launch_bounds__(256)
void k_vproj(const __half* __restrict__ xhi, const __half* __restrict__ xlo,
             const __half* __restrict__ wv, const float* __restrict__ bv,
             float* __restrict__ v)
{
    gemm2_core(xhi, xlo, wv, bv, v);
}

__global__ __launch_bounds__(256)
void k_oproj16(const __half* __restrict__ chi, const __half* __restrict__ clo,
               const __half* __restrict__ wo, const float* __restrict__ bo,
               float* __restrict__ out)
{
    gemm2_core(chi, clo, wo, bo, out);
}

// ---------------------------------------------------------------------------
// Flash attention: QK^T tf32 (ldmatrix), PV fp16, cp.async 2-stage prefetch.
// 256 threads / 8 warps, 128 q rows, 64-key tiles, base-2 softmax.
// Dynamic smem layout (bytes):
//   Kst [2][64][68] f32 @ 0       (34816)
//   Vst [2][64][68] f32 @ 34816   (34816)
//   Vp  [64][36] u32    @ 69632   ( 9216)
//   Pp  [128][36] u32   @ 78848   (18432)
//   msk [2][64] int     @ 97280   (  512)
// ---------------------------------------------------------------------------
constexpr int ATTN_SMEM = 97792;

__global__ __launch_bounds__(256)
void k_attn(const int* __restrict__ mask,
            __half* __restrict__ Chi, __half* __restrict__ Clo)
{
    extern __shared__ __align__(16) unsigned char smraw[];
    float*    Vst = (float*)(smraw + 34816);
    unsigned* Pp  = (unsigned*)(smraw + 78848);
    int*      msk = (int*)(smraw + 97280);
    unsigned* Vp  = (unsigned*)(smraw + 69632);

    const int tid  = threadIdx.x;
    const int lane = tid & 31;
    const int wq   = tid >> 5;
    const int bh   = blockIdx.y;
    const int b    = bh >> 4;
    const int h    = bh & 15;
    const int q0   = blockIdx.x * 128;

    const uint32_t KstA = (uint32_t)__cvta_generic_to_shared(smraw);
    const uint32_t VstA = KstA + 34816;
    const uint32_t VpA  = KstA + 69632;
    const uint32_t PpA  = KstA + 78848;
    const uint32_t mskA = KstA + 97280;

    // cp.async addressing
    const int prow = tid >> 2;
    const int pseg = (tid & 3) * 16;
    const uint32_t kDst = (uint32_t)(prow * 68 + pseg) * 4;

    // ldmatrix per-lane offsets
    const int rowB = (lane & 7) + ((lane & 16) ? 8 : 0);
    const int colB = ((lane >> 3) & 1) * 4;
    const uint32_t offQK  = (uint32_t)(rowB * 68 + colB) * 4;
    const uint32_t offPVb = (uint32_t)(rowB * 36 + colB) * 4;
    const int rowA = wq * 16 + (lane & 7) + ((lane >> 3) & 1) * 8;
    const int colA = ((lane >> 4) & 1) * 4;
    const uint32_t offPVa = (uint32_t)(rowA * 36 + colA) * 4;

    // Q fragments: pre-rounded tf32 * (1/8 * log2e)
    const float QSCALE = 0.125f * 1.44269504088896f;
    unsigned qf[8][4];
    {
        const float* qbase = g_Q + ((size_t)(b * Sn + q0 + wq * 16) * Dm + h * Dh);
#pragma unroll
        for (int k8 = 0; k8 < 8; ++k8)
#pragma unroll
            for (int j = 0; j < 4; ++j) {
                int row = (lane >> 2) + ((j & 1) << 3);
                int col = k8 * 8 + (lane & 3) + ((j >> 1) << 2);
                qf[k8][j] = __float_as_uint(qbase[(size_t)row * Dm + col] * QSCALE);
            }
    }

    float of[8][4];
#pragma unroll
    for (int nf = 0; nf < 8; ++nf)
#pragma unroll
        for (int j = 0; j < 4; ++j) of[nf][j] = 0.f;

    float m0r = -INFINITY, m1r = -INFINITY;
    float l0 = 0.f, l1 = 0.f;

    const int NT = Sn / 64;

    // prefetch tile 0 into buffer 0
    {
        const size_t gbase = (size_t)(b * Sn + prow) * Dm + h * Dh + pseg;
        const float* kp = g_K + gbase;
        const float* vp = g_V + gbase;
#pragma unroll
        for (int i = 0; i < 4; ++i) {
            cpasync16(KstA + kDst + i * 16, kp + i * 4);
            cpasync16(VstA + kDst + i * 16, vp + i * 4);
        }
        if (tid < 16) cpasync16(mskA + tid * 16, mask + (size_t)b * Sn + tid * 4);
        asm volatile("cp.async.commit_group;");
    }

    for (int kt = 0; kt < NT; ++kt) {
        const int p = kt & 1;
        __syncthreads();   // prior consumers of buffers p^1 / Vp done

        if (kt + 1 < NT) {
            const size_t gbase = (size_t)(b * Sn + (kt + 1) * 64 + prow) * Dm + h * Dh + pseg;
            const float* kp = g_K + gbase;
            const float* vp = g_V + gbase;
            const uint32_t bofs = (uint32_t)((p ^ 1) * 17408);
#pragma unroll
            for (int i = 0; i < 4; ++i) {
                cpasync16(KstA + bofs + kDst + i * 16, kp + i * 4);
                cpasync16(VstA + bofs + kDst + i * 16, vp + i * 4);
            }
            if (tid < 16)
                cpasync16(mskA + (p ^ 1) * 256 + tid * 16,
                          mask + (size_t)b * Sn + (kt + 1) * 64 + tid * 4);
            asm volatile("cp.async.commit_group;");
            asm volatile("cp.async.wait_group 1;");
        } else {
            asm volatile("cp.async.wait_group 0;");
        }
        __syncthreads();   // tile kt visible to all

        // pack V from Vst[p] into Vp ([d][keypair] half2)
        {
            const int kpi  = tid >> 3;
            const int dseg = (tid & 7) * 8;
            const float* v0 = Vst + p * 4352 + (2 * kpi) * 68 + dseg;
            const float* v1 = v0 + 68;
            float4 a0 = *reinterpret_cast<const float4*>(v0);
            float4 a1 = *reinterpret_cast<const float4*>(v0 + 4);
            float4 b0 = *reinterpret_cast<const float4*>(v1);
            float4 b1 = *reinterpret_cast<const float4*>(v1 + 4);
            Vp[(dseg + 0) * 36 + kpi] = packh2(a0.x, b0.x);
            Vp[(dseg + 1) * 36 + kpi] = packh2(a0.y, b0.y);
            Vp[(dseg + 2) * 36 + kpi] = packh2(a0.z, b0.z);
            Vp[(dseg + 3) * 36 + kpi] = packh2(a0.w, b0.w);
            Vp[(dseg + 4) * 36 + kpi] = packh2(a1.x, b1.x);
            Vp[(dseg + 5) * 36 + kpi] = packh2(a1.y, b1.y);
            Vp[(dseg + 6) * 36 + kpi] = packh2(a1.z, b1.z);
            Vp[(dseg + 7) * 36 + kpi] = packh2(a1.w, b1.w);
        }

        // S = Q . K^T from Kst[p]
        float sf[8][4];
#pragma unroll
        for (int nf = 0; nf < 8; ++nf)
#pragma unroll
            for (int j = 0; j < 4; ++j) sf[nf][j] = 0.f;

        const uint32_t kBase = KstA + (uint32_t)(p * 17408) + offQK;
#pragma unroll
        for (int k8 = 0; k8 < 8; ++k8) {
#pragma unroll
            for (int np = 0; np < 4; ++np) {
                unsigned t[4];
                ldm_x4(t, kBase + (uint32_t)(np * 16 * 68 * 4 + k8 * 32));
                mma8(sf[np * 2],     qf[k8], t);
                mma8(sf[np * 2 + 1], qf[k8], t + 2);
            }
        }

        // mask + online softmax (base 2)
        const int* mk = msk + p * 64;
        float tmax0 = -INFINITY, tmax1 = -INFINITY;
#pragma unroll
        for (int nf = 0; nf < 8; ++nf) {
            const int c = nf * 8 + (lane & 3) * 2;
            if (!mk[c])     { sf[nf][0] = -1e20f; sf[nf][2] = -1e20f; }
            if (!mk[c + 1]) { sf[nf][1] = -1e20f; sf[nf][3] = -1e20f; }
            tmax0 = fmaxf(tmax0, fmaxf(sf[nf][0], sf[nf][1]));
            tmax1 = fmaxf(tmax1, fmaxf(sf[nf][2], sf[nf][3]));
        }
        tmax0 = fmaxf(tmax0, __shfl_xor_sync(0xffffffff, tmax0, 1));
        tmax0 = fmaxf(tmax0, __shfl_xor_sync(0xffffffff, tmax0, 2));
        tmax1 = fmaxf(tmax1, __shfl_xor_sync(0xffffffff, tmax1, 1));
        tmax1 = fmaxf(tmax1, __shfl_xor_sync(0xffffffff, tmax1, 2));

        const float mn0 = fmaxf(m0r, tmax0);
        const float mn1 = fmaxf(m1r, tmax1);
        const float a0  = ex2(m0r - mn0);
        const float a1  = ex2(m1r - mn1);
        l0 *= a0; l1 *= a1;
        if (!__all_sync(0xffffffff, (a0 == 1.f) & (a1 == 1.f))) {
#pragma unroll
            for (int nf = 0; nf < 8; ++nf) {
                of[nf][0] *= a0; of[nf][1] *= a0;
                of[nf][2] *= a1; of[nf][3] *= a1;
            }
        }

        float s0 = 0.f, s1 = 0.f;
#pragma unroll
        for (int nf = 0; nf < 8; ++nf) {
            sf[nf][0] = ex2(sf[nf][0] - mn0);
            sf[nf][1] = ex2(sf[nf][1] - mn0);
            sf[nf][2] = ex2(sf[nf][2] - mn1);
            sf[nf][3] = ex2(sf[nf][3] - mn1);
            s0 += sf[nf][0] + sf[nf][1];
            s1 += sf[nf][2] + sf[nf][3];
        }
        s0 += __shfl_xor_sync(0xffffffff, s0, 1);
        s0 += __shfl_xor_sync(0xffffffff, s0, 2);
        s1 += __shfl_xor_sync(0xffffffff, s1, 1);
        s1 += __shfl_xor_sync(0xffffffff, s1, 2);
        l0 += s0; l1 += s1;
        m0r = mn0; m1r = mn1;

        // pack P -> half2 (warp-private rows)
        {
            const int r  = wq * 16 + (lane >> 2);
            const int kp = (lane & 3);
#pragma unroll
            for (int nf = 0; nf < 8; ++nf) {
                Pp[r * 36 + nf * 4 + kp]       = packh2(sf[nf][0], sf[nf][1]);
                Pp[(r + 8) * 36 + nf * 4 + kp] = packh2(sf[nf][2], sf[nf][3]);
            }
        }
        __syncthreads();   // Vp pack complete before PV reads

        // O += P . V
#pragma unroll
        for (int c = 0; c < 4; ++c) {
            unsigned af[4];
            ldm_x4(af, PpA + (uint32_t)(c * 32) + offPVa);
#pragma unroll
            for (int np = 0; np < 4; ++np) {
                unsigned t[4];
                ldm_x4(t, VpA + (uint32_t)(np * 16 * 36 * 4 + c * 32) + offPVb);
                mma16h(of[np * 2],     af, t);
                mma16h(of[np * 2 + 1], af, t + 2);
            }
        }
    }

    // epilogue: normalize, split to fp16 hi/lo, write
    const float inv0 = 1.f / l0;
    const float inv1 = 1.f / l1;
    const size_t rbase = (size_t)(b * Sn + q0 + wq * 16);
#pragma unroll
    for (int nf = 0; nf < 8; ++nf) {
        const int c = h * Dh + nf * 8 + (lane & 3) * 2;
        const int r = lane >> 2;
        float v00 = of[nf][0] * inv0, v01 = of[nf][1] * inv0;
        float v10 = of[nf][2] * inv1, v11 = of[nf][3] * inv1;
        __half h00 = __float2half_rn(v00), h01 = __float2half_rn(v01);
        __half h10 = __float2half_rn(v10), h11 = __float2half_rn(v11);
        __half l00 = __float2half_rn(v00 - __half2float(h00));
        __half l01 = __float2half_rn(v01 - __half2float(h01));
        __half l10 = __float2half_rn(v10 - __half2float(h10));
        __half l11 = __float2half_rn(v11 - __half2float(h11));
        *reinterpret_cast<__half2*>(Chi + (rbase + r) * Dm + c)     = __halves2half2(h00, h01);
        *reinterpret_cast<__half2*>(Chi + (rbase + r + 8) * Dm + c) = __halves2half2(h10, h11);
        *reinterpret_cast<__half2*>(Clo + (rbase + r) * Dm + c)     = __halves2half2(l00, l01);
        *reinterpret_cast<__half2*>(Clo + (rbase + r + 8) * Dm + c) = __halves2half2(l10, l11);
    }
}

// ---------------------------------------------------------------------------
// Launch
// ---------------------------------------------------------------------------
extern "C" void kernel_launch(void* const* d_in, const int* in_sizes, int n_in,
                              void* d_out, int out_size)
{
    const float* query = (const float*)d_in[0];
    const int*   mask  = (const int*)  d_in[1];
    const float* Wq    = (const float*)d_in[2];
    const float* bq    = (const float*)d_in[3];
    const float* Wk    = (const float*)d_in[4];
    const float* bk    = (const float*)d_in[5];
    const float* Wv    = (const float*)d_in[6];
    const float* bv    = (const float*)d_in[7];
    const float* Wo    = (const float*)d_in[8];
    const float* bo    = (const float*)d_in[9];
    float* out = (float*)d_out;

    static int init_done = 0;
    if (!init_done) {
        cudaFuncSetAttribute(k_qkv2,   cudaFuncAttributeMaxDynamicSharedMemorySize, GEMM_SMEM);
        cudaFuncSetAttribute(k_vproj,  cudaFuncAttributeMaxDynamicSharedMemorySize, GEMM2_SMEM);
        cudaFuncSetAttribute(k_oproj16,cudaFuncAttributeMaxDynamicSharedMemorySize, GEMM2_SMEM);
        cudaFuncSetAttribute(k_attn,   cudaFuncAttributeMaxDynamicSharedMemorySize, ATTN_SMEM);
        init_done = 1;
    }

    __nv_bfloat16 *xhi, *xlo, *whi, *wlo;
    __half *x16hi, *x16lo, *c16hi, *c16lo, *wv16, *wo16;
    float *q32, *k32, *v32;
    cudaGetSymbolAddress((void**)&xhi, g_Xhi);
    cudaGetSymbolAddress((void**)&xlo, g_Xlo);
    cudaGetSymbolAddress((void**)&whi, g_Whi);
    cudaGetSymbolAddress((void**)&wlo, g_Wlo);
    cudaGetSymbolAddress((void**)&x16hi, g_X16hi);
    cudaGetSymbolAddress((void**)&x16lo, g_X16lo);
    cudaGetSymbolAddress((void**)&c16hi, g_C16hi);
    cudaGetSymbolAddress((void**)&c16lo, g_C16lo);
    cudaGetSymbolAddress((void**)&wv16, g_Wv16);
    cudaGetSymbolAddress((void**)&wo16, g_Wo16);
    cudaGetSymbolAddress((void**)&q32, g_Q);
    cudaGetSymbolAddress((void**)&k32, g_K);
    cudaGetSymbolAddress((void**)&v32, g_V);

    const size_t WSZ = (size_t)Dm * Dm;
    const int nX4 = MTOT * Dm / 4;
    const int nW4 = Dm * Dm / 4;

    // conversions
    k_cvt<<<(nX4 + 255) / 256, 256>>>(query, xhi, xlo, nX4);
    k_cvt<<<(nW4 + 255) / 256, 256>>>(Wq, whi + 0 * WSZ, wlo + 0 * WSZ, nW4);
    k_cvt<<<(nW4 + 255) / 256, 256>>>(Wk, whi + 1 * WSZ, wlo + 1 * WSZ, nW4);
    k_cvt16<<<(nX4 + 255) / 256, 256>>>(query, x16hi, x16lo, nX4);
    k_cvt16h<<<(nW4 + 255) / 256, 256>>>(Wv, wv16, nW4);
    k_cvt16h<<<(nW4 + 255) / 256, 256>>>(Wo, wo16, nW4);

    // Q,K projections (bf16 3-pass, tf32-rounded out)
    dim3 gq(Dm / 128, MTOT / 128, 2);
    k_qkv2<<<gq, 256, GEMM_SMEM>>>(xhi, xlo, whi, wlo, bq, bk, q32, k32);

    // V projection (fp16 2-pass)
    dim3 gv(Dm / 128, MTOT / 128);
    k_vproj<<<gv, 256, GEMM2_SMEM>>>(x16hi, x16lo, wv16, bv, v32);

    // attention (writes fp16 hi/lo ctx)
    dim3 ga(Sn / 128, Bn * Hn);
    k_attn<<<ga, 256, ATTN_SMEM>>>(mask, c16hi, c16lo);

    // output projection (fp16 2-pass)
    k_oproj16<<<gv, 256, GEMM2_SMEM>>>(c16hi, c16lo, wo16, bo, out);
}

// round 9
// speedup vs baseline: 4.6252x; 1.1086x over previous
#include <cuda_runtime.h>
#include <cuda_fp16.h>
#include <math.h>
#include <stdint.h>

constexpr int Bn  = 4;
constexpr int Sn  = 2048;
constexpr int Dm  = 1024;
constexpr int Hn  = 16;
constexpr int Dh  = 64;
constexpr int MTOT = Bn * Sn;   // 8192

// f32 scratch (Q/K post-projection, tf32-rounded)
__device__ float g_Q[(size_t)MTOT * Dm];
__device__ float g_K[(size_t)MTOT * Dm];
// fp16 scratch
__device__ __half g_V16[(size_t)MTOT * Dm];
__device__ __half g_X16hi[(size_t)MTOT * Dm];
__device__ __half g_X16lo[(size_t)MTOT * Dm];
__device__ __half g_C16hi[(size_t)MTOT * Dm];
__device__ __half g_C16lo[(size_t)MTOT * Dm];
__device__ __half g_W16[4][(size_t)Dm * Dm];

// ---------------------------------------------------------------------------
// helpers
// ---------------------------------------------------------------------------
__device__ __forceinline__ unsigned f2tf(float x) {
    unsigned r;
    asm("cvt.rna.tf32.f32 %0, %1;" : "=r"(r) : "f"(x));
    return r;
}

__device__ __forceinline__ float ex2(float x) {
    float y;
    asm("ex2.approx.ftz.f32 %0, %1;" : "=f"(y) : "f"(x));
    return y;
}

__device__ __forceinline__ void mma8(float* d, const unsigned* a, const unsigned* b) {
    asm volatile(
        "mma.sync.aligned.m16n8k8.row.col.f32.tf32.tf32.f32 "
        "{%0,%1,%2,%3},{%4,%5,%6,%7},{%8,%9},{%0,%1,%2,%3};"
        : "+f"(d[0]), "+f"(d[1]), "+f"(d[2]), "+f"(d[3])
        : "r"(a[0]), "r"(a[1]), "r"(a[2]), "r"(a[3]), "r"(b[0]), "r"(b[1]));
}

__device__ __forceinline__ void mma16h(float* d, const unsigned* a, const unsigned* b) {
    asm volatile(
        "mma.sync.aligned.m16n8k16.row.col.f32.f16.f16.f32 "
        "{%0,%1,%2,%3},{%4,%5,%6,%7},{%8,%9},{%0,%1,%2,%3};"
        : "+f"(d[0]), "+f"(d[1]), "+f"(d[2]), "+f"(d[3])
        : "r"(a[0]), "r"(a[1]), "r"(a[2]), "r"(a[3]), "r"(b[0]), "r"(b[1]));
}

__device__ __forceinline__ void ldm_x4(unsigned* r, uint32_t addr) {
    asm volatile(
        "ldmatrix.sync.aligned.m8n8.x4.shared.b16 {%0,%1,%2,%3}, [%4];"
        : "=r"(r[0]), "=r"(r[1]), "=r"(r[2]), "=r"(r[3]) : "r"(addr));
}

__device__ __forceinline__ unsigned packh2(float a, float b) {
    __half2 h = __floats2half2_rn(a, b);    // low = a
    return *reinterpret_cast<unsigned*>(&h);
}

__device__ __forceinline__ void cpasync16(uint32_t dst, const void* src) {
    asm volatile("cp.async.cg.shared.global [%0], [%1], 16;" :: "r"(dst), "l"(src));
}

// ---------------------------------------------------------------------------
// conversions
// ---------------------------------------------------------------------------
__global__ __launch_bounds__(256)
void k_cvt16(const float* __restrict__ src, __half* __restrict__ hi,
             __half* __restrict__ lo, int n4)
{
    int i = blockIdx.x * blockDim.x + threadIdx.x;
    if (i >= n4) return;
    float4 v = reinterpret_cast<const float4*>(src)[i];
    __half h0 = __float2half_rn(v.x);
    __half h1 = __float2half_rn(v.y);
    __half h2 = __float2half_rn(v.z);
    __half h3 = __float2half_rn(v.w);
    __half l0 = __float2half_rn(v.x - __half2float(h0));
    __half l1 = __float2half_rn(v.y - __half2float(h1));
    __half l2 = __float2half_rn(v.z - __half2float(h2));
    __half l3 = __float2half_rn(v.w - __half2float(h3));
    reinterpret_cast<__half2*>(hi)[i * 2 + 0] = __halves2half2(h0, h1);
    reinterpret_cast<__half2*>(hi)[i * 2 + 1] = __halves2half2(h2, h3);
    reinterpret_cast<__half2*>(lo)[i * 2 + 0] = __halves2half2(l0, l1);
    reinterpret_cast<__half2*>(lo)[i * 2 + 1] = __halves2half2(l2, l3);
}

__global__ __launch_bounds__(256)
void k_cvt16h(const float* __restrict__ src, __half* __restrict__ hi, int n4)
{
    int i = blockIdx.x * blockDim.x + threadIdx.x;
    if (i >= n4) return;
    float4 v = reinterpret_cast<const float4*>(src)[i];
    reinterpret_cast<__half2*>(hi)[i * 2 + 0] =
        __halves2half2(__float2half_rn(v.x), __float2half_rn(v.y));
    reinterpret_cast<__half2*>(hi)[i * 2 + 1] =
        __halves2half2(__float2half_rn(v.z), __float2half_rn(v.w));
}

// ---------------------------------------------------------------------------
// fp16 2-pass GEMM core: C = (Ahi + Alo) . Bh^T + bias
// mode: 0 = f32 out, 1 = f32 tf32-rounded out, 2 = fp16 out
// Block tile 128x128, K-stage 32 (2 x k16), double-buffered smem, ldmatrix.
// ---------------------------------------------------------------------------
constexpr int ROWU  = 20;
constexpr int TILEU = 128 * ROWU;
constexpr int TILEB = TILEU * 4;
constexpr int GEMM2_SMEM = 2 * 3 * TILEB;   // 61440 bytes

__device__ __forceinline__ void gemm2_core(
    const __half* __restrict__ Ahi,
    const __half* __restrict__ Alo,
    const __half* __restrict__ Bh,
    const float* __restrict__ bias,
    float* __restrict__ Cf, __half* __restrict__ Ch, int mode)
{
    extern __shared__ unsigned sm[];

    const int tid  = threadIdx.x;
    const int lane = tid & 31;
    const int warp = tid >> 5;
    const int wm   = warp >> 2;
    const int wn   = warp & 3;
    const int m0   = blockIdx.y * 128;
    const int n0   = blockIdx.x * 128;

    const int r  = tid >> 1;
    const int c0 = (tid & 1) * 8;

    const unsigned* gp[3];
    gp[0] = reinterpret_cast<const unsigned*>(Ahi) + (size_t)(m0 + r) * (Dm / 2) + c0;
    gp[1] = reinterpret_cast<const unsigned*>(Alo) + (size_t)(m0 + r) * (Dm / 2) + c0;
    gp[2] = reinterpret_cast<const unsigned*>(Bh)  + (size_t)(n0 + r) * (Dm / 2) + c0;
    const int stoff = r * ROWU + c0;

    const uint32_t smemBase = (uint32_t)__cvta_generic_to_shared(sm);
    const uint32_t aOff = ((lane & 15) * ROWU + ((lane >> 4) & 1) * 4) * 4
                          + wm * 64 * ROWU * 4;
    const uint32_t bOff = (((lane & 7) + ((lane >> 1) & 8)) * ROWU
                           + ((lane >> 3) & 1) * 4) * 4
                          + wn * 32 * ROWU * 4;

    float acc[4][4][4];
#pragma unroll
    for (int mf = 0; mf < 4; ++mf)
#pragma unroll
        for (int nf = 0; nf < 4; ++nf)
#pragma unroll
            for (int j = 0; j < 4; ++j) acc[mf][nf][j] = 0.f;

    uint4 ld[3][2];

#pragma unroll
    for (int mat = 0; mat < 3; ++mat) {
        ld[mat][0] = *reinterpret_cast<const uint4*>(gp[mat]);
        ld[mat][1] = *reinterpret_cast<const uint4*>(gp[mat] + 4);
    }
#pragma unroll
    for (int mat = 0; mat < 3; ++mat) {
        *reinterpret_cast<uint4*>(sm + mat * TILEU + stoff)     = ld[mat][0];
        *reinterpret_cast<uint4*>(sm + mat * TILEU + stoff + 4) = ld[mat][1];
    }
    __syncthreads();

    int buf = 0;
    const int NSTAGE = Dm / 32;

    for (int st = 0; st < NSTAGE; ++st) {
        if (st + 1 < NSTAGE) {
#pragma unroll
            for (int mat = 0; mat < 3; ++mat) {
                ld[mat][0] = *reinterpret_cast<const uint4*>(gp[mat] + (st + 1) * 16);
                ld[mat][1] = *reinterpret_cast<const uint4*>(gp[mat] + (st + 1) * 16 + 4);
            }
        }

        const uint32_t aHiB = smemBase + (buf * 3 + 0) * TILEB + aOff;
        const uint32_t aLoB = smemBase + (buf * 3 + 1) * TILEB + aOff;
        const uint32_t bB   = smemBase + (buf * 3 + 2) * TILEB + bOff;

#pragma unroll
        for (int ks = 0; ks < 2; ++ks) {
            const uint32_t kadd = ks * 32;
            unsigned ahi[4][4], alo[4][4], bf[4][2];
#pragma unroll
            for (int mf = 0; mf < 4; ++mf) {
                ldm_x4(ahi[mf], aHiB + mf * (16 * ROWU * 4) + kadd);
                ldm_x4(alo[mf], aLoB + mf * (16 * ROWU * 4) + kadd);
            }
#pragma unroll
            for (int np = 0; np < 2; ++np) {
                unsigned t[4];
                ldm_x4(t, bB + np * (16 * ROWU * 4) + kadd);
                bf[np * 2][0] = t[0]; bf[np * 2][1] = t[1];
                bf[np * 2 + 1][0] = t[2]; bf[np * 2 + 1][1] = t[3];
            }
#pragma unroll
            for (int mf = 0; mf < 4; ++mf)
#pragma unroll
                for (int nf = 0; nf < 4; ++nf) {
                    mma16h(acc[mf][nf], ahi[mf], bf[nf]);
                    mma16h(acc[mf][nf], alo[mf], bf[nf]);
                }
        }

        if (st + 1 < NSTAGE) {
            const int nb = buf ^ 1;
#pragma unroll
            for (int mat = 0; mat < 3; ++mat) {
                *reinterpret_cast<uint4*>(sm + (nb * 3 + mat) * TILEU + stoff)     = ld[mat][0];
                *reinterpret_cast<uint4*>(sm + (nb * 3 + mat) * TILEU + stoff + 4) = ld[mat][1];
            }
        }
        __syncthreads();
        buf ^= 1;
    }

#pragma unroll
    for (int mf = 0; mf < 4; ++mf) {
        const int r0 = m0 + wm * 64 + mf * 16 + (lane >> 2);
#pragma unroll
        for (int nf = 0; nf < 4; ++nf) {
            const int c = n0 + wn * 32 + nf * 8 + (lane & 3) * 2;
            float2 bv = *reinterpret_cast<const float2*>(bias + c);
            float o0x = acc[mf][nf][0] + bv.x;
            float o0y = acc[mf][nf][1] + bv.y;
            float o1x = acc[mf][nf][2] + bv.x;
            float o1y = acc[mf][nf][3] + bv.y;
            if (mode == 2) {
                *reinterpret_cast<__half2*>(Ch + (size_t)r0 * Dm + c) =
                    __halves2half2(__float2half_rn(o0x), __float2half_rn(o0y));
                *reinterpret_cast<__half2*>(Ch + (size_t)(r0 + 8) * Dm + c) =
                    __halves2half2(__float2half_rn(o1x), __float2half_rn(o1y));
            } else {
                if (mode == 1) {
                    o0x = __uint_as_float(f2tf(o0x));
                    o0y = __uint_as_float(f2tf(o0y));
                    o1x = __uint_as_float(f2tf(o1x));
                    o1y = __uint_as_float(f2tf(o1y));
                }
                *reinterpret_cast<float2*>(Cf + (size_t)r0 * Dm + c)       = make_float2(o0x, o0y);
                *reinterpret_cast<float2*>(Cf + (size_t)(r0 + 8) * Dm + c) = make_float2(o1x, o1y);
            }
        }
    }
}

// QKV fused: z=0 Q (tf32-rounded f32), z=1 K (same), z=2 V (fp16)
__global__ __launch_bounds__(256)
void k_proj3(const __half* __restrict__ xhi, const __half* __restrict__ xlo,
             const __half* __restrict__ w16,
             const float* __restrict__ bq, const float* __restrict__ bk,
             const float* __restrict__ bv,
             float* __restrict__ q, float* __restrict__ k, __half* __restrict__ v)
{
    const size_t WSZ = (size_t)Dm * Dm;
    const int z = blockIdx.z;
    if (z == 0)      gemm2_core(xhi, xlo, w16,           bq, q, nullptr, 1);
    else if (z == 1) gemm2_core(xhi, xlo, w16 + WSZ,     bk, k, nullptr, 1);
    else             gemm2_core(xhi, xlo, w16 + 2 * WSZ, bv, nullptr, v, 2);
}

__global__ __launch_bounds__(256)
void k_oproj16(const __half* __restrict__ chi, const __half* __restrict__ clo,
               const __half* __restrict__ wo, const float* __restrict__ bo,
               float* __restrict__ out)
{
    gemm2_core(chi, clo, wo, bo, out, nullptr, 0);
}

// ---------------------------------------------------------------------------
// Flash attention: QK^T tf32 (K cp.async double-buffered), PV fp16
// (V prefetched fp16->regs, packed with byte_perm). 256 thr / 8 warps,
// 128 q rows, 64-key tiles, base-2 softmax.
// Smem layout (bytes):
//   Kst [2][64][68] f32 @ 0      (34816)
//   Vp  [64][36] u32    @ 34816  ( 9216)
//   Pp  [128][36] u32   @ 44032  (18432)
//   msk [2][64] int     @ 62464  (  512)
// ---------------------------------------------------------------------------
constexpr int ATTN_SMEM = 62976;

__global__ __launch_bounds__(256)
void k_attn(const int* __restrict__ mask,
            __half* __restrict__ Chi, __half* __restrict__ Clo)
{
    extern __shared__ __align__(16) unsigned char smraw[];
    unsigned* Vp  = (unsigned*)(smraw + 34816);
    unsigned* Pp  = (unsigned*)(smraw + 44032);
    int*      msk = (int*)(smraw + 62464);

    const int tid  = threadIdx.x;
    const int lane = tid & 31;
    const int wq   = tid >> 5;
    const int bh   = blockIdx.y;
    const int b    = bh >> 4;
    const int h    = bh & 15;
    const int q0   = blockIdx.x * 128;

    const uint32_t KstA = (uint32_t)__cvta_generic_to_shared(smraw);
    const uint32_t VpA  = KstA + 34816;
    const uint32_t PpA  = KstA + 44032;
    const uint32_t mskA = KstA + 62464;

    // cp.async addressing (K tile)
    const int prow = tid >> 2;
    const int pseg = (tid & 3) * 16;
    const uint32_t kDst = (uint32_t)(prow * 68 + pseg) * 4;

    // V prefetch addressing
    const int kpi  = tid >> 3;            // 0..31 (key pair)
    const int dseg = (tid & 7) * 8;       // 0..56

    // ldmatrix per-lane offsets
    const int rowB = (lane & 7) + ((lane & 16) ? 8 : 0);
    const int colB = ((lane >> 3) & 1) * 4;
    const uint32_t offQK  = (uint32_t)(rowB * 68 + colB) * 4;
    const uint32_t offPVb = (uint32_t)(rowB * 36 + colB) * 4;
    const int rowA = wq * 16 + (lane & 7) + ((lane >> 3) & 1) * 8;
    const int colA = ((lane >> 4) & 1) * 4;
    const uint32_t offPVa = (uint32_t)(rowA * 36 + colA) * 4;

    // Q fragments: pre-rounded tf32 * (1/8 * log2e)
    const float QSCALE = 0.125f * 1.44269504088896f;
    unsigned qf[8][4];
    {
        const float* qbase = g_Q + ((size_t)(b * Sn + q0 + wq * 16) * Dm + h * Dh);
#pragma unroll
        for (int k8 = 0; k8 < 8; ++k8)
#pragma unroll
            for (int j = 0; j < 4; ++j) {
                int row = (lane >> 2) + ((j & 1) << 3);
                int col = k8 * 8 + (lane & 3) + ((j >> 1) << 2);
                qf[k8][j] = __float_as_uint(qbase[(size_t)row * Dm + col] * QSCALE);
            }
    }

    float of[8][4];
#pragma unroll
    for (int nf = 0; nf < 8; ++nf)
#pragma unroll
        for (int j = 0; j < 4; ++j) of[nf][j] = 0.f;

    float m0r = -INFINITY, m1r = -INFINITY;
    float l0 = 0.f, l1 = 0.f;

    const int NT = Sn / 64;

    // prefetch K tile 0 + mask 0
    {
        const float* kp = g_K + (size_t)(b * Sn + prow) * Dm + h * Dh + pseg;
#pragma unroll
        for (int i = 0; i < 4; ++i)
            cpasync16(KstA + kDst + i * 16, kp + i * 4);
        if (tid < 16) cpasync16(mskA + tid * 16, mask + (size_t)b * Sn + tid * 4);
        asm volatile("cp.async.commit_group;");
    }

    for (int kt = 0; kt < NT; ++kt) {
        const int p = kt & 1;
        __syncthreads();   // prior PV consumers of Vp/Pp done; Kst[p^1] free

        // V prefetch for tile kt (fp16, registers; consumed after QK)
        uint4 va, vb;
        {
            const __half* vsrc = g_V16 +
                (size_t)(b * Sn + kt * 64 + 2 * kpi) * Dm + h * Dh + dseg;
            va = *reinterpret_cast<const uint4*>(vsrc);
            vb = *reinterpret_cast<const uint4*>(vsrc + Dm);
        }

        if (kt + 1 < NT) {
            const float* kp = g_K +
                (size_t)(b * Sn + (kt + 1) * 64 + prow) * Dm + h * Dh + pseg;
            const uint32_t bofs = (uint32_t)((p ^ 1) * 17408);
#pragma unroll
            for (int i = 0; i < 4; ++i)
                cpasync16(KstA + bofs + kDst + i * 16, kp + i * 4);
            if (tid < 16)
                cpasync16(mskA + (p ^ 1) * 256 + tid * 16,
                          mask + (size_t)b * Sn + (kt + 1) * 64 + tid * 4);
            asm volatile("cp.async.commit_group;");
            asm volatile("cp.async.wait_group 1;");
        } else {
            asm volatile("cp.async.wait_group 0;");
        }
        __syncthreads();   // K tile kt visible

        // S = Q . K^T from Kst[p]
        float sf[8][4];
#pragma unroll
        for (int nf = 0; nf < 8; ++nf)
#pragma unroll
            for (int j = 0; j < 4; ++j) sf[nf][j] = 0.f;

        const uint32_t kBase = KstA + (uint32_t)(p * 17408) + offQK;
#pragma unroll
        for (int k8 = 0; k8 < 8; ++k8) {
#pragma unroll
            for (int np = 0; np < 4; ++np) {
                unsigned t[4];
                ldm_x4(t, kBase + (uint32_t)(np * 16 * 68 * 4 + k8 * 32));
                mma8(sf[np * 2],     qf[k8], t);
                mma8(sf[np * 2 + 1], qf[k8], t + 2);
            }
        }

        // pack V regs -> Vp ([d][keypair] half2) via byte_perm
        {
            unsigned* vrow = Vp + dseg * 36 + kpi;
            vrow[0 * 36] = __byte_perm(va.x, vb.x, 0x5410);
            vrow[1 * 36] = __byte_perm(va.x, vb.x, 0x7632);
            vrow[2 * 36] = __byte_perm(va.y, vb.y, 0x5410);
            vrow[3 * 36] = __byte_perm(va.y, vb.y, 0x7632);
            vrow[4 * 36] = __byte_perm(va.z, vb.z, 0x5410);
            vrow[5 * 36] = __byte_perm(va.z, vb.z, 0x7632);
            vrow[6 * 36] = __byte_perm(va.w, vb.w, 0x5410);
            vrow[7 * 36] = __byte_perm(va.w, vb.w, 0x7632);
        }

        // mask + online softmax (base 2)
        const int* mk = msk + p * 64;
        float tmax0 = -INFINITY, tmax1 = -INFINITY;
#pragma unroll
        for (int nf = 0; nf < 8; ++nf) {
            const int c = nf * 8 + (lane & 3) * 2;
            if (!mk[c])     { sf[nf][0] = -1e20f; sf[nf][2] = -1e20f; }
            if (!mk[c + 1]) { sf[nf][1] = -1e20f; sf[nf][3] = -1e20f; }
            tmax0 = fmaxf(tmax0, fmaxf(sf[nf][0], sf[nf][1]));
            tmax1 = fmaxf(tmax1, fmaxf(sf[nf][2], sf[nf][3]));
        }
        tmax0 = fmaxf(tmax0, __shfl_xor_sync(0xffffffff, tmax0, 1));
        tmax0 = fmaxf(tmax0, __shfl_xor_sync(0xffffffff, tmax0, 2));
        tmax1 = fmaxf(tmax1, __shfl_xor_sync(0xffffffff, tmax1, 1));
        tmax1 = fmaxf(tmax1, __shfl_xor_sync(0xffffffff, tmax1, 2));

        const float mn0 = fmaxf(m0r, tmax0);
        const float mn1 = fmaxf(m1r, tmax1);
        const float a0  = ex2(m0r - mn0);
        const float a1  = ex2(m1r - mn1);
        l0 *= a0; l1 *= a1;
        if (!__all_sync(0xffffffff, (a0 == 1.f) & (a1 == 1.f))) {
#pragma unroll
            for (int nf = 0; nf < 8; ++nf) {
                of[nf][0] *= a0; of[nf][1] *= a0;
                of[nf][2] *= a1; of[nf][3] *= a1;
            }
        }

        float s0 = 0.f, s1 = 0.f;
#pragma unroll
        for (int nf = 0; nf < 8; ++nf) {
            sf[nf][0] = ex2(sf[nf][0] - mn0);
            sf[nf][1] = ex2(sf[nf][1] - mn0);
            sf[nf][2] = ex2(sf[nf][2] - mn1);
            sf[nf][3] = ex2(sf[nf][3] - mn1);
            s0 += sf[nf][0] + sf[nf][1];
            s1 += sf[nf][2] + sf[nf][3];
        }
        s0 += __shfl_xor_sync(0xffffffff, s0, 1);
        s0 += __shfl_xor_sync(0xffffffff, s0, 2);
        s1 += __shfl_xor_sync(0xffffffff, s1, 1);
        s1 += __shfl_xor_sync(0xffffffff, s1, 2);
        l0 += s0; l1 += s1;
        m0r = mn0; m1r = mn1;

        // pack P -> half2 (warp-private rows)
        {
            const int r  = wq * 16 + (lane >> 2);
            const int kp = (lane & 3);
#pragma unroll
            for (int nf = 0; nf < 8; ++nf) {
                Pp[r * 36 + nf * 4 + kp]       = packh2(sf[nf][0], sf[nf][1]);
                Pp[(r + 8) * 36 + nf * 4 + kp] = packh2(sf[nf][2], sf[nf][3]);
            }
        }
        __syncthreads();   // Vp pack + Pp writes complete before PV reads

        // O += P . V
#pragma unroll
        for (int c = 0; c < 4; ++c) {
            unsigned af[4];
            ldm_x4(af, PpA + (uint32_t)(c * 32) + offPVa);
#pragma unroll
            for (int np = 0; np < 4; ++np) {
                unsigned t[4];
                ldm_x4(t, VpA + (uint32_t)(np * 16 * 36 * 4 + c * 32) + offPVb);
                mma16h(of[np * 2],     af, t);
                mma16h(of[np * 2 + 1], af, t + 2);
            }
        }
    }

    // epilogue: normalize, split to fp16 hi/lo, write
    const float inv0 = 1.f / l0;
    const float inv1 = 1.f / l1;
    const size_t rbase = (size_t)(b * Sn + q0 + wq * 16);
#pragma unroll
    for (int nf = 0; nf < 8; ++nf) {
        const int c = h * Dh + nf * 8 + (lane & 3) * 2;
        const int r = lane >> 2;
        float v00 = of[nf][0] * inv0, v01 = of[nf][1] * inv0;
        float v10 = of[nf][2] * inv1, v11 = of[nf][3] * inv1;
        __half h00 = __float2half_rn(v00), h01 = __float2half_rn(v01);
        __half h10 = __float2half_rn(v10), h11 = __float2half_rn(v11);
        __half l00 = __float2half_rn(v00 - __half2float(h00));
        __half l01 = __float2half_rn(v01 - __half2float(h01));
        __half l10 = __float2half_rn(v10 - __half2float(h10));
        __half l11 = __float2half_rn(v11 - __half2float(h11));
        *reinterpret_cast<__half2*>(Chi + (rbase + r) * Dm + c)     = __halves2half2(h00, h01);
        *reinterpret_cast<__half2*>(Chi + (rbase + r + 8) * Dm + c) = __halves2half2(h10, h11);
        *reinterpret_cast<__half2*>(Clo + (rbase + r) * Dm + c)     = __halves2half2(l00, l01);
        *reinterpret_cast<__half2*>(Clo + (rbase + r + 8) * Dm + c) = __halves2half2(l10, l11);
    }
}

// ---------------------------------------------------------------------------
// Launch
// ---------------------------------------------------------------------------
extern "C" void kernel_launch(void* const* d_in, const int* in_sizes, int n_in,
                              void* d_out, int out_size)
{
    const float* query = (const float*)d_in[0];
    const int*   mask  = (const int*)  d_in[1];
    const float* Wq    = (const float*)d_in[2];
    const float* bq    = (const float*)d_in[3];
    const float* Wk    = (const float*)d_in[4];
    const float* bk    = (const float*)d_in[5];
    const float* Wv    = (const float*)d_in[6];
    const float* bv    = (const float*)d_in[7];
    const float* Wo    = (const float*)d_in[8];
    const float* bo    = (const float*)d_in[9];
    float* out = (float*)d_out;

    static int init_done = 0;
    if (!init_done) {
        cudaFuncSetAttribute(k_proj3,  cudaFuncAttributeMaxDynamicSharedMemorySize, GEMM2_SMEM);
        cudaFuncSetAttribute(k_oproj16,cudaFuncAttributeMaxDynamicSharedMemorySize, GEMM2_SMEM);
        cudaFuncSetAttribute(k_attn,   cudaFuncAttributeMaxDynamicSharedMemorySize, ATTN_SMEM);
        init_done = 1;
    }

    __half *x16hi, *x16lo, *c16hi, *c16lo, *w16, *v16;
    float *q32, *k32;
    cudaGetSymbolAddress((void**)&x16hi, g_X16hi);
    cudaGetSymbolAddress((void**)&x16lo, g_X16lo);
    cudaGetSymbolAddress((void**)&c16hi, g_C16hi);
    cudaGetSymbolAddress((void**)&c16lo, g_C16lo);
    cudaGetSymbolAddress((void**)&w16, g_W16);
    cudaGetSymbolAddress((void**)&v16, g_V16);
    cudaGetSymbolAddress((void**)&q32, g_Q);
    cudaGetSymbolAddress((void**)&k32, g_K);

    const size_t WSZ = (size_t)Dm * Dm;
    const int nX4 = MTOT * Dm / 4;
    const int nW4 = Dm * Dm / 4;

    // conversions
    k_cvt16<<<(nX4 + 255) / 256, 256>>>(query, x16hi, x16lo, nX4);
    k_cvt16h<<<(nW4 + 255) / 256, 256>>>(Wq, w16 + 0 * WSZ, nW4);
    k_cvt16h<<<(nW4 + 255) / 256, 256>>>(Wk, w16 + 1 * WSZ, nW4);
    k_cvt16h<<<(nW4 + 255) / 256, 256>>>(Wv, w16 + 2 * WSZ, nW4);
    k_cvt16h<<<(nW4 + 255) / 256, 256>>>(Wo, w16 + 3 * WSZ, nW4);

    // QKV projections (fp16 2-pass)
    dim3 gq(Dm / 128, MTOT / 128, 3);
    k_proj3<<<gq, 256, GEMM2_SMEM>>>(x16hi, x16lo, w16, bq, bk, bv, q32, k32, v16);

    // attention
    dim3 ga(Sn / 128, Bn * Hn);
    k_attn<<<ga, 256, ATTN_SMEM>>>(mask, c16hi, c16lo);

    // output projection (fp16 2-pass)
    dim3 go(Dm / 128, MTOT / 128);
    k_oproj16<<<go, 256, GEMM2_SMEM>>>(c16hi, c16lo, w16 + 3 * WSZ, bo, out);
}

// round 10
// speedup vs baseline: 5.8889x; 1.2732x over previous
#include <cuda_runtime.h>
#include <cuda_fp16.h>
#include <math.h>
#include <stdint.h>

constexpr int Bn  = 4;
constexpr int Sn  = 2048;
constexpr int Dm  = 1024;
constexpr int Hn  = 16;
constexpr int Dh  = 64;
constexpr int MTOT = Bn * Sn;   // 8192

// fp16 scratch
__device__ __half g_Q16[(size_t)MTOT * Dm];   // pre-scaled by 0.125*log2e
__device__ __half g_K16[(size_t)MTOT * Dm];
__device__ __half g_V16[(size_t)MTOT * Dm];
__device__ __half g_X16hi[(size_t)MTOT * Dm];
__device__ __half g_X16lo[(size_t)MTOT * Dm];
__device__ __half g_C16hi[(size_t)MTOT * Dm];
__device__ __half g_C16lo[(size_t)MTOT * Dm];
__device__ __half g_W16[4][(size_t)Dm * Dm];

// ---------------------------------------------------------------------------
// helpers
// ---------------------------------------------------------------------------
__device__ __forceinline__ float ex2(float x) {
    float y;
    asm("ex2.approx.ftz.f32 %0, %1;" : "=f"(y) : "f"(x));
    return y;
}

__device__ __forceinline__ void mma16h(float* d, const unsigned* a, const unsigned* b) {
    asm volatile(
        "mma.sync.aligned.m16n8k16.row.col.f32.f16.f16.f32 "
        "{%0,%1,%2,%3},{%4,%5,%6,%7},{%8,%9},{%0,%1,%2,%3};"
        : "+f"(d[0]), "+f"(d[1]), "+f"(d[2]), "+f"(d[3])
        : "r"(a[0]), "r"(a[1]), "r"(a[2]), "r"(a[3]), "r"(b[0]), "r"(b[1]));
}

__device__ __forceinline__ void ldm_x4(unsigned* r, uint32_t addr) {
    asm volatile(
        "ldmatrix.sync.aligned.m8n8.x4.shared.b16 {%0,%1,%2,%3}, [%4];"
        : "=r"(r[0]), "=r"(r[1]), "=r"(r[2]), "=r"(r[3]) : "r"(addr));
}

__device__ __forceinline__ unsigned packh2(float a, float b) {
    __half2 h = __floats2half2_rn(a, b);    // low = a
    return *reinterpret_cast<unsigned*>(&h);
}

__device__ __forceinline__ void cpasync16(uint32_t dst, const void* src) {
    asm volatile("cp.async.cg.shared.global [%0], [%1], 16;" :: "r"(dst), "l"(src));
}

// ---------------------------------------------------------------------------
// conversions
// ---------------------------------------------------------------------------
__global__ __launch_bounds__(256)
void k_cvt16(const float* __restrict__ src, __half* __restrict__ hi,
             __half* __restrict__ lo, int n4)
{
    int i = blockIdx.x * blockDim.x + threadIdx.x;
    if (i >= n4) return;
    float4 v = reinterpret_cast<const float4*>(src)[i];
    __half h0 = __float2half_rn(v.x);
    __half h1 = __float2half_rn(v.y);
    __half h2 = __float2half_rn(v.z);
    __half h3 = __float2half_rn(v.w);
    __half l0 = __float2half_rn(v.x - __half2float(h0));
    __half l1 = __float2half_rn(v.y - __half2float(h1));
    __half l2 = __float2half_rn(v.z - __half2float(h2));
    __half l3 = __float2half_rn(v.w - __half2float(h3));
    reinterpret_cast<__half2*>(hi)[i * 2 + 0] = __halves2half2(h0, h1);
    reinterpret_cast<__half2*>(hi)[i * 2 + 1] = __halves2half2(h2, h3);
    reinterpret_cast<__half2*>(lo)[i * 2 + 0] = __halves2half2(l0, l1);
    reinterpret_cast<__half2*>(lo)[i * 2 + 1] = __halves2half2(l2, l3);
}

// all 4 weights in one launch: blockIdx.y selects the matrix
__global__ __launch_bounds__(256)
void k_cvtW(const float* __restrict__ wq, const float* __restrict__ wk,
            const float* __restrict__ wv, const float* __restrict__ wo,
            __half* __restrict__ dst, int n4)
{
    int i = blockIdx.x * blockDim.x + threadIdx.x;
    if (i >= n4) return;
    const float* src = (blockIdx.y == 0) ? wq : (blockIdx.y == 1) ? wk
                       : (blockIdx.y == 2) ? wv : wo;
    __half* out = dst + (size_t)blockIdx.y * Dm * Dm;
    float4 v = reinterpret_cast<const float4*>(src)[i];
    reinterpret_cast<__half2*>(out)[i * 2 + 0] =
        __halves2half2(__float2half_rn(v.x), __float2half_rn(v.y));
    reinterpret_cast<__half2*>(out)[i * 2 + 1] =
        __halves2half2(__float2half_rn(v.z), __float2half_rn(v.w));
}

// ---------------------------------------------------------------------------
// fp16 2-pass GEMM core: C = (Ahi + Alo) . Bh^T + bias
// mode: 0 = f32 out, 2 = fp16 out (scaled by oscale)
// ---------------------------------------------------------------------------
constexpr int ROWU  = 20;
constexpr int TILEU = 128 * ROWU;
constexpr int TILEB = TILEU * 4;
constexpr int GEMM2_SMEM = 2 * 3 * TILEB;   // 61440 bytes

__device__ __forceinline__ void gemm2_core(
    const __half* __restrict__ Ahi,
    const __half* __restrict__ Alo,
    const __half* __restrict__ Bh,
    const float* __restrict__ bias,
    float* __restrict__ Cf, __half* __restrict__ Ch, int mode, float oscale)
{
    extern __shared__ unsigned sm[];

    const int tid  = threadIdx.x;
    const int lane = tid & 31;
    const int warp = tid >> 5;
    const int wm   = warp >> 2;
    const int wn   = warp & 3;
    const int m0   = blockIdx.y * 128;
    const int n0   = blockIdx.x * 128;

    const int r  = tid >> 1;
    const int c0 = (tid & 1) * 8;

    const unsigned* gp[3];
    gp[0] = reinterpret_cast<const unsigned*>(Ahi) + (size_t)(m0 + r) * (Dm / 2) + c0;
    gp[1] = reinterpret_cast<const unsigned*>(Alo) + (size_t)(m0 + r) * (Dm / 2) + c0;
    gp[2] = reinterpret_cast<const unsigned*>(Bh)  + (size_t)(n0 + r) * (Dm / 2) + c0;
    const int stoff = r * ROWU + c0;

    const uint32_t smemBase = (uint32_t)__cvta_generic_to_shared(sm);
    const uint32_t aOff = ((lane & 15) * ROWU + ((lane >> 4) & 1) * 4) * 4
                          + wm * 64 * ROWU * 4;
    const uint32_t bOff = (((lane & 7) + ((lane >> 1) & 8)) * ROWU
                           + ((lane >> 3) & 1) * 4) * 4
                          + wn * 32 * ROWU * 4;

    float acc[4][4][4];
#pragma unroll
    for (int mf = 0; mf < 4; ++mf)
#pragma unroll
        for (int nf = 0; nf < 4; ++nf)
#pragma unroll
            for (int j = 0; j < 4; ++j) acc[mf][nf][j] = 0.f;

    uint4 ld[3][2];

#pragma unroll
    for (int mat = 0; mat < 3; ++mat) {
        ld[mat][0] = *reinterpret_cast<const uint4*>(gp[mat]);
        ld[mat][1] = *reinterpret_cast<const uint4*>(gp[mat] + 4);
    }
#pragma unroll
    for (int mat = 0; mat < 3; ++mat) {
        *reinterpret_cast<uint4*>(sm + mat * TILEU + stoff)     = ld[mat][0];
        *reinterpret_cast<uint4*>(sm + mat * TILEU + stoff + 4) = ld[mat][1];
    }
    __syncthreads();

    int buf = 0;
    const int NSTAGE = Dm / 32;

    for (int st = 0; st < NSTAGE; ++st) {
        if (st + 1 < NSTAGE) {
#pragma unroll
            for (int mat = 0; mat < 3; ++mat) {
                ld[mat][0] = *reinterpret_cast<const uint4*>(gp[mat] + (st + 1) * 16);
                ld[mat][1] = *reinterpret_cast<const uint4*>(gp[mat] + (st + 1) * 16 + 4);
            }
        }

        const uint32_t aHiB = smemBase + (buf * 3 + 0) * TILEB + aOff;
        const uint32_t aLoB = smemBase + (buf * 3 + 1) * TILEB + aOff;
        const uint32_t bB   = smemBase + (buf * 3 + 2) * TILEB + bOff;

#pragma unroll
        for (int ks = 0; ks < 2; ++ks) {
            const uint32_t kadd = ks * 32;
            unsigned ahi[4][4], alo[4][4], bf[4][2];
#pragma unroll
            for (int mf = 0; mf < 4; ++mf) {
                ldm_x4(ahi[mf], aHiB + mf * (16 * ROWU * 4) + kadd);
                ldm_x4(alo[mf], aLoB + mf * (16 * ROWU * 4) + kadd);
            }
#pragma unroll
            for (int np = 0; np < 2; ++np) {
                unsigned t[4];
                ldm_x4(t, bB + np * (16 * ROWU * 4) + kadd);
                bf[np * 2][0] = t[0]; bf[np * 2][1] = t[1];
                bf[np * 2 + 1][0] = t[2]; bf[np * 2 + 1][1] = t[3];
            }
#pragma unroll
            for (int mf = 0; mf < 4; ++mf)
#pragma unroll
                for (int nf = 0; nf < 4; ++nf) {
                    mma16h(acc[mf][nf], ahi[mf], bf[nf]);
                    mma16h(acc[mf][nf], alo[mf], bf[nf]);
                }
        }

        if (st + 1 < NSTAGE) {
            const int nb = buf ^ 1;
#pragma unroll
            for (int mat = 0; mat < 3; ++mat) {
                *reinterpret_cast<uint4*>(sm + (nb * 3 + mat) * TILEU + stoff)     = ld[mat][0];
                *reinterpret_cast<uint4*>(sm + (nb * 3 + mat) * TILEU + stoff + 4) = ld[mat][1];
            }
        }
        __syncthreads();
        buf ^= 1;
    }

#pragma unroll
    for (int mf = 0; mf < 4; ++mf) {
        const int r0 = m0 + wm * 64 + mf * 16 + (lane >> 2);
#pragma unroll
        for (int nf = 0; nf < 4; ++nf) {
            const int c = n0 + wn * 32 + nf * 8 + (lane & 3) * 2;
            float2 bv = *reinterpret_cast<const float2*>(bias + c);
            float o0x = acc[mf][nf][0] + bv.x;
            float o0y = acc[mf][nf][1] + bv.y;
            float o1x = acc[mf][nf][2] + bv.x;
            float o1y = acc[mf][nf][3] + bv.y;
            if (mode == 2) {
                o0x *= oscale; o0y *= oscale; o1x *= oscale; o1y *= oscale;
                *reinterpret_cast<__half2*>(Ch + (size_t)r0 * Dm + c) =
                    __halves2half2(__float2half_rn(o0x), __float2half_rn(o0y));
                *reinterpret_cast<__half2*>(Ch + (size_t)(r0 + 8) * Dm + c) =
                    __halves2half2(__float2half_rn(o1x), __float2half_rn(o1y));
            } else {
                *reinterpret_cast<float2*>(Cf + (size_t)r0 * Dm + c)       = make_float2(o0x, o0y);
                *reinterpret_cast<float2*>(Cf + (size_t)(r0 + 8) * Dm + c) = make_float2(o1x, o1y);
            }
        }
    }
}

constexpr float QSCALE = 0.125f * 1.44269504088896f;

// QKV fused: z=0 Q (fp16, pre-scaled), z=1 K (fp16), z=2 V (fp16)
__global__ __launch_bounds__(256)
void k_proj3(const __half* __restrict__ xhi, const __half* __restrict__ xlo,
             const __half* __restrict__ w16,
             const float* __restrict__ bq, const float* __restrict__ bk,
             const float* __restrict__ bv,
             __half* __restrict__ q, __half* __restrict__ k, __half* __restrict__ v)
{
    const size_t WSZ = (size_t)Dm * Dm;
    const int z = blockIdx.z;
    if (z == 0)      gemm2_core(xhi, xlo, w16,           bq, nullptr, q, 2, QSCALE);
    else if (z == 1) gemm2_core(xhi, xlo, w16 + WSZ,     bk, nullptr, k, 2, 1.f);
    else             gemm2_core(xhi, xlo, w16 + 2 * WSZ, bv, nullptr, v, 2, 1.f);
}

__global__ __launch_bounds__(256)
void k_oproj16(const __half* __restrict__ chi, const __half* __restrict__ clo,
               const __half* __restrict__ wo, const float* __restrict__ bo,
               float* __restrict__ out)
{
    gemm2_core(chi, clo, wo, bo, out, nullptr, 0, 1.f);
}

// ---------------------------------------------------------------------------
// Flash attention: QK^T fp16 single-pass (K cp.async double-buffered fp16),
// PV fp16 (V register-prefetch + byte_perm pack). 256 thr / 8 warps,
// 128 q rows, 64-key tiles, base-2 softmax (Q pre-scaled).
// Smem layout (bytes):
//   Kst [2][64][72] half @ 0      (18432)
//   Vp  [64][36] u32     @ 18432  ( 9216)
//   Pp  [128][36] u32    @ 27648  (18432)
//   msk [2][64] int      @ 46080  (  512)
// ---------------------------------------------------------------------------
constexpr int ATTN_SMEM = 46592;

__global__ __launch_bounds__(256)
void k_attn(const int* __restrict__ mask,
            __half* __restrict__ Chi, __half* __restrict__ Clo)
{
    extern __shared__ __align__(16) unsigned char smraw[];
    unsigned* Vp  = (unsigned*)(smraw + 18432);
    unsigned* Pp  = (unsigned*)(smraw + 27648);
    int*      msk = (int*)(smraw + 46080);

    const int tid  = threadIdx.x;
    const int lane = tid & 31;
    const int wq   = tid >> 5;
    const int bh   = blockIdx.y;
    const int b    = bh >> 4;
    const int h    = bh & 15;
    const int q0   = blockIdx.x * 128;

    const uint32_t KstA = (uint32_t)__cvta_generic_to_shared(smraw);
    const uint32_t VpA  = KstA + 18432;
    const uint32_t PpA  = KstA + 27648;
    const uint32_t mskA = KstA + 46080;

    // cp.async addressing (K tile, fp16: 64 rows x 128 B)
    const int prow = tid >> 2;                 // 0..63
    const int pcol = (tid & 3) * 32;           // byte offset in row: 0,32,64,96
    const uint32_t kDst = (uint32_t)(prow * 144 + pcol);

    // V prefetch addressing
    const int kpi  = tid >> 3;            // 0..31 (key pair)
    const int dseg = (tid & 7) * 8;       // 0..56

    // ldmatrix per-lane offsets
    const int rowB = (lane & 7) + ((lane >> 1) & 8);
    const int colB16 = ((lane >> 3) & 1) * 16;            // byte col within 32B half-row
    const uint32_t offQK  = (uint32_t)(rowB * 144 + colB16);
    const int rowBv = (lane & 7) + ((lane & 16) ? 8 : 0);
    const uint32_t offPVb = (uint32_t)(rowBv * 144 + ((lane >> 3) & 1) * 16);
    const int rowA = wq * 16 + (lane & 7) + ((lane >> 3) & 1) * 8;
    const uint32_t offPVa = (uint32_t)(rowA * 144 + ((lane >> 4) & 1) * 16);

    // Q fragments (fp16, pre-scaled): a-frag for m16n8k16, 4 k-steps
    unsigned qf[4][4];
    {
        const __half* qbase = g_Q16 + ((size_t)(b * Sn + q0 + wq * 16) * Dm + h * Dh);
#pragma unroll
        for (int c = 0; c < 4; ++c)
#pragma unroll
            for (int j = 0; j < 4; ++j) {
                int row = (lane >> 2) + ((j & 1) << 3);
                int col = c * 16 + (lane & 3) * 2 + ((j >> 1) << 3);
                qf[c][j] = *reinterpret_cast<const unsigned*>(
                    qbase + (size_t)row * Dm + col);
            }
    }

    float of[8][4];
#pragma unroll
    for (int nf = 0; nf < 8; ++nf)
#pragma unroll
        for (int j = 0; j < 4; ++j) of[nf][j] = 0.f;

    float m0r = -INFINITY, m1r = -INFINITY;
    float l0 = 0.f, l1 = 0.f;

    const int NT = Sn / 64;

    // prefetch K tile 0 + mask 0
    {
        const __half* kp = g_K16 + (size_t)(b * Sn + prow) * Dm + h * Dh + pcol / 2;
        cpasync16(KstA + kDst,      kp);
        cpasync16(KstA + kDst + 16, kp + 8);
        if (tid < 16) cpasync16(mskA + tid * 16, mask + (size_t)b * Sn + tid * 4);
        asm volatile("cp.async.commit_group;");
    }

    for (int kt = 0; kt < NT; ++kt) {
        const int p = kt & 1;
        __syncthreads();   // prior consumers of Vp/Pp done; Kst[p^1] free

        // V prefetch for tile kt (fp16, registers; consumed after QK)
        uint4 va, vb;
        {
            const __half* vsrc = g_V16 +
                (size_t)(b * Sn + kt * 64 + 2 * kpi) * Dm + h * Dh + dseg;
            va = *reinterpret_cast<const uint4*>(vsrc);
            vb = *reinterpret_cast<const uint4*>(vsrc + Dm);
        }

        if (kt + 1 < NT) {
            const __half* kp = g_K16 +
                (size_t)(b * Sn + (kt + 1) * 64 + prow) * Dm + h * Dh + pcol / 2;
            const uint32_t bofs = (uint32_t)((p ^ 1) * 9216);
            cpasync16(KstA + bofs + kDst,      kp);
            cpasync16(KstA + bofs + kDst + 16, kp + 8);
            if (tid < 16)
                cpasync16(mskA + (p ^ 1) * 256 + tid * 16,
                          mask + (size_t)b * Sn + (kt + 1) * 64 + tid * 4);
            asm volatile("cp.async.commit_group;");
            asm volatile("cp.async.wait_group 1;");
        } else {
            asm volatile("cp.async.wait_group 0;");
        }
        __syncthreads();   // K tile kt visible

        // S = Q . K^T (fp16 m16n8k16)
        float sf[8][4];
#pragma unroll
        for (int nf = 0; nf < 8; ++nf)
#pragma unroll
            for (int j = 0; j < 4; ++j) sf[nf][j] = 0.f;

        const uint32_t kBase = KstA + (uint32_t)(p * 9216) + offQK;
#pragma unroll
        for (int c = 0; c < 4; ++c) {
#pragma unroll
            for (int np = 0; np < 4; ++np) {
                unsigned t[4];
                ldm_x4(t, kBase + (uint32_t)(np * 16 * 144 + c * 32));
                unsigned b0[2] = { t[0], t[1] };
                unsigned b1[2] = { t[2], t[3] };
                mma16h(sf[np * 2],     qf[c], b0);
                mma16h(sf[np * 2 + 1], qf[c], b1);
            }
        }

        // pack V regs -> Vp ([d][keypair] half2) via byte_perm
        {
            unsigned* vrow = Vp + dseg * 36 + kpi;
            vrow[0 * 36] = __byte_perm(va.x, vb.x, 0x5410);
            vrow[1 * 36] = __byte_perm(va.x, vb.x, 0x7632);
            vrow[2 * 36] = __byte_perm(va.y, vb.y, 0x5410);
            vrow[3 * 36] = __byte_perm(va.y, vb.y, 0x7632);
            vrow[4 * 36] = __byte_perm(va.z, vb.z, 0x5410);
            vrow[5 * 36] = __byte_perm(va.z, vb.z, 0x7632);
            vrow[6 * 36] = __byte_perm(va.w, vb.w, 0x5410);
            vrow[7 * 36] = __byte_perm(va.w, vb.w, 0x7632);
        }

        // mask + online softmax (base 2)
        const int* mk = msk + p * 64;
        float tmax0 = -INFINITY, tmax1 = -INFINITY;
#pragma unroll
        for (int nf = 0; nf < 8; ++nf) {
            const int c = nf * 8 + (lane & 3) * 2;
            if (!mk[c])     { sf[nf][0] = -1e20f; sf[nf][2] = -1e20f; }
            if (!mk[c + 1]) { sf[nf][1] = -1e20f; sf[nf][3] = -1e20f; }
            tmax0 = fmaxf(tmax0, fmaxf(sf[nf][0], sf[nf][1]));
            tmax1 = fmaxf(tmax1, fmaxf(sf[nf][2], sf[nf][3]));
        }
        tmax0 = fmaxf(tmax0, __shfl_xor_sync(0xffffffff, tmax0, 1));
        tmax0 = fmaxf(tmax0, __shfl_xor_sync(0xffffffff, tmax0, 2));
        tmax1 = fmaxf(tmax1, __shfl_xor_sync(0xffffffff, tmax1, 1));
        tmax1 = fmaxf(tmax1, __shfl_xor_sync(0xffffffff, tmax1, 2));

        const float mn0 = fmaxf(m0r, tmax0);
        const float mn1 = fmaxf(m1r, tmax1);
        const float a0  = ex2(m0r - mn0);
        const float a1  = ex2(m1r - mn1);
        l0 *= a0; l1 *= a1;
        if (!__all_sync(0xffffffff, (a0 == 1.f) & (a1 == 1.f))) {
#pragma unroll
            for (int nf = 0; nf < 8; ++nf) {
                of[nf][0] *= a0; of[nf][1] *= a0;
                of[nf][2] *= a1; of[nf][3] *= a1;
            }
        }

        float s0 = 0.f, s1 = 0.f;
#pragma unroll
        for (int nf = 0; nf < 8; ++nf) {
            sf[nf][0] = ex2(sf[nf][0] - mn0);
            sf[nf][1] = ex2(sf[nf][1] - mn0);
            sf[nf][2] = ex2(sf[nf][2] - mn1);
            sf[nf][3] = ex2(sf[nf][3] - mn1);
            s0 += sf[nf][0] + sf[nf][1];
            s1 += sf[nf][2] + sf[nf][3];
        }
        s0 += __shfl_xor_sync(0xffffffff, s0, 1);
        s0 += __shfl_xor_sync(0xffffffff, s0, 2);
        s1 += __shfl_xor_sync(0xffffffff, s1, 1);
        s1 += __shfl_xor_sync(0xffffffff, s1, 2);
        l0 += s0; l1 += s1;
        m0r = mn0; m1r = mn1;

        // pack P -> half2 (warp-private rows; Pp row stride 36 u32 = 144 B)
        {
            const int r  = wq * 16 + (lane >> 2);
            const int kp = (lane & 3);
#pragma unroll
            for (int nf = 0; nf < 8; ++nf) {
                Pp[r * 36 + nf * 4 + kp]       = packh2(sf[nf][0], sf[nf][1]);
                Pp[(r + 8) * 36 + nf * 4 + kp] = packh2(sf[nf][2], sf[nf][3]);
            }
        }
        __syncthreads();   // Vp pack + Pp writes complete before PV reads

        // O += P . V
#pragma unroll
        for (int c = 0; c < 4; ++c) {
            unsigned af[4];
            ldm_x4(af, PpA + (uint32_t)(c * 32) + offPVa);
#pragma unroll
            for (int np = 0; np < 4; ++np) {
                unsigned t[4];
                ldm_x4(t, VpA + (uint32_t)(np * 16 * 144 + c * 32) + offPVb);
                unsigned b0[2] = { t[0], t[1] };
                unsigned b1[2] = { t[2], t[3] };
                mma16h(of[np * 2],     af, b0);
                mma16h(of[np * 2 + 1], af, b1);
            }
        }
    }

    // epilogue: normalize, split to fp16 hi/lo, write
    const float inv0 = 1.f / l0;
    const float inv1 = 1.f / l1;
    const size_t rbase = (size_t)(b * Sn + q0 + wq * 16);
#pragma unroll
    for (int nf = 0; nf < 8; ++nf) {
        const int c = h * Dh + nf * 8 + (lane & 3) * 2;
        const int r = lane >> 2;
        float v00 = of[nf][0] * inv0, v01 = of[nf][1] * inv0;
        float v10 = of[nf][2] * inv1, v11 = of[nf][3] * inv1;
        __half h00 = __float2half_rn(v00), h01 = __float2half_rn(v01);
        __half h10 = __float2half_rn(v10), h11 = __float2half_rn(v11);
        __half l00 = __float2half_rn(v00 - __half2float(h00));
        __half l01 = __float2half_rn(v01 - __half2float(h01));
        __half l10 = __float2half_rn(v10 - __half2float(h10));
        __half l11 = __float2half_rn(v11 - __half2float(h11));
        *reinterpret_cast<__half2*>(Chi + (rbase + r) * Dm + c)     = __halves2half2(h00, h01);
        *reinterpret_cast<__half2*>(Chi + (rbase + r + 8) * Dm + c) = __halves2half2(h10, h11);
        *reinterpret_cast<__half2*>(Clo + (rbase + r) * Dm + c)     = __halves2half2(l00, l01);
        *reinterpret_cast<__half2*>(Clo + (rbase + r + 8) * Dm + c) = __halves2half2(l10, l11);
    }
}

// ---------------------------------------------------------------------------
// Launch
// ---------------------------------------------------------------------------
extern "C" void kernel_launch(void* const* d_in, const int* in_sizes, int n_in,
                              void* d_out, int out_size)
{
    const float* query = (const float*)d_in[0];
    const int*   mask  = (const int*)  d_in[1];
    const float* Wq    = (const float*)d_in[2];
    const float* bq    = (const float*)d_in[3];
    const float* Wk    = (const float*)d_in[4];
    const float* bk    = (const float*)d_in[5];
    const float* Wv    = (const float*)d_in[6];
    const float* bv    = (const float*)d_in[7];
    const float* Wo    = (const float*)d_in[8];
    const float* bo    = (const float*)d_in[9];
    float* out = (float*)d_out;

    static int init_done = 0;
    if (!init_done) {
        cudaFuncSetAttribute(k_proj3,  cudaFuncAttributeMaxDynamicSharedMemorySize, GEMM2_SMEM);
        cudaFuncSetAttribute(k_oproj16,cudaFuncAttributeMaxDynamicSharedMemorySize, GEMM2_SMEM);
        cudaFuncSetAttribute(k_attn,   cudaFuncAttributeMaxDynamicSharedMemorySize, ATTN_SMEM);
        init_done = 1;
    }

    __half *x16hi, *x16lo, *c16hi, *c16lo, *w16, *q16, *k16, *v16;
    cudaGetSymbolAddress((void**)&x16hi, g_X16hi);
    cudaGetSymbolAddress((void**)&x16lo, g_X16lo);
    cudaGetSymbolAddress((void**)&c16hi, g_C16hi);
    cudaGetSymbolAddress((void**)&c16lo, g_C16lo);
    cudaGetSymbolAddress((void**)&w16, g_W16);
    cudaGetSymbolAddress((void**)&q16, g_Q16);
    cudaGetSymbolAddress((void**)&k16, g_K16);
    cudaGetSymbolAddress((void**)&v16, g_V16);

    const size_t WSZ = (size_t)Dm * Dm;
    const int nX4 = MTOT * Dm / 4;
    const int nW4 = Dm * Dm / 4;

    // conversions
    k_cvt16<<<(nX4 + 255) / 256, 256>>>(query, x16hi, x16lo, nX4);
    dim3 gw((nW4 + 255) / 256, 4);
    k_cvtW<<<gw, 256>>>(Wq, Wk, Wv, Wo, w16, nW4);

    // QKV projections (fp16 2-pass, fp16 out)
    dim3 gq(Dm / 128, MTOT / 128, 3);
    k_proj3<<<gq, 256, GEMM2_SMEM>>>(x16hi, x16lo, w16, bq, bk, bv, q16, k16, v16);

    // attention
    dim3 ga(Sn / 128, Bn * Hn);
    k_attn<<<ga, 256, ATTN_SMEM>>>(mask, c16hi, c16lo);

    // output projection (fp16 2-pass, f32 out)
    dim3 go(Dm / 128, MTOT / 128);
    k_oproj16<<<go, 256, GEMM2_SMEM>>>(c16hi, c16lo, w16 + 3 * WSZ, bo, out);
}

// round 11
// speedup vs baseline: 7.6417x; 1.2976x over previous
#include <cuda_runtime.h>
#include <cuda_fp16.h>
#include <math.h>
#include <stdint.h>

constexpr int Bn  = 4;
constexpr int Sn  = 2048;
constexpr int Dm  = 1024;
constexpr int Hn  = 16;
constexpr int Dh  = 64;
constexpr int MTOT = Bn * Sn;   // 8192

// fp16 scratch
__device__ __half g_Q16[(size_t)MTOT * Dm];   // pre-scaled by 0.125*log2e
__device__ __half g_K16[(size_t)MTOT * Dm];
__device__ __half g_V16[(size_t)MTOT * Dm];
__device__ __half g_X16[(size_t)MTOT * Dm];
__device__ __half g_C16[(size_t)MTOT * Dm];
__device__ __half g_W16[4][(size_t)Dm * Dm];

// ---------------------------------------------------------------------------
// helpers
// ---------------------------------------------------------------------------
__device__ __forceinline__ float ex2(float x) {
    float y;
    asm("ex2.approx.ftz.f32 %0, %1;" : "=f"(y) : "f"(x));
    return y;
}

__device__ __forceinline__ void mma16h(float* d, const unsigned* a, const unsigned* b) {
    asm volatile(
        "mma.sync.aligned.m16n8k16.row.col.f32.f16.f16.f32 "
        "{%0,%1,%2,%3},{%4,%5,%6,%7},{%8,%9},{%0,%1,%2,%3};"
        : "+f"(d[0]), "+f"(d[1]), "+f"(d[2]), "+f"(d[3])
        : "r"(a[0]), "r"(a[1]), "r"(a[2]), "r"(a[3]), "r"(b[0]), "r"(b[1]));
}

__device__ __forceinline__ void ldm_x4(unsigned* r, uint32_t addr) {
    asm volatile(
        "ldmatrix.sync.aligned.m8n8.x4.shared.b16 {%0,%1,%2,%3}, [%4];"
        : "=r"(r[0]), "=r"(r[1]), "=r"(r[2]), "=r"(r[3]) : "r"(addr));
}

__device__ __forceinline__ unsigned packh2(float a, float b) {
    __half2 h = __floats2half2_rn(a, b);    // low = a
    return *reinterpret_cast<unsigned*>(&h);
}

__device__ __forceinline__ void cpasync16(uint32_t dst, const void* src) {
    asm volatile("cp.async.cg.shared.global [%0], [%1], 16;" :: "r"(dst), "l"(src));
}

// ---------------------------------------------------------------------------
// conversions
// ---------------------------------------------------------------------------
__global__ __launch_bounds__(256)
void k_cvtX(const float* __restrict__ src, __half* __restrict__ dst, int n4)
{
    int i = blockIdx.x * blockDim.x + threadIdx.x;
    if (i >= n4) return;
    float4 v = reinterpret_cast<const float4*>(src)[i];
    reinterpret_cast<__half2*>(dst)[i * 2 + 0] =
        __halves2half2(__float2half_rn(v.x), __float2half_rn(v.y));
    reinterpret_cast<__half2*>(dst)[i * 2 + 1] =
        __halves2half2(__float2half_rn(v.z), __float2half_rn(v.w));
}

__global__ __launch_bounds__(256)
void k_cvtW(const float* __restrict__ wq, const float* __restrict__ wk,
            const float* __restrict__ wv, const float* __restrict__ wo,
            __half* __restrict__ dst, int n4)
{
    int i = blockIdx.x * blockDim.x + threadIdx.x;
    if (i >= n4) return;
    const float* src = (blockIdx.y == 0) ? wq : (blockIdx.y == 1) ? wk
                       : (blockIdx.y == 2) ? wv : wo;
    __half* out = dst + (size_t)blockIdx.y * Dm * Dm;
    float4 v = reinterpret_cast<const float4*>(src)[i];
    reinterpret_cast<__half2*>(out)[i * 2 + 0] =
        __halves2half2(__float2half_rn(v.x), __float2half_rn(v.y));
    reinterpret_cast<__half2*>(out)[i * 2 + 1] =
        __halves2half2(__float2half_rn(v.z), __float2half_rn(v.w));
}

// ---------------------------------------------------------------------------
// Single-pass fp16 GEMM core: C = A . B^T + bias
// mode: 0 = f32 out, 2 = fp16 out (scaled by oscale)
// Block tile 128x128, K-stage 32, double-buffered smem, ldmatrix.
// ---------------------------------------------------------------------------
constexpr int ROWU  = 20;
constexpr int TILEU = 128 * ROWU;
constexpr int TILEB = TILEU * 4;
constexpr int GEMM1_SMEM = 2 * 2 * TILEB;   // 40960 bytes

__device__ __forceinline__ void gemm1_core(
    const __half* __restrict__ A,
    const __half* __restrict__ Bh,
    const float* __restrict__ bias,
    float* __restrict__ Cf, __half* __restrict__ Ch, int mode, float oscale)
{
    extern __shared__ unsigned sm[];

    const int tid  = threadIdx.x;
    const int lane = tid & 31;
    const int warp = tid >> 5;
    const int wm   = warp >> 2;
    const int wn   = warp & 3;
    const int m0   = blockIdx.y * 128;
    const int n0   = blockIdx.x * 128;

    const int r  = tid >> 1;
    const int c0 = (tid & 1) * 8;

    const unsigned* gp[2];
    gp[0] = reinterpret_cast<const unsigned*>(A)  + (size_t)(m0 + r) * (Dm / 2) + c0;
    gp[1] = reinterpret_cast<const unsigned*>(Bh) + (size_t)(n0 + r) * (Dm / 2) + c0;
    const int stoff = r * ROWU + c0;

    const uint32_t smemBase = (uint32_t)__cvta_generic_to_shared(sm);
    const uint32_t aOff = ((lane & 15) * ROWU + ((lane >> 4) & 1) * 4) * 4
                          + wm * 64 * ROWU * 4;
    const uint32_t bOff = (((lane & 7) + ((lane >> 1) & 8)) * ROWU
                           + ((lane >> 3) & 1) * 4) * 4
                          + wn * 32 * ROWU * 4;

    float acc[4][4][4];
#pragma unroll
    for (int mf = 0; mf < 4; ++mf)
#pragma unroll
        for (int nf = 0; nf < 4; ++nf)
#pragma unroll
            for (int j = 0; j < 4; ++j) acc[mf][nf][j] = 0.f;

    uint4 ld[2][2];

#pragma unroll
    for (int mat = 0; mat < 2; ++mat) {
        ld[mat][0] = *reinterpret_cast<const uint4*>(gp[mat]);
        ld[mat][1] = *reinterpret_cast<const uint4*>(gp[mat] + 4);
    }
#pragma unroll
    for (int mat = 0; mat < 2; ++mat) {
        *reinterpret_cast<uint4*>(sm + mat * TILEU + stoff)     = ld[mat][0];
        *reinterpret_cast<uint4*>(sm + mat * TILEU + stoff + 4) = ld[mat][1];
    }
    __syncthreads();

    int buf = 0;
    const int NSTAGE = Dm / 32;

    for (int st = 0; st < NSTAGE; ++st) {
        if (st + 1 < NSTAGE) {
#pragma unroll
            for (int mat = 0; mat < 2; ++mat) {
                ld[mat][0] = *reinterpret_cast<const uint4*>(gp[mat] + (st + 1) * 16);
                ld[mat][1] = *reinterpret_cast<const uint4*>(gp[mat] + (st + 1) * 16 + 4);
            }
        }

        const uint32_t aB = smemBase + (buf * 2 + 0) * TILEB + aOff;
        const uint32_t bB = smemBase + (buf * 2 + 1) * TILEB + bOff;

#pragma unroll
        for (int ks = 0; ks < 2; ++ks) {
            const uint32_t kadd = ks * 32;
            unsigned af[4][4], bf[4][2];
#pragma unroll
            for (int mf = 0; mf < 4; ++mf)
                ldm_x4(af[mf], aB + mf * (16 * ROWU * 4) + kadd);
#pragma unroll
            for (int np = 0; np < 2; ++np) {
                unsigned t[4];
                ldm_x4(t, bB + np * (16 * ROWU * 4) + kadd);
                bf[np * 2][0] = t[0]; bf[np * 2][1] = t[1];
                bf[np * 2 + 1][0] = t[2]; bf[np * 2 + 1][1] = t[3];
            }
#pragma unroll
            for (int mf = 0; mf < 4; ++mf)
#pragma unroll
                for (int nf = 0; nf < 4; ++nf)
                    mma16h(acc[mf][nf], af[mf], bf[nf]);
        }

        if (st + 1 < NSTAGE) {
            const int nb = buf ^ 1;
#pragma unroll
            for (int mat = 0; mat < 2; ++mat) {
                *reinterpret_cast<uint4*>(sm + (nb * 2 + mat) * TILEU + stoff)     = ld[mat][0];
                *reinterpret_cast<uint4*>(sm + (nb * 2 + mat) * TILEU + stoff + 4) = ld[mat][1];
            }
        }
        __syncthreads();
        buf ^= 1;
    }

#pragma unroll
    for (int mf = 0; mf < 4; ++mf) {
        const int r0 = m0 + wm * 64 + mf * 16 + (lane >> 2);
#pragma unroll
        for (int nf = 0; nf < 4; ++nf) {
            const int c = n0 + wn * 32 + nf * 8 + (lane & 3) * 2;
            float2 bv = *reinterpret_cast<const float2*>(bias + c);
            float o0x = acc[mf][nf][0] + bv.x;
            float o0y = acc[mf][nf][1] + bv.y;
            float o1x = acc[mf][nf][2] + bv.x;
            float o1y = acc[mf][nf][3] + bv.y;
            if (mode == 2) {
                o0x *= oscale; o0y *= oscale; o1x *= oscale; o1y *= oscale;
                *reinterpret_cast<__half2*>(Ch + (size_t)r0 * Dm + c) =
                    __halves2half2(__float2half_rn(o0x), __float2half_rn(o0y));
                *reinterpret_cast<__half2*>(Ch + (size_t)(r0 + 8) * Dm + c) =
                    __halves2half2(__float2half_rn(o1x), __float2half_rn(o1y));
            } else {
                *reinterpret_cast<float2*>(Cf + (size_t)r0 * Dm + c)       = make_float2(o0x, o0y);
                *reinterpret_cast<float2*>(Cf + (size_t)(r0 + 8) * Dm + c) = make_float2(o1x, o1y);
            }
        }
    }
}

constexpr float QSCALE = 0.125f * 1.44269504088896f;

__global__ __launch_bounds__(256)
void k_proj3(const __half* __restrict__ x16, const __half* __restrict__ w16,
             const float* __restrict__ bq, const float* __restrict__ bk,
             const float* __restrict__ bv,
             __half* __restrict__ q, __half* __restrict__ k, __half* __restrict__ v)
{
    const size_t WSZ = (size_t)Dm * Dm;
    const int z = blockIdx.z;
    if (z == 0)      gemm1_core(x16, w16,           bq, nullptr, q, 2, QSCALE);
    else if (z == 1) gemm1_core(x16, w16 + WSZ,     bk, nullptr, k, 2, 1.f);
    else             gemm1_core(x16, w16 + 2 * WSZ, bv, nullptr, v, 2, 1.f);
}

__global__ __launch_bounds__(256)
void k_oproj(const __half* __restrict__ c16, const __half* __restrict__ wo,
             const float* __restrict__ bo, float* __restrict__ out)
{
    gemm1_core(c16, wo, bo, out, nullptr, 0, 1.f);
}

// ---------------------------------------------------------------------------
// Flash attention: fp16 QK^T and PV; P kept entirely in registers
// (S-accumulator fragments ARE the PV A-fragments after packing).
// K cp.async double-buffered (issued AFTER the barrier -> 1 sync/tile);
// V register-prefetch + byte_perm pack into double-buffered Vp.
// 256 thr / 8 warps, 128 q rows, 64-key tiles, base-2 softmax.
// Smem layout (bytes):
//   Kst [2][64 rows x 144B] @ 0      (18432)
//   Vp  [2][64 rows x 144B] @ 18432  (18432)
//   msk [2][64] int         @ 36864  (  512)
// ---------------------------------------------------------------------------
constexpr int ATTN_SMEM = 37376;

__global__ __launch_bounds__(256)
void k_attn(const int* __restrict__ mask, __half* __restrict__ C16)
{
    extern __shared__ __align__(16) unsigned char smraw[];
    unsigned* Vp  = (unsigned*)(smraw + 18432);
    int*      msk = (int*)(smraw + 36864);

    const int tid  = threadIdx.x;
    const int lane = tid & 31;
    const int wq   = tid >> 5;
    const int bh   = blockIdx.y;
    const int b    = bh >> 4;
    const int h    = bh & 15;
    const int q0   = blockIdx.x * 128;

    const uint32_t KstA = (uint32_t)__cvta_generic_to_shared(smraw);
    const uint32_t VpA  = KstA + 18432;
    const uint32_t mskA = KstA + 36864;

    // cp.async addressing (K tile: 64 rows x 128B data, 144B stride)
    const int prow = tid >> 2;
    const int pcol = (tid & 3) * 32;
    const uint32_t kDst = (uint32_t)(prow * 144 + pcol);

    // V prefetch addressing
    const int kpi  = tid >> 3;            // 0..31 (key pair)
    const int dseg = (tid & 7) * 8;       // 0..56

    // ldmatrix per-lane offsets (B-fragments; row stride 144 B)
    const int rowB = (lane & 7) + ((lane >> 1) & 8);
    const uint32_t offB = (uint32_t)(rowB * 144 + ((lane >> 3) & 1) * 16);

    // Q fragments (fp16, pre-scaled): a-frags for 4 k16-steps
    unsigned qf[4][4];
    {
        const __half* qbase = g_Q16 + ((size_t)(b * Sn + q0 + wq * 16) * Dm + h * Dh);
#pragma unroll
        for (int c = 0; c < 4; ++c)
#pragma unroll
            for (int j = 0; j < 4; ++j) {
                int row = (lane >> 2) + ((j & 1) << 3);
                int col = c * 16 + (lane & 3) * 2 + ((j >> 1) << 3);
                qf[c][j] = *reinterpret_cast<const unsigned*>(
                    qbase + (size_t)row * Dm + col);
            }
    }

    float of[8][4];
#pragma unroll
    for (int nf = 0; nf < 8; ++nf)
#pragma unroll
        for (int j = 0; j < 4; ++j) of[nf][j] = 0.f;

    float m0r = -INFINITY, m1r = -INFINITY;
    float l0 = 0.f, l1 = 0.f;

    const int NT = Sn / 64;

    // prologue: K/mask tile 0 via cp.async; V tile 0 to regs
    {
        const __half* kp = g_K16 + (size_t)(b * Sn + prow) * Dm + h * Dh + pcol / 2;
        cpasync16(KstA + kDst,      kp);
        cpasync16(KstA + kDst + 16, kp + 8);
        if (tid < 16) cpasync16(mskA + tid * 16, mask + (size_t)b * Sn + tid * 4);
        asm volatile("cp.async.commit_group;");
    }
    uint4 va, vb;
    {
        const __half* vsrc = g_V16 + (size_t)(b * Sn + 2 * kpi) * Dm + h * Dh + dseg;
        va = *reinterpret_cast<const uint4*>(vsrc);
        vb = *reinterpret_cast<const uint4*>(vsrc + Dm);
    }

    for (int kt = 0; kt < NT; ++kt) {
        const int p = kt & 1;

        // pack V regs (tile kt) -> Vp[p]
        {
            unsigned* vrow = Vp + p * 2304 + dseg * 36 + kpi;
            vrow[0 * 36] = __byte_perm(va.x, vb.x, 0x5410);
            vrow[1 * 36] = __byte_perm(va.x, vb.x, 0x7632);
            vrow[2 * 36] = __byte_perm(va.y, vb.y, 0x5410);
            vrow[3 * 36] = __byte_perm(va.y, vb.y, 0x7632);
            vrow[4 * 36] = __byte_perm(va.z, vb.z, 0x5410);
            vrow[5 * 36] = __byte_perm(va.z, vb.z, 0x7632);
            vrow[6 * 36] = __byte_perm(va.w, vb.w, 0x5410);
            vrow[7 * 36] = __byte_perm(va.w, vb.w, 0x7632);
        }
        // V prefetch for next tile
        if (kt + 1 < NT) {
            const __half* vsrc = g_V16 +
                (size_t)(b * Sn + (kt + 1) * 64 + 2 * kpi) * Dm + h * Dh + dseg;
            va = *reinterpret_cast<const uint4*>(vsrc);
            vb = *reinterpret_cast<const uint4*>(vsrc + Dm);
        }

        asm volatile("cp.async.wait_group 0;");   // K[p] landed
        __syncthreads();   // K[p], Vp[p] visible; all prior compute done

        // issue next K tile AFTER barrier (everyone done reading Kst[p^1])
        if (kt + 1 < NT) {
            const __half* kp = g_K16 +
                (size_t)(b * Sn + (kt + 1) * 64 + prow) * Dm + h * Dh + pcol / 2;
            const uint32_t bofs = (uint32_t)((p ^ 1) * 9216);
            cpasync16(KstA + bofs + kDst,      kp);
            cpasync16(KstA + bofs + kDst + 16, kp + 8);
            if (tid < 16)
                cpasync16(mskA + (p ^ 1) * 256 + tid * 16,
                          mask + (size_t)b * Sn + (kt + 1) * 64 + tid * 4);
            asm volatile("cp.async.commit_group;");
        }

        // S = Q . K^T (fp16 m16n8k16)
        float sf[8][4];
#pragma unroll
        for (int nf = 0; nf < 8; ++nf)
#pragma unroll
            for (int j = 0; j < 4; ++j) sf[nf][j] = 0.f;

        const uint32_t kBase = KstA + (uint32_t)(p * 9216) + offB;
#pragma unroll
        for (int c = 0; c < 4; ++c) {
#pragma unroll
            for (int np = 0; np < 4; ++np) {
                unsigned t[4];
                ldm_x4(t, kBase + (uint32_t)(np * 16 * 144 + c * 32));
                unsigned b0[2] = { t[0], t[1] };
                unsigned b1[2] = { t[2], t[3] };
                mma16h(sf[np * 2],     qf[c], b0);
                mma16h(sf[np * 2 + 1], qf[c], b1);
            }
        }

        // mask + online softmax (base 2)
        const int* mk = msk + p * 64;
        float tmax0 = -INFINITY, tmax1 = -INFINITY;
#pragma unroll
        for (int nf = 0; nf < 8; ++nf) {
            const int c = nf * 8 + (lane & 3) * 2;
            if (!mk[c])     { sf[nf][0] = -1e20f; sf[nf][2] = -1e20f; }
            if (!mk[c + 1]) { sf[nf][1] = -1e20f; sf[nf][3] = -1e20f; }
            tmax0 = fmaxf(tmax0, fmaxf(sf[nf][0], sf[nf][1]));
            tmax1 = fmaxf(tmax1, fmaxf(sf[nf][2], sf[nf][3]));
        }
        tmax0 = fmaxf(tmax0, __shfl_xor_sync(0xffffffff, tmax0, 1));
        tmax0 = fmaxf(tmax0, __shfl_xor_sync(0xffffffff, tmax0, 2));
        tmax1 = fmaxf(tmax1, __shfl_xor_sync(0xffffffff, tmax1, 1));
        tmax1 = fmaxf(tmax1, __shfl_xor_sync(0xffffffff, tmax1, 2));

        const float mn0 = fmaxf(m0r, tmax0);
        const float mn1 = fmaxf(m1r, tmax1);
        const float a0  = ex2(m0r - mn0);
        const float a1  = ex2(m1r - mn1);
        l0 *= a0; l1 *= a1;
        if (!__all_sync(0xffffffff, (a0 == 1.f) & (a1 == 1.f))) {
#pragma unroll
            for (int nf = 0; nf < 8; ++nf) {
                of[nf][0] *= a0; of[nf][1] *= a0;
                of[nf][2] *= a1; of[nf][3] *= a1;
            }
        }

        float s0 = 0.f, s1 = 0.f;
#pragma unroll
        for (int nf = 0; nf < 8; ++nf) {
            sf[nf][0] = ex2(sf[nf][0] - mn0);
            sf[nf][1] = ex2(sf[nf][1] - mn0);
            sf[nf][2] = ex2(sf[nf][2] - mn1);
            sf[nf][3] = ex2(sf[nf][3] - mn1);
            s0 += sf[nf][0] + sf[nf][1];
            s1 += sf[nf][2] + sf[nf][3];
        }
        s0 += __shfl_xor_sync(0xffffffff, s0, 1);
        s0 += __shfl_xor_sync(0xffffffff, s0, 2);
        s1 += __shfl_xor_sync(0xffffffff, s1, 1);
        s1 += __shfl_xor_sync(0xffffffff, s1, 2);
        l0 += s0; l1 += s1;
        m0r = mn0; m1r = mn1;

        // O += P . V   (P packed from S fragments -- no smem round trip)
        const uint32_t vBase = VpA + (uint32_t)(p * 9216) + offB;
#pragma unroll
        for (int c = 0; c < 4; ++c) {
            unsigned af[4];
            af[0] = packh2(sf[2 * c][0],     sf[2 * c][1]);
            af[1] = packh2(sf[2 * c][2],     sf[2 * c][3]);
            af[2] = packh2(sf[2 * c + 1][0], sf[2 * c + 1][1]);
            af[3] = packh2(sf[2 * c + 1][2], sf[2 * c + 1][3]);
#pragma unroll
            for (int np = 0; np < 4; ++np) {
                unsigned t[4];
                ldm_x4(t, vBase + (uint32_t)(np * 16 * 144 + c * 32));
                unsigned b0[2] = { t[0], t[1] };
                unsigned b1[2] = { t[2], t[3] };
                mma16h(of[np * 2],     af, b0);
                mma16h(of[np * 2 + 1], af, b1);
            }
        }
    }

    // epilogue: normalize, write fp16 ctx
    const float inv0 = 1.f / l0;
    const float inv1 = 1.f / l1;
    const size_t rbase = (size_t)(b * Sn + q0 + wq * 16);
#pragma unroll
    for (int nf = 0; nf < 8; ++nf) {
        const int c = h * Dh + nf * 8 + (lane & 3) * 2;
        const int r = lane >> 2;
        *reinterpret_cast<__half2*>(C16 + (rbase + r) * Dm + c) =
            __halves2half2(__float2half_rn(of[nf][0] * inv0),
                           __float2half_rn(of[nf][1] * inv0));
        *reinterpret_cast<__half2*>(C16 + (rbase + r + 8) * Dm + c) =
            __halves2half2(__float2half_rn(of[nf][2] * inv1),
                           __float2half_rn(of[nf][3] * inv1));
    }
}

// ---------------------------------------------------------------------------
// Launch
// ---------------------------------------------------------------------------
extern "C" void kernel_launch(void* const* d_in, const int* in_sizes, int n_in,
                              void* d_out, int out_size)
{
    const float* query = (const float*)d_in[0];
    const int*   mask  = (const int*)  d_in[1];
    const float* Wq    = (const float*)d_in[2];
    const float* bq    = (const float*)d_in[3];
    const float* Wk    = (const float*)d_in[4];
    const float* bk    = (const float*)d_in[5];
    const float* Wv    = (const float*)d_in[6];
    const float* bv    = (const float*)d_in[7];
    const float* Wo    = (const float*)d_in[8];
    const float* bo    = (const float*)d_in[9];
    float* out = (float*)d_out;

    static int init_done = 0;
    if (!init_done) {
        cudaFuncSetAttribute(k_proj3, cudaFuncAttributeMaxDynamicSharedMemorySize, GEMM1_SMEM);
        cudaFuncSetAttribute(k_oproj, cudaFuncAttributeMaxDynamicSharedMemorySize, GEMM1_SMEM);
        cudaFuncSetAttribute(k_attn,  cudaFuncAttributeMaxDynamicSharedMemorySize, ATTN_SMEM);
        init_done = 1;
    }

    __half *x16, *c16, *w16, *q16, *k16, *v16;
    cudaGetSymbolAddress((void**)&x16, g_X16);
    cudaGetSymbolAddress((void**)&c16, g_C16);
    cudaGetSymbolAddress((void**)&w16, g_W16);
    cudaGetSymbolAddress((void**)&q16, g_Q16);
    cudaGetSymbolAddress((void**)&k16, g_K16);
    cudaGetSymbolAddress((void**)&v16, g_V16);

    const size_t WSZ = (size_t)Dm * Dm;
    const int nX4 = MTOT * Dm / 4;
    const int nW4 = Dm * Dm / 4;

    // conversions
    k_cvtX<<<(nX4 + 255) / 256, 256>>>(query, x16, nX4);
    dim3 gw((nW4 + 255) / 256, 4);
    k_cvtW<<<gw, 256>>>(Wq, Wk, Wv, Wo, w16, nW4);

    // QKV projections (single-pass fp16)
    dim3 gq(Dm / 128, MTOT / 128, 3);
    k_proj3<<<gq, 256, GEMM1_SMEM>>>(x16, w16, bq, bk, bv, q16, k16, v16);

    // attention
    dim3 ga(Sn / 128, Bn * Hn);
    k_attn<<<ga, 256, ATTN_SMEM>>>(mask, c16);

    // output projection (single-pass fp16, f32 out)
    dim3 go(Dm / 128, MTOT / 128);
    k_oproj<<<go, 256, GEMM1_SMEM>>>(c16, w16 + 3 * WSZ, bo, out);
}

// round 12
// speedup vs baseline: 8.2765x; 1.0831x over previous
#include <cuda_runtime.h>
#include <cuda_fp16.h>
#include <math.h>
#include <stdint.h>

constexpr int Bn  = 4;
constexpr int Sn  = 2048;
constexpr int Dm  = 1024;
constexpr int Hn  = 16;
constexpr int Dh  = 64;
constexpr int MTOT = Bn * Sn;   // 8192

// fp16 scratch
__device__ __half g_Q16[(size_t)MTOT * Dm];   // pre-scaled by 0.125*log2e
__device__ __half g_K16[(size_t)MTOT * Dm];
__device__ __half g_V16[(size_t)MTOT * Dm];
__device__ __half g_X16[(size_t)MTOT * Dm];
__device__ __half g_C16[(size_t)MTOT * Dm];
__device__ __half g_W16[4][(size_t)Dm * Dm];

// ---------------------------------------------------------------------------
// helpers
// ---------------------------------------------------------------------------
__device__ __forceinline__ float ex2(float x) {
    float y;
    asm("ex2.approx.ftz.f32 %0, %1;" : "=f"(y) : "f"(x));
    return y;
}

__device__ __forceinline__ void mma16h(float* d, const unsigned* a, const unsigned* b) {
    asm volatile(
        "mma.sync.aligned.m16n8k16.row.col.f32.f16.f16.f32 "
        "{%0,%1,%2,%3},{%4,%5,%6,%7},{%8,%9},{%0,%1,%2,%3};"
        : "+f"(d[0]), "+f"(d[1]), "+f"(d[2]), "+f"(d[3])
        : "r"(a[0]), "r"(a[1]), "r"(a[2]), "r"(a[3]), "r"(b[0]), "r"(b[1]));
}

__device__ __forceinline__ void ldm_x4(unsigned* r, uint32_t addr) {
    asm volatile(
        "ldmatrix.sync.aligned.m8n8.x4.shared.b16 {%0,%1,%2,%3}, [%4];"
        : "=r"(r[0]), "=r"(r[1]), "=r"(r[2]), "=r"(r[3]) : "r"(addr));
}

__device__ __forceinline__ unsigned packh2(float a, float b) {
    __half2 h = __floats2half2_rn(a, b);    // low = a
    return *reinterpret_cast<unsigned*>(&h);
}

__device__ __forceinline__ void cpasync16(uint32_t dst, const void* src) {
    asm volatile("cp.async.cg.shared.global [%0], [%1], 16;" :: "r"(dst), "l"(src));
}

// ---------------------------------------------------------------------------
// conversions
// ---------------------------------------------------------------------------
__global__ __launch_bounds__(256)
void k_cvtX(const float* __restrict__ src, __half* __restrict__ dst, int n4)
{
    int i = blockIdx.x * blockDim.x + threadIdx.x;
    if (i >= n4) return;
    float4 v = reinterpret_cast<const float4*>(src)[i];
    reinterpret_cast<__half2*>(dst)[i * 2 + 0] =
        __halves2half2(__float2half_rn(v.x), __float2half_rn(v.y));
    reinterpret_cast<__half2*>(dst)[i * 2 + 1] =
        __halves2half2(__float2half_rn(v.z), __float2half_rn(v.w));
}

__global__ __launch_bounds__(256)
void k_cvtW(const float* __restrict__ wq, const float* __restrict__ wk,
            const float* __restrict__ wv, const float* __restrict__ wo,
            __half* __restrict__ dst, int n4)
{
    int i = blockIdx.x * blockDim.x + threadIdx.x;
    if (i >= n4) return;
    const float* src = (blockIdx.y == 0) ? wq : (blockIdx.y == 1) ? wk
                       : (blockIdx.y == 2) ? wv : wo;
    __half* out = dst + (size_t)blockIdx.y * Dm * Dm;
    float4 v = reinterpret_cast<const float4*>(src)[i];
    reinterpret_cast<__half2*>(out)[i * 2 + 0] =
        __halves2half2(__float2half_rn(v.x), __float2half_rn(v.y));
    reinterpret_cast<__half2*>(out)[i * 2 + 1] =
        __halves2half2(__float2half_rn(v.z), __float2half_rn(v.w));
}

// ---------------------------------------------------------------------------
// Single-pass fp16 GEMM core: C = A . B^T + bias
// CTA tile 128x128, 4 warps (2x2) of 64x64, K-stage 32, cp.async double buffer.
// Stage tile: 128 rows x 80 B (64 B data + 16 pad); A and B tiles per buffer.
// mode: 0 = f32 out, 2 = fp16 out (scaled by oscale)
// ---------------------------------------------------------------------------
constexpr int GROWB = 80;                    // bytes per stage row
constexpr int GTILE = 128 * GROWB;           // 10240 B per matrix
constexpr int GEMM_SMEM = 2 * 2 * GTILE;     // 40960 B

__device__ __forceinline__ void gemm1_core(
    const __half* __restrict__ A,
    const __half* __restrict__ Bh,
    const float* __restrict__ bias,
    float* __restrict__ Cf, __half* __restrict__ Ch, int mode, float oscale)
{
    extern __shared__ __align__(16) unsigned char gsm[];

    const int tid  = threadIdx.x;
    const int lane = tid & 31;
    const int warp = tid >> 5;           // 0..3
    const int wm   = warp >> 1;          // 0..1
    const int wn   = warp & 1;           // 0..1
    const int m0   = blockIdx.y * 128;
    const int n0   = blockIdx.x * 128;

    const uint32_t smemBase = (uint32_t)__cvta_generic_to_shared(gsm);

    // cp.async fill: thread -> row (128), 4 chunks of 16 B each for A and B
    const int frow = tid;
    const uint32_t fDst = (uint32_t)(frow * GROWB);
    const __half* srcA = A  + (size_t)(m0 + frow) * Dm;
    const __half* srcB = Bh + (size_t)(n0 + frow) * Dm;

    // ldmatrix per-lane offsets
    const uint32_t aOff = (uint32_t)((lane & 15) * GROWB + ((lane >> 4) & 1) * 16)
                          + wm * 64 * GROWB;
    const uint32_t bOff = (uint32_t)(((lane & 7) + ((lane >> 1) & 8)) * GROWB
                          + ((lane >> 3) & 1) * 16)
                          + wn * 64 * GROWB;

    float acc[4][8][4];
#pragma unroll
    for (int mf = 0; mf < 4; ++mf)
#pragma unroll
        for (int nf = 0; nf < 8; ++nf)
#pragma unroll
            for (int j = 0; j < 4; ++j) acc[mf][nf][j] = 0.f;

    const int NSTAGE = Dm / 32;

    // prologue: issue stage 0 into buffer 0
    {
#pragma unroll
        for (int i = 0; i < 4; ++i) {
            cpasync16(smemBase + fDst + i * 16,          srcA + i * 8);
            cpasync16(smemBase + GTILE + fDst + i * 16,  srcB + i * 8);
        }
        asm volatile("cp.async.commit_group;");
    }

    int buf = 0;
    for (int st = 0; st < NSTAGE; ++st) {
        asm volatile("cp.async.wait_group 0;");
        __syncthreads();   // stage st visible; prior compute of buf done

        if (st + 1 < NSTAGE) {
            const uint32_t nb = (uint32_t)((buf ^ 1) * 2 * GTILE);
#pragma unroll
            for (int i = 0; i < 4; ++i) {
                cpasync16(smemBase + nb + fDst + i * 16,
                          srcA + (st + 1) * 32 + i * 8);
                cpasync16(smemBase + nb + GTILE + fDst + i * 16,
                          srcB + (st + 1) * 32 + i * 8);
            }
            asm volatile("cp.async.commit_group;");
        }

        const uint32_t aB = smemBase + (uint32_t)(buf * 2 * GTILE) + aOff;
        const uint32_t bB = smemBase + (uint32_t)(buf * 2 * GTILE) + GTILE + bOff;

#pragma unroll
        for (int ks = 0; ks < 2; ++ks) {
            const uint32_t kadd = ks * 32;
            unsigned af[4][4], bf[8][2];
#pragma unroll
            for (int mf = 0; mf < 4; ++mf)
                ldm_x4(af[mf], aB + mf * (16 * GROWB) + kadd);
#pragma unroll
            for (int np = 0; np < 4; ++np) {
                unsigned t[4];
                ldm_x4(t, bB + np * (16 * GROWB) + kadd);
                bf[np * 2][0] = t[0]; bf[np * 2][1] = t[1];
                bf[np * 2 + 1][0] = t[2]; bf[np * 2 + 1][1] = t[3];
            }
#pragma unroll
            for (int mf = 0; mf < 4; ++mf)
#pragma unroll
                for (int nf = 0; nf < 8; ++nf)
                    mma16h(acc[mf][nf], af[mf], bf[nf]);
        }
        buf ^= 1;
    }

#pragma unroll
    for (int mf = 0; mf < 4; ++mf) {
        const int r0 = m0 + wm * 64 + mf * 16 + (lane >> 2);
#pragma unroll
        for (int nf = 0; nf < 8; ++nf) {
            const int c = n0 + wn * 64 + nf * 8 + (lane & 3) * 2;
            float2 bv = *reinterpret_cast<const float2*>(bias + c);
            float o0x = acc[mf][nf][0] + bv.x;
            float o0y = acc[mf][nf][1] + bv.y;
            float o1x = acc[mf][nf][2] + bv.x;
            float o1y = acc[mf][nf][3] + bv.y;
            if (mode == 2) {
                o0x *= oscale; o0y *= oscale; o1x *= oscale; o1y *= oscale;
                *reinterpret_cast<__half2*>(Ch + (size_t)r0 * Dm + c) =
                    __halves2half2(__float2half_rn(o0x), __float2half_rn(o0y));
                *reinterpret_cast<__half2*>(Ch + (size_t)(r0 + 8) * Dm + c) =
                    __halves2half2(__float2half_rn(o1x), __float2half_rn(o1y));
            } else {
                *reinterpret_cast<float2*>(Cf + (size_t)r0 * Dm + c)       = make_float2(o0x, o0y);
                *reinterpret_cast<float2*>(Cf + (size_t)(r0 + 8) * Dm + c) = make_float2(o1x, o1y);
            }
        }
    }
}

constexpr float QSCALE = 0.125f * 1.44269504088896f;

__global__ __launch_bounds__(128)
void k_proj3(const __half* __restrict__ x16, const __half* __restrict__ w16,
             const float* __restrict__ bq, const float* __restrict__ bk,
             const float* __restrict__ bv,
             __half* __restrict__ q, __half* __restrict__ k, __half* __restrict__ v)
{
    const size_t WSZ = (size_t)Dm * Dm;
    const int z = blockIdx.z;
    if (z == 0)      gemm1_core(x16, w16,           bq, nullptr, q, 2, QSCALE);
    else if (z == 1) gemm1_core(x16, w16 + WSZ,     bk, nullptr, k, 2, 1.f);
    else             gemm1_core(x16, w16 + 2 * WSZ, bv, nullptr, v, 2, 1.f);
}

__global__ __launch_bounds__(128)
void k_oproj(const __half* __restrict__ c16, const __half* __restrict__ wo,
             const float* __restrict__ bo, float* __restrict__ out)
{
    gemm1_core(c16, wo, bo, out, nullptr, 0, 1.f);
}

// ---------------------------------------------------------------------------
// Flash attention: fp16 QK^T and PV; 4 warps x 32 q-rows = 128 q/CTA.
// K/V fragment loads hoisted across the two m-tiles -> ldmatrix traffic
// halved vs 8-warp version. P stays in registers. 1 syncthreads per tile.
// Smem layout (bytes):
//   Kst [2][64 rows x 144B] @ 0      (18432)
//   Vp  [2][64 rows x 144B] @ 18432  (18432)
//   msk [2][64] int         @ 36864  (  512)
// ---------------------------------------------------------------------------
constexpr int ATTN_SMEM = 37376;

__global__ __launch_bounds__(128)
void k_attn(const int* __restrict__ mask, __half* __restrict__ C16)
{
    extern __shared__ __align__(16) unsigned char smraw[];
    unsigned* Vp  = (unsigned*)(smraw + 18432);
    int*      msk = (int*)(smraw + 36864);

    const int tid  = threadIdx.x;
    const int lane = tid & 31;
    const int wq   = tid >> 5;            // 0..3, warp owns rows wq*32..+31
    const int bh   = blockIdx.y;
    const int b    = bh >> 4;
    const int h    = bh & 15;
    const int q0   = blockIdx.x * 128;

    const uint32_t KstA = (uint32_t)__cvta_generic_to_shared(smraw);
    const uint32_t VpA  = KstA + 18432;
    const uint32_t mskA = KstA + 36864;

    // cp.async addressing (K tile: 64 rows x 128B data, 144B stride); 128 thr
    const int krow = tid >> 1;                  // 0..63
    const int kcb  = (tid & 1) * 64;            // byte col base 0 or 64
    const uint32_t kDst = (uint32_t)(krow * 144 + kcb);

    // V prefetch addressing: thread -> keypair kpi (0..31), d range dseg..+15
    const int kpi  = tid >> 2;
    const int dseg = (tid & 3) * 16;

    // ldmatrix per-lane offsets (B-fragments; row stride 144 B)
    const int rowB = (lane & 7) + ((lane >> 1) & 8);
    const uint32_t offB = (uint32_t)(rowB * 144 + ((lane >> 3) & 1) * 16);

    // Q fragments (fp16, pre-scaled): 2 m-tiles x 4 k16-steps
    unsigned qf[2][4][4];
    {
        const __half* qbase = g_Q16 + ((size_t)(b * Sn + q0 + wq * 32) * Dm + h * Dh);
#pragma unroll
        for (int mt = 0; mt < 2; ++mt)
#pragma unroll
            for (int c = 0; c < 4; ++c)
#pragma unroll
                for (int j = 0; j < 4; ++j) {
                    int row = mt * 16 + (lane >> 2) + ((j & 1) << 3);
                    int col = c * 16 + (lane & 3) * 2 + ((j >> 1) << 3);
                    qf[mt][c][j] = *reinterpret_cast<const unsigned*>(
                        qbase + (size_t)row * Dm + col);
                }
    }

    float of[2][8][4];
#pragma unroll
    for (int mt = 0; mt < 2; ++mt)
#pragma unroll
        for (int nf = 0; nf < 8; ++nf)
#pragma unroll
            for (int j = 0; j < 4; ++j) of[mt][nf][j] = 0.f;

    float mr[2][2] = { {-INFINITY, -INFINITY}, {-INFINITY, -INFINITY} };
    float lr[2][2] = { {0.f, 0.f}, {0.f, 0.f} };

    const int NT = Sn / 64;

    // prologue: K/mask tile 0 via cp.async; V tile 0 to regs
    {
        const __half* kp = g_K16 + (size_t)(b * Sn + krow) * Dm + h * Dh + kcb / 2;
#pragma unroll
        for (int i = 0; i < 4; ++i)
            cpasync16(KstA + kDst + i * 16, kp + i * 8);
        if (tid < 16) cpasync16(mskA + tid * 16, mask + (size_t)b * Sn + tid * 4);
        asm volatile("cp.async.commit_group;");
    }
    uint4 va0, va1, vb0, vb1;
    {
        const __half* vsrc = g_V16 + (size_t)(b * Sn + 2 * kpi) * Dm + h * Dh + dseg;
        va0 = *reinterpret_cast<const uint4*>(vsrc);
        va1 = *reinterpret_cast<const uint4*>(vsrc + 8);
        vb0 = *reinterpret_cast<const uint4*>(vsrc + Dm);
        vb1 = *reinterpret_cast<const uint4*>(vsrc + Dm + 8);
    }

    for (int kt = 0; kt < NT; ++kt) {
        const int p = kt & 1;

        // pack V regs (tile kt) -> Vp[p]: d rows dseg..dseg+15, col kpi
        {
            unsigned* vrow = Vp + p * 2304 + dseg * 36 + kpi;
            vrow[0 * 36]  = __byte_perm(va0.x, vb0.x, 0x5410);
            vrow[1 * 36]  = __byte_perm(va0.x, vb0.x, 0x7632);
            vrow[2 * 36]  = __byte_perm(va0.y, vb0.y, 0x5410);
            vrow[3 * 36]  = __byte_perm(va0.y, vb0.y, 0x7632);
            vrow[4 * 36]  = __byte_perm(va0.z, vb0.z, 0x5410);
            vrow[5 * 36]  = __byte_perm(va0.z, vb0.z, 0x7632);
            vrow[6 * 36]  = __byte_perm(va0.w, vb0.w, 0x5410);
            vrow[7 * 36]  = __byte_perm(va0.w, vb0.w, 0x7632);
            vrow[8 * 36]  = __byte_perm(va1.x, vb1.x, 0x5410);
            vrow[9 * 36]  = __byte_perm(va1.x, vb1.x, 0x7632);
            vrow[10 * 36] = __byte_perm(va1.y, vb1.y, 0x5410);
            vrow[11 * 36] = __byte_perm(va1.y, vb1.y, 0x7632);
            vrow[12 * 36] = __byte_perm(va1.z, vb1.z, 0x5410);
            vrow[13 * 36] = __byte_perm(va1.z, vb1.z, 0x7632);
            vrow[14 * 36] = __byte_perm(va1.w, vb1.w, 0x5410);
            vrow[15 * 36] = __byte_perm(va1.w, vb1.w, 0x7632);
        }
        // V prefetch next tile
        if (kt + 1 < NT) {
            const __half* vsrc = g_V16 +
                (size_t)(b * Sn + (kt + 1) * 64 + 2 * kpi) * Dm + h * Dh + dseg;
            va0 = *reinterpret_cast<const uint4*>(vsrc);
            va1 = *reinterpret_cast<const uint4*>(vsrc + 8);
            vb0 = *reinterpret_cast<const uint4*>(vsrc + Dm);
            vb1 = *reinterpret_cast<const uint4*>(vsrc + Dm + 8);
        }

        asm volatile("cp.async.wait_group 0;");
        __syncthreads();   // K[p], Vp[p] visible; prior compute done

        // issue next K/mask tile AFTER barrier
        if (kt + 1 < NT) {
            const __half* kp = g_K16 +
                (size_t)(b * Sn + (kt + 1) * 64 + krow) * Dm + h * Dh + kcb / 2;
            const uint32_t bofs = (uint32_t)((p ^ 1) * 9216);
#pragma unroll
            for (int i = 0; i < 4; ++i)
                cpasync16(KstA + bofs + kDst + i * 16, kp + i * 8);
            if (tid < 16)
                cpasync16(mskA + (p ^ 1) * 256 + tid * 16,
                          mask + (size_t)b * Sn + (kt + 1) * 64 + tid * 4);
            asm volatile("cp.async.commit_group;");
        }

        // S = Q . K^T : K frags shared across both m-tiles
        float sf[2][8][4];
#pragma unroll
        for (int mt = 0; mt < 2; ++mt)
#pragma unroll
            for (int nf = 0; nf < 8; ++nf)
#pragma unroll
                for (int j = 0; j < 4; ++j) sf[mt][nf][j] = 0.f;

        const uint32_t kBase = KstA + (uint32_t)(p * 9216) + offB;
#pragma unroll
        for (int c = 0; c < 4; ++c) {
#pragma unroll
            for (int np = 0; np < 4; ++np) {
                unsigned t[4];
                ldm_x4(t, kBase + (uint32_t)(np * 16 * 144 + c * 32));
                unsigned b0[2] = { t[0], t[1] };
                unsigned b1[2] = { t[2], t[3] };
#pragma unroll
                for (int mt = 0; mt < 2; ++mt) {
                    mma16h(sf[mt][np * 2],     qf[mt][c], b0);
                    mma16h(sf[mt][np * 2 + 1], qf[mt][c], b1);
                }
            }
        }

        // mask + online softmax (base 2), per m-tile
        const int* mk = msk + p * 64;
        bool nochange = true;
#pragma unroll
        for (int mt = 0; mt < 2; ++mt) {
            float tmax0 = -INFINITY, tmax1 = -INFINITY;
#pragma unroll
            for (int nf = 0; nf < 8; ++nf) {
                const int c = nf * 8 + (lane & 3) * 2;
                if (!mk[c])     { sf[mt][nf][0] = -1e20f; sf[mt][nf][2] = -1e20f; }
                if (!mk[c + 1]) { sf[mt][nf][1] = -1e20f; sf[mt][nf][3] = -1e20f; }
                tmax0 = fmaxf(tmax0, fmaxf(sf[mt][nf][0], sf[mt][nf][1]));
                tmax1 = fmaxf(tmax1, fmaxf(sf[mt][nf][2], sf[mt][nf][3]));
            }
            tmax0 = fmaxf(tmax0, __shfl_xor_sync(0xffffffff, tmax0, 1));
            tmax0 = fmaxf(tmax0, __shfl_xor_sync(0xffffffff, tmax0, 2));
            tmax1 = fmaxf(tmax1, __shfl_xor_sync(0xffffffff, tmax1, 1));
            tmax1 = fmaxf(tmax1, __shfl_xor_sync(0xffffffff, tmax1, 2));

            const float mn0 = fmaxf(mr[mt][0], tmax0);
            const float mn1 = fmaxf(mr[mt][1], tmax1);
            const float a0  = ex2(mr[mt][0] - mn0);
            const float a1  = ex2(mr[mt][1] - mn1);
            lr[mt][0] *= a0; lr[mt][1] *= a1;
            if (a0 != 1.f || a1 != 1.f) {
                nochange = false;
#pragma unroll
                for (int nf = 0; nf < 8; ++nf) {
                    of[mt][nf][0] *= a0; of[mt][nf][1] *= a0;
                    of[mt][nf][2] *= a1; of[mt][nf][3] *= a1;
                }
            }

            float s0 = 0.f, s1 = 0.f;
#pragma unroll
            for (int nf = 0; nf < 8; ++nf) {
                sf[mt][nf][0] = ex2(sf[mt][nf][0] - mn0);
                sf[mt][nf][1] = ex2(sf[mt][nf][1] - mn0);
                sf[mt][nf][2] = ex2(sf[mt][nf][2] - mn1);
                sf[mt][nf][3] = ex2(sf[mt][nf][3] - mn1);
                s0 += sf[mt][nf][0] + sf[mt][nf][1];
                s1 += sf[mt][nf][2] + sf[mt][nf][3];
            }
            s0 += __shfl_xor_sync(0xffffffff, s0, 1);
            s0 += __shfl_xor_sync(0xffffffff, s0, 2);
            s1 += __shfl_xor_sync(0xffffffff, s1, 1);
            s1 += __shfl_xor_sync(0xffffffff, s1, 2);
            lr[mt][0] += s0; lr[mt][1] += s1;
            mr[mt][0] = mn0; mr[mt][1] = mn1;
        }
        (void)nochange;

        // O += P . V : V frags shared across both m-tiles
        const uint32_t vBase = VpA + (uint32_t)(p * 9216) + offB;
#pragma unroll
        for (int c = 0; c < 4; ++c) {
            unsigned af[2][4];
#pragma unroll
            for (int mt = 0; mt < 2; ++mt) {
                af[mt][0] = packh2(sf[mt][2 * c][0],     sf[mt][2 * c][1]);
                af[mt][1] = packh2(sf[mt][2 * c][2],     sf[mt][2 * c][3]);
                af[mt][2] = packh2(sf[mt][2 * c + 1][0], sf[mt][2 * c + 1][1]);
                af[mt][3] = packh2(sf[mt][2 * c + 1][2], sf[mt][2 * c + 1][3]);
            }
#pragma unroll
            for (int np = 0; np < 4; ++np) {
                unsigned t[4];
                ldm_x4(t, vBase + (uint32_t)(np * 16 * 144 + c * 32));
                unsigned b0[2] = { t[0], t[1] };
                unsigned b1[2] = { t[2], t[3] };
#pragma unroll
                for (int mt = 0; mt < 2; ++mt) {
                    mma16h(of[mt][np * 2],     af[mt], b0);
                    mma16h(of[mt][np * 2 + 1], af[mt], b1);
                }
            }
        }
    }

    // epilogue: normalize, write fp16 ctx
#pragma unroll
    for (int mt = 0; mt < 2; ++mt) {
        const float inv0 = 1.f / lr[mt][0];
        const float inv1 = 1.f / lr[mt][1];
        const size_t rbase = (size_t)(b * Sn + q0 + wq * 32 + mt * 16);
#pragma unroll
        for (int nf = 0; nf < 8; ++nf) {
            const int c = h * Dh + nf * 8 + (lane & 3) * 2;
            const int r = lane >> 2;
            *reinterpret_cast<__half2*>(C16 + (rbase + r) * Dm + c) =
                __halves2half2(__float2half_rn(of[mt][nf][0] * inv0),
                               __float2half_rn(of[mt][nf][1] * inv0));
            *reinterpret_cast<__half2*>(C16 + (rbase + r + 8) * Dm + c) =
                __halves2half2(__float2half_rn(of[mt][nf][2] * inv1),
                               __float2half_rn(of[mt][nf][3] * inv1));
        }
    }
}

// ---------------------------------------------------------------------------
// Launch
// ---------------------------------------------------------------------------
extern "C" void kernel_launch(void* const* d_in, const int* in_sizes, int n_in,
                              void* d_out, int out_size)
{
    const float* query = (const float*)d_in[0];
    const int*   mask  = (const int*)  d_in[1];
    const float* Wq    = (const float*)d_in[2];
    const float* bq    = (const float*)d_in[3];
    const float* Wk    = (const float*)d_in[4];
    const float* bk    = (const float*)d_in[5];
    const float* Wv    = (const float*)d_in[6];
    const float* bv    = (const float*)d_in[7];
    const float* Wo    = (const float*)d_in[8];
    const float* bo    = (const float*)d_in[9];
    float* out = (float*)d_out;

    static int init_done = 0;
    if (!init_done) {
        cudaFuncSetAttribute(k_proj3, cudaFuncAttributeMaxDynamicSharedMemorySize, GEMM_SMEM);
        cudaFuncSetAttribute(k_oproj, cudaFuncAttributeMaxDynamicSharedMemorySize, GEMM_SMEM);
        cudaFuncSetAttribute(k_attn,  cudaFuncAttributeMaxDynamicSharedMemorySize, ATTN_SMEM);
        init_done = 1;
    }

    __half *x16, *c16, *w16, *q16, *k16, *v16;
    cudaGetSymbolAddress((void**)&x16, g_X16);
    cudaGetSymbolAddress((void**)&c16, g_C16);
    cudaGetSymbolAddress((void**)&w16, g_W16);
    cudaGetSymbolAddress((void**)&q16, g_Q16);
    cudaGetSymbolAddress((void**)&k16, g_K16);
    cudaGetSymbolAddress((void**)&v16, g_V16);

    const size_t WSZ = (size_t)Dm * Dm;
    const int nX4 = MTOT * Dm / 4;
    const int nW4 = Dm * Dm / 4;

    // conversions
    k_cvtX<<<(nX4 + 255) / 256, 256>>>(query, x16, nX4);
    dim3 gw((nW4 + 255) / 256, 4);
    k_cvtW<<<gw, 256>>>(Wq, Wk, Wv, Wo, w16, nW4);

    // QKV projections (single-pass fp16)
    dim3 gq(Dm / 128, MTOT / 128, 3);
    k_proj3<<<gq, 128, GEMM_SMEM>>>(x16, w16, bq, bk, bv, q16, k16, v16);

    // attention
    dim3 ga(Sn / 128, Bn * Hn);
    k_attn<<<ga, 128, ATTN_SMEM>>>(mask, c16);

    // output projection (single-pass fp16, f32 out)
    dim3 go(Dm / 128, MTOT / 128);
    k_oproj<<<go, 128, GEMM_SMEM>>>(c16, w16 + 3 * WSZ, bo, out);
}